// round 12
// baseline (speedup 1.0000x reference)
#include <cuda_runtime.h>
#include <cuda_bf16.h>
#include <math.h>
#include <stdint.h>

// ---------------- problem constants ----------------
#define BB 2
#define SS 1024
#define NN (BB*SS)          // 2048 tokens
#define EE 768
#define HH 12
#define DD 64
#define II 3072
#define LL 4
#define RH 128
#define MAXD 4
#define VV 50257
#define QKVW (3*EE)         // 2304

// ---------------- scratch (device globals; no allocation allowed) ----------------
__device__ float g_h   [NN*EE];
__device__ float g_hn  [NN*EE];
__device__ float g_qkv [NN*QKVW];   // also reused as 2x split-K partial buffers (wo/w2)
__device__ float g_attn[NN*EE];
__device__ float g_ffa [NN*II];
__device__ float g_rlog[NN*MAXD];
__device__ int   g_dep [NN];
__device__ float g_loss[1];

// ---------------- embedding ----------------
__global__ void embed_kernel(const int* __restrict__ ids,
                             const float* __restrict__ tok,
                             const float* __restrict__ pos,
                             float* __restrict__ h) {
    int i = blockIdx.x * blockDim.x + threadIdx.x;
    if (i >= NN*EE) return;
    int n = i / EE, e = i - n*EE;
    int s = n % SS;
    h[i] = tok[(size_t)ids[n]*EE + e] + pos[(size_t)s*EE + e];
}

// ---------------- router ----------------
__global__ void router_kernel(const float* __restrict__ h,
                              const float* __restrict__ w1, const float* __restrict__ b1,
                              const float* __restrict__ w2, const float* __restrict__ b2,
                              float* __restrict__ rlog, int* __restrict__ dep) {
    int n = blockIdx.x;
    int tid = threadIdx.x;   // 128 threads
    __shared__ float r1[RH];
    __shared__ float lg[MAXD];
    const float* hr = h + (size_t)n*EE;
    {
        const float4* hv = reinterpret_cast<const float4*>(hr);
        const float4* wv = reinterpret_cast<const float4*>(w1 + (size_t)tid*EE);
        float acc = b1[tid];
        #pragma unroll 4
        for (int e = 0; e < EE/4; e++) {
            float4 a = hv[e], b = wv[e];
            acc += a.x*b.x + a.y*b.y + a.z*b.z + a.w*b.w;
        }
        r1[tid] = fmaxf(acc, 0.f);
    }
    __syncthreads();
    if (tid < MAXD) {
        float acc = b2[tid];
        const float* wr = w2 + tid*RH;
        #pragma unroll 8
        for (int j = 0; j < RH; j++) acc += r1[j]*wr[j];
        lg[tid] = acc;
        rlog[n*MAXD + tid] = acc;
    }
    __syncthreads();
    if (tid == 0) {
        int best = 0; float bv = lg[0];
        #pragma unroll
        for (int m = 1; m < MAXD; m++) if (lg[m] > bv) { bv = lg[m]; best = m; }
        dep[n] = best + 1;
    }
}

// ---------------- layernorm per token ----------------
__global__ void ln_kernel(const float* __restrict__ x,
                          const float* __restrict__ g, const float* __restrict__ b,
                          float* __restrict__ y) {
    int n = blockIdx.x, tid = threadIdx.x;   // 256 threads
    __shared__ float red[256];
    __shared__ float s_mu, s_rstd;
    const float* xr = x + (size_t)n*EE;
    float s = 0.f;
    for (int e = tid; e < EE; e += 256) s += xr[e];
    red[tid] = s; __syncthreads();
    for (int o = 128; o > 0; o >>= 1) { if (tid < o) red[tid] += red[tid+o]; __syncthreads(); }
    if (tid == 0) s_mu = red[0] * (1.f/EE);
    __syncthreads();
    float mu = s_mu;
    float v = 0.f;
    for (int e = tid; e < EE; e += 256) { float d = xr[e]-mu; v += d*d; }
    red[tid] = v; __syncthreads();
    for (int o = 128; o > 0; o >>= 1) { if (tid < o) red[tid] += red[tid+o]; __syncthreads(); }
    if (tid == 0) s_rstd = rsqrtf(red[0]*(1.f/EE) + 1e-5f);
    __syncthreads();
    float rstd = s_rstd;
    float* yr = y + (size_t)n*EE;
    for (int e = tid; e < EE; e += 256) yr[e] = (xr[e]-mu)*rstd*g[e] + b[e];
}

// ---------------- fused split-K reduce + layernorm ----------------
// h[n] += p0[n] + p1[n]  (written back), then y[n] = LN(h[n]) * g + b
__global__ void ln_add_kernel(float* __restrict__ x,
                              const float* __restrict__ p0, const float* __restrict__ p1,
                              const float* __restrict__ g, const float* __restrict__ b,
                              float* __restrict__ y) {
    int n = blockIdx.x, tid = threadIdx.x;   // 256 threads, EE=768 -> 3 elems/thread
    __shared__ float red[256];
    __shared__ float s_mu, s_rstd;
    size_t base = (size_t)n*EE;
    float xv[3];
    float s = 0.f;
    #pragma unroll
    for (int i = 0; i < 3; i++) {
        int e = tid + i*256;
        float v = x[base + e] + (p0[base + e] + p1[base + e]);
        xv[i] = v;
        x[base + e] = v;
        s += v;
    }
    red[tid] = s; __syncthreads();
    for (int o = 128; o > 0; o >>= 1) { if (tid < o) red[tid] += red[tid+o]; __syncthreads(); }
    if (tid == 0) s_mu = red[0] * (1.f/EE);
    __syncthreads();
    float mu = s_mu;
    float v = 0.f;
    #pragma unroll
    for (int i = 0; i < 3; i++) { float d = xv[i]-mu; v += d*d; }
    red[tid] = v; __syncthreads();
    for (int o = 128; o > 0; o >>= 1) { if (tid < o) red[tid] += red[tid+o]; __syncthreads(); }
    if (tid == 0) s_rstd = rsqrtf(red[0]*(1.f/EE) + 1e-5f);
    __syncthreads();
    float rstd = s_rstd;
    #pragma unroll
    for (int i = 0; i < 3; i++) {
        int e = tid + i*256;
        y[base + e] = (xv[i]-mu)*rstd*g[e] + b[e];
    }
}

// ---------------- tf32 helpers ----------------
__device__ __forceinline__ void split_tf32(float x, uint32_t& hi, uint32_t& lo) {
    uint32_t h;
    asm("cvt.rna.tf32.f32 %0, %1;" : "=r"(h) : "f"(x));
    float lf = x - __uint_as_float(h);
    uint32_t l;
    asm("cvt.rna.tf32.f32 %0, %1;" : "=r"(l) : "f"(lf));
    hi = h; lo = l;
}

__device__ __forceinline__ void mma_tf32(float* d, const uint32_t* a, const uint32_t* b) {
    asm volatile(
        "mma.sync.aligned.m16n8k8.row.col.f32.tf32.tf32.f32 "
        "{%0,%1,%2,%3}, {%4,%5,%6,%7}, {%8,%9}, {%0,%1,%2,%3};"
        : "+f"(d[0]), "+f"(d[1]), "+f"(d[2]), "+f"(d[3])
        : "r"(a[0]), "r"(a[1]), "r"(a[2]), "r"(a[3]),
          "r"(b[0]), "r"(b[1]));
}

// ---------------- bf16 helpers (lm_head only) ----------------
__device__ __forceinline__ void split_bf16(float2 v, uint32_t& hi, uint32_t& lo) {
    uint32_t ux = __float_as_uint(v.x);
    uint32_t uy = __float_as_uint(v.y);
    uint32_t hx = ux & 0xFFFF0000u;
    uint32_t hy = uy & 0xFFFF0000u;
    hi = (hx >> 16) | hy;                       // x -> low half, y -> high half
    float lx = v.x - __uint_as_float(hx);
    float ly = v.y - __uint_as_float(hy);
    asm("cvt.rn.bf16x2.f32 %0, %1, %2;" : "=r"(lo) : "f"(ly), "f"(lx));
}

__device__ __forceinline__ void mma_bf16(float* d, const uint32_t* a, const uint32_t* b) {
    asm volatile(
        "mma.sync.aligned.m16n8k16.row.col.f32.bf16.bf16.f32 "
        "{%0,%1,%2,%3}, {%4,%5,%6,%7}, {%8,%9}, {%0,%1,%2,%3};"
        : "+f"(d[0]), "+f"(d[1]), "+f"(d[2]), "+f"(d[3])
        : "r"(a[0]), "r"(a[1]), "r"(a[2]), "r"(a[3]),
          "r"(b[0]), "r"(b[1]));
}

__device__ __forceinline__ void cp_async16(uint32_t dst, const void* src, bool pred) {
    int sz = pred ? 16 : 0;
    asm volatile("cp.async.ca.shared.global [%0], [%1], 16, %2;\n"
                 :: "r"(dst), "l"(src), "r"(sz));
}

// ---------------- GEMM NT via 3xTF32 mma + cp.async 2-stage pipeline ----------------
// C[M,Nn] (op)= act(A[M,K] * W[Nn,K]^T + bias),  M = 2048 rows always.
// EPI: 0 = store, 1 = gelu + store.
// Split-K: gridDim.z = P parts; part z covers K-range [z*K/P, (z+1)*K/P) and
// writes to C + z*2048*Nn (partial buffers). bias applied only on z==0.
#define TILE_B (128*36*4)            // one 128x36 fp32 tile in bytes
#define GEMM_SMEM (4*TILE_B)         // 2 stages x (A + W)
template <int EPI>
__global__ __launch_bounds__(256, 2)
void gemm3x(const float* __restrict__ A, const float* __restrict__ W,
            const float* __restrict__ bias, float* __restrict__ C,
            int Nn, int K) {
    extern __shared__ float smem_f[];
    uint32_t sbase;
    asm("{ .reg .u64 t; cvta.to.shared.u64 t, %1; cvt.u32.u64 %0, t; }"
        : "=r"(sbase) : "l"(smem_f));

    int tid = threadIdx.x;
    int m0 = blockIdx.y * 128;
    int n0 = blockIdx.x * 128;
    // split-K part
    int Kp = K / gridDim.z;
    int kbase = blockIdx.z * Kp;
    if (gridDim.z > 1) C += (size_t)blockIdx.z * (size_t)2048 * Nn;
    bool do_bias = (bias != nullptr) && (blockIdx.z == 0);

    int warp = tid >> 5, lane = tid & 31;
    int wm = (warp & 1) * 64;     // warp tile 64(m) x 32(n)
    int wn = (warp >> 1) * 32;
    int g = lane >> 2, t = lane & 3;

    float acc[4][4][4];
    #pragma unroll
    for (int mf = 0; mf < 4; mf++)
        #pragma unroll
        for (int nf = 0; nf < 4; nf++)
            #pragma unroll
            for (int i = 0; i < 4; i++) acc[mf][nf][i] = 0.f;

    int lrow = tid >> 3;          // 0..31
    int lk4  = (tid & 7) * 4;     // 0,4,...,28

    const int nk = Kp >> 5;

    auto load_stage = [&](int st, int k0) {
        uint32_t baseA = sbase + (uint32_t)st * 2u * TILE_B;
        uint32_t baseW = baseA + TILE_B;
        #pragma unroll
        for (int p = 0; p < 4; p++) {
            int r = lrow + p * 32;
            uint32_t off = (uint32_t)(r*36 + lk4) * 4u;
            cp_async16(baseA + off, &A[(size_t)(m0 + r)*K + kbase + k0 + lk4], true);
            int nn = n0 + r;
            int nnc = nn < Nn ? nn : (Nn - 1);
            cp_async16(baseW + off, &W[(size_t)nnc*K + kbase + k0 + lk4], nn < Nn);
        }
    };

    load_stage(0, 0);
    asm volatile("cp.async.commit_group;");

    for (int i = 0; i < nk; i++) {
        if (i + 1 < nk) {
            load_stage((i + 1) & 1, (i + 1) << 5);
            asm volatile("cp.async.commit_group;");
            asm volatile("cp.async.wait_group 1;");
        } else {
            asm volatile("cp.async.wait_group 0;");
        }
        __syncthreads();

        int st = i & 1;
        float (*sA)[36] = (float(*)[36])(smem_f + (size_t)st * 2 * 128 * 36);
        float (*sW)[36] = (float(*)[36])(smem_f + (size_t)st * 2 * 128 * 36 + 128 * 36);

        #pragma unroll
        for (int ks = 0; ks < 4; ks++) {
            int kk = ks * 8;
            uint32_t ahi[4][4], alo[4][4], bhi[4][2], blo[4][2];
            #pragma unroll
            for (int mf = 0; mf < 4; mf++) {
                int mr = wm + mf*16;
                split_tf32(sA[mr + g    ][kk + t    ], ahi[mf][0], alo[mf][0]);
                split_tf32(sA[mr + g + 8][kk + t    ], ahi[mf][1], alo[mf][1]);
                split_tf32(sA[mr + g    ][kk + t + 4], ahi[mf][2], alo[mf][2]);
                split_tf32(sA[mr + g + 8][kk + t + 4], ahi[mf][3], alo[mf][3]);
            }
            #pragma unroll
            for (int nf = 0; nf < 4; nf++) {
                int nr = wn + nf*8;
                split_tf32(sW[nr + g][kk + t    ], bhi[nf][0], blo[nf][0]);
                split_tf32(sW[nr + g][kk + t + 4], bhi[nf][1], blo[nf][1]);
            }
            #pragma unroll
            for (int mf = 0; mf < 4; mf++)
                #pragma unroll
                for (int nf = 0; nf < 4; nf++) {
                    mma_tf32(acc[mf][nf], ahi[mf], bhi[nf]);
                    mma_tf32(acc[mf][nf], alo[mf], bhi[nf]);
                    mma_tf32(acc[mf][nf], ahi[mf], blo[nf]);
                }
        }
        __syncthreads();
    }

    #pragma unroll
    for (int mf = 0; mf < 4; mf++) {
        #pragma unroll
        for (int nf = 0; nf < 4; nf++) {
            #pragma unroll
            for (int i = 0; i < 4; i++) {
                int m = m0 + wm + mf*16 + g + (i >> 1) * 8;
                int n = n0 + wn + nf*8 + t*2 + (i & 1);
                if (n < Nn) {
                    float v = acc[mf][nf][i] + (do_bias ? bias[n] : 0.f);
                    if (EPI == 1) v = 0.5f*v*(1.0f + erff(v*0.70710678118654752f));
                    C[(size_t)m*Nn + n] = v;
                }
            }
        }
    }
}

// ---------------- lm_head GEMM: bf16x2 3-term emulation (2x tensor rate) ----------------
// C[M,Nn] = A[M,K] * W[Nn,K]^T (no bias). Grid: x = m-tile, y = n-tile (W reuse in L2).
__global__ __launch_bounds__(256, 2)
void gemm_lmh(const float* __restrict__ A, const float* __restrict__ W,
              float* __restrict__ C, int Nn, int K) {
    extern __shared__ float smem_f[];
    uint32_t sbase;
    asm("{ .reg .u64 t; cvta.to.shared.u64 t, %1; cvt.u32.u64 %0, t; }"
        : "=r"(sbase) : "l"(smem_f));

    int tid = threadIdx.x;
    int m0 = blockIdx.x * 128;     // transposed grid: x = m-tile
    int n0 = blockIdx.y * 128;     //                  y = n-tile
    int warp = tid >> 5, lane = tid & 31;
    int wm = (warp & 1) * 64;
    int wn = (warp >> 1) * 32;
    int g = lane >> 2, t = lane & 3;

    float acc[4][4][4];
    #pragma unroll
    for (int mf = 0; mf < 4; mf++)
        #pragma unroll
        for (int nf = 0; nf < 4; nf++)
            #pragma unroll
            for (int i = 0; i < 4; i++) acc[mf][nf][i] = 0.f;

    int lrow = tid >> 3;
    int lk4  = (tid & 7) * 4;
    const int nk = K >> 5;

    auto load_stage = [&](int st, int k0) {
        uint32_t baseA = sbase + (uint32_t)st * 2u * TILE_B;
        uint32_t baseW = baseA + TILE_B;
        #pragma unroll
        for (int p = 0; p < 4; p++) {
            int r = lrow + p * 32;
            uint32_t off = (uint32_t)(r*36 + lk4) * 4u;
            cp_async16(baseA + off, &A[(size_t)(m0 + r)*K + k0 + lk4], true);
            int nn = n0 + r;
            int nnc = nn < Nn ? nn : (Nn - 1);
            cp_async16(baseW + off, &W[(size_t)nnc*K + k0 + lk4], nn < Nn);
        }
    };

    load_stage(0, 0);
    asm volatile("cp.async.commit_group;");

    for (int i = 0; i < nk; i++) {
        if (i + 1 < nk) {
            load_stage((i + 1) & 1, (i + 1) << 5);
            asm volatile("cp.async.commit_group;");
            asm volatile("cp.async.wait_group 1;");
        } else {
            asm volatile("cp.async.wait_group 0;");
        }
        __syncthreads();

        int st = i & 1;
        float (*sA)[36] = (float(*)[36])(smem_f + (size_t)st * 2 * 128 * 36);
        float (*sW)[36] = (float(*)[36])(smem_f + (size_t)st * 2 * 128 * 36 + 128 * 36);

        #pragma unroll
        for (int ks = 0; ks < 2; ks++) {          // two k=16 steps per 32-tile
            int kk = ks * 16;
            int t2 = 2 * t;
            uint32_t ahi[4][4], alo[4][4], bhi[4][2], blo[4][2];
            #pragma unroll
            for (int mf = 0; mf < 4; mf++) {
                int mr = wm + mf*16;
                float2 f;
                f = *reinterpret_cast<const float2*>(&sA[mr + g    ][kk + t2    ]);
                split_bf16(f, ahi[mf][0], alo[mf][0]);
                f = *reinterpret_cast<const float2*>(&sA[mr + g + 8][kk + t2    ]);
                split_bf16(f, ahi[mf][1], alo[mf][1]);
                f = *reinterpret_cast<const float2*>(&sA[mr + g    ][kk + t2 + 8]);
                split_bf16(f, ahi[mf][2], alo[mf][2]);
                f = *reinterpret_cast<const float2*>(&sA[mr + g + 8][kk + t2 + 8]);
                split_bf16(f, ahi[mf][3], alo[mf][3]);
            }
            #pragma unroll
            for (int nf = 0; nf < 4; nf++) {
                int nr = wn + nf*8;
                float2 f;
                f = *reinterpret_cast<const float2*>(&sW[nr + g][kk + t2    ]);
                split_bf16(f, bhi[nf][0], blo[nf][0]);
                f = *reinterpret_cast<const float2*>(&sW[nr + g][kk + t2 + 8]);
                split_bf16(f, bhi[nf][1], blo[nf][1]);
            }
            #pragma unroll
            for (int mf = 0; mf < 4; mf++)
                #pragma unroll
                for (int nf = 0; nf < 4; nf++) {
                    mma_bf16(acc[mf][nf], ahi[mf], bhi[nf]);
                    mma_bf16(acc[mf][nf], alo[mf], bhi[nf]);
                    mma_bf16(acc[mf][nf], ahi[mf], blo[nf]);
                }
        }
        __syncthreads();
    }

    #pragma unroll
    for (int mf = 0; mf < 4; mf++) {
        #pragma unroll
        for (int nf = 0; nf < 4; nf++) {
            #pragma unroll
            for (int i = 0; i < 4; i++) {
                int m = m0 + wm + mf*16 + g + (i >> 1) * 8;
                int n = n0 + wn + nf*8 + t*2 + (i & 1);
                if (n < Nn)
                    C[(size_t)m*Nn + n] = acc[mf][nf][i];
            }
        }
    }
}

// ---------------- tiled attention: 64 q-rows per block, online softmax ----------------
// K/V tiles register-double-buffered; depth flags for all 1024 keys preloaded once.
__global__ __launch_bounds__(256)
void attn_tile_kernel(const float* __restrict__ qkv, const int* __restrict__ dep,
                      int depth, float* __restrict__ out) {
    extern __shared__ float sm[];
    float (*Qs)[65] = (float(*)[65])(sm);
    float (*Ks)[65] = (float(*)[65])(sm + 64*65);
    float (*Vs)[65] = (float(*)[65])(sm + 2*64*65);
    float (*Ps)[65] = (float(*)[65])(sm + 3*64*65);
    float* m_s  = sm + 4*64*65;
    float* l_s  = m_s + 64;
    float* al_s = l_s + 64;
    int*   kf   = (int*)(al_s + 64);   // flags for all SS keys

    int qt = blockIdx.x, h = blockIdx.y, b = blockIdx.z;
    int q0 = qt * 64;
    int tid = threadIdx.x;
    int tx = tid & 15, ty = tid >> 4;

    int d4 = (tid & 15) * 4, jr = tid >> 4;
    {
        #pragma unroll
        for (int p = 0; p < 4; p++) {
            int qq = jr + p*16;
            float4 v = *reinterpret_cast<const float4*>(
                &qkv[((size_t)b*SS + q0 + qq)*QKVW + h*DD + d4]);
            Qs[qq][d4+0] = v.x; Qs[qq][d4+1] = v.y; Qs[qq][d4+2] = v.z; Qs[qq][d4+3] = v.w;
        }
    }
    for (int j = tid; j < SS; j += 256)
        kf[j] = (dep[b*SS + j] >= depth) ? 1 : 0;
    if (tid < 64) {
        m_s[tid] = -1e30f;
        l_s[tid] = 0.f;
    }

    float O[4][4];
    #pragma unroll
    for (int i = 0; i < 4; i++)
        #pragma unroll
        for (int j = 0; j < 4; j++) O[i][j] = 0.f;

    // prefetch K/V tile 0 into registers
    float4 ka[4], va[4];
    #pragma unroll
    for (int p = 0; p < 4; p++) {
        size_t row = ((size_t)b*SS + jr + p*16)*QKVW + h*DD;
        ka[p] = *reinterpret_cast<const float4*>(&qkv[row + EE + d4]);
        va[p] = *reinterpret_cast<const float4*>(&qkv[row + 2*EE + d4]);
    }

    for (int k0 = 0; k0 < SS; k0 += 64) {
        __syncthreads();   // Q/flags visible (iter 0); previous PV done (iters >0)
        #pragma unroll
        for (int p = 0; p < 4; p++) {
            int jj = jr + p*16;
            Ks[jj][d4+0] = ka[p].x; Ks[jj][d4+1] = ka[p].y; Ks[jj][d4+2] = ka[p].z; Ks[jj][d4+3] = ka[p].w;
            Vs[jj][d4+0] = va[p].x; Vs[jj][d4+1] = va[p].y; Vs[jj][d4+2] = va[p].z; Vs[jj][d4+3] = va[p].w;
        }
        if (k0 + 64 < SS) {    // prefetch next tile (overlaps entire compute below)
            #pragma unroll
            for (int p = 0; p < 4; p++) {
                size_t row = ((size_t)b*SS + k0 + 64 + jr + p*16)*QKVW + h*DD;
                ka[p] = *reinterpret_cast<const float4*>(&qkv[row + EE + d4]);
                va[p] = *reinterpret_cast<const float4*>(&qkv[row + 2*EE + d4]);
            }
        }
        __syncthreads();

        float sacc[4][4];
        #pragma unroll
        for (int i = 0; i < 4; i++)
            #pragma unroll
            for (int j = 0; j < 4; j++) sacc[i][j] = 0.f;
        #pragma unroll 8
        for (int d = 0; d < 64; d++) {
            float a[4], bb[4];
            #pragma unroll
            for (int i = 0; i < 4; i++) a[i] = Qs[ty*4+i][d];
            #pragma unroll
            for (int j = 0; j < 4; j++) bb[j] = Ks[tx*4+j][d];
            #pragma unroll
            for (int i = 0; i < 4; i++)
                #pragma unroll
                for (int j = 0; j < 4; j++) sacc[i][j] += a[i]*bb[j];
        }
        #pragma unroll
        for (int i = 0; i < 4; i++) {
            int row = ty*4 + i;
            int rowg = q0 + row;
            #pragma unroll
            for (int j = 0; j < 4; j++) {
                int col = tx*4 + j;
                int colg = k0 + col;
                float msk = (colg <= rowg && kf[rowg] && kf[colg]) ? 1.f : 0.f;
                Ps[row][col] = sacc[i][j]*0.125f + msk;
            }
        }
        __syncthreads();

        {
            int rid = tid >> 2, sub = tid & 3;
            float mx = -1e30f;
            #pragma unroll
            for (int jj = 0; jj < 16; jj++) mx = fmaxf(mx, Ps[rid][sub*16+jj]);
            mx = fmaxf(mx, __shfl_xor_sync(0xffffffff, mx, 1));
            mx = fmaxf(mx, __shfl_xor_sync(0xffffffff, mx, 2));
            float mold = m_s[rid];
            float mnew = fmaxf(mold, mx);
            float sum = 0.f;
            #pragma unroll
            for (int jj = 0; jj < 16; jj++) {
                float p = __expf(Ps[rid][sub*16+jj] - mnew);
                Ps[rid][sub*16+jj] = p;
                sum += p;
            }
            sum += __shfl_xor_sync(0xffffffff, sum, 1);
            sum += __shfl_xor_sync(0xffffffff, sum, 2);
            if (sub == 0) {
                float alpha = __expf(mold - mnew);
                al_s[rid] = alpha;
                l_s[rid] = l_s[rid]*alpha + sum;
                m_s[rid] = mnew;
            }
        }
        __syncthreads();

        float alr[4];
        #pragma unroll
        for (int i = 0; i < 4; i++) alr[i] = al_s[ty*4+i];
        #pragma unroll
        for (int i = 0; i < 4; i++)
            #pragma unroll
            for (int j = 0; j < 4; j++) O[i][j] *= alr[i];
        #pragma unroll 8
        for (int k = 0; k < 64; k++) {
            float a[4], bb[4];
            #pragma unroll
            for (int i = 0; i < 4; i++) a[i] = Ps[ty*4+i][k];
            #pragma unroll
            for (int j = 0; j < 4; j++) bb[j] = Vs[k][tx*4+j];
            #pragma unroll
            for (int i = 0; i < 4; i++)
                #pragma unroll
                for (int j = 0; j < 4; j++) O[i][j] += a[i]*bb[j];
        }
    }
    __syncthreads();

    #pragma unroll
    for (int i = 0; i < 4; i++) {
        int row = ty*4 + i;
        float inv = 1.f / l_s[row];
        #pragma unroll
        for (int j = 0; j < 4; j++) {
            out[((size_t)b*SS + q0 + row)*EE + h*DD + tx*4 + j] = O[i][j]*inv;
        }
    }
}

// ---------------- router aux loss ----------------
__global__ void loss_kernel(const float* __restrict__ rlog, const int* __restrict__ dep,
                            float* __restrict__ loss) {
    int tid = threadIdx.x;  // 1024
    __shared__ float red[1024];
    float p[MAXD] = {0,0,0,0};
    float ds = 0.f;
    for (int n = tid; n < NN; n += 1024) {
        float l0 = rlog[n*4+0], l1 = rlog[n*4+1], l2 = rlog[n*4+2], l3 = rlog[n*4+3];
        float m = fmaxf(fmaxf(l0,l1), fmaxf(l2,l3));
        float e0 = expf(l0-m), e1 = expf(l1-m), e2 = expf(l2-m), e3 = expf(l3-m);
        float inv = 1.f/(e0+e1+e2+e3);
        p[0] += e0*inv; p[1] += e1*inv; p[2] += e2*inv; p[3] += e3*inv;
        ds += (float)dep[n];
    }
    float sums[5];
    float vals[5] = {p[0], p[1], p[2], p[3], ds};
    for (int v = 0; v < 5; v++) {
        red[tid] = vals[v]; __syncthreads();
        for (int o = 512; o > 0; o >>= 1) { if (tid < o) red[tid] += red[tid+o]; __syncthreads(); }
        sums[v] = red[0]; __syncthreads();
    }
    if (tid == 0) {
        const float u = 1.f/MAXD;
        float lb = 0.f;
        for (int m = 0; m < MAXD; m++) {
            float mp = sums[m] / (float)NN;
            lb += u * (logf(u) - logf(mp));
        }
        lb /= MAXD;
        float sparsity = (sums[4] / (float)NN) / MAXD;
        loss[0] = 0.01f*lb + 0.001f*sparsity;
    }
}

// ---------------- output tail ----------------
__global__ void finalize_kernel(const int* __restrict__ dep, const float* __restrict__ rlog,
                                const float* __restrict__ loss, float* __restrict__ out) {
    int i = blockIdx.x * blockDim.x + threadIdx.x;
    size_t base = (size_t)NN * VV;
    if (i < NN) out[base + i] = (float)dep[i];
    if (i == 0) out[base + NN] = loss[0];
    if (i < NN*MAXD) out[base + NN + 1 + i] = rlog[i];
}

// ---------------- host orchestration ----------------
extern "C" void kernel_launch(void* const* d_in, const int* in_sizes, int n_in,
                              void* d_out, int out_size) {
    const int*   ids  = (const int*)  d_in[0];
    const float* tok  = (const float*)d_in[1];
    const float* pos  = (const float*)d_in[2];
    const float* rw1  = (const float*)d_in[3];
    const float* rb1  = (const float*)d_in[4];
    const float* rw2  = (const float*)d_in[5];
    const float* rb2  = (const float*)d_in[6];
    const float* wqkv = (const float*)d_in[7];
    const float* bqkv = (const float*)d_in[8];
    const float* wo   = (const float*)d_in[9];
    const float* bo   = (const float*)d_in[10];
    const float* ln1g = (const float*)d_in[11];
    const float* ln1b = (const float*)d_in[12];
    const float* ln2g = (const float*)d_in[13];
    const float* ln2b = (const float*)d_in[14];
    const float* w1   = (const float*)d_in[15];
    const float* b1   = (const float*)d_in[16];
    const float* w2   = (const float*)d_in[17];
    const float* b2   = (const float*)d_in[18];
    const float* lnfg = (const float*)d_in[19];
    const float* lnfb = (const float*)d_in[20];
    const float* lmh  = (const float*)d_in[21];
    float* out = (float*)d_out;

    float *ph, *phn, *pqkv, *pattn, *pffa, *prl, *ploss;
    int* pdep;
    cudaGetSymbolAddress((void**)&ph,    g_h);
    cudaGetSymbolAddress((void**)&phn,   g_hn);
    cudaGetSymbolAddress((void**)&pqkv,  g_qkv);
    cudaGetSymbolAddress((void**)&pattn, g_attn);
    cudaGetSymbolAddress((void**)&pffa,  g_ffa);
    cudaGetSymbolAddress((void**)&prl,   g_rlog);
    cudaGetSymbolAddress((void**)&ploss, g_loss);
    cudaGetSymbolAddress((void**)&pdep,  g_dep);

    static const int ATTN_SMEM = (4*64*65 + 3*64) * sizeof(float) + SS*sizeof(int);
    cudaFuncSetAttribute(attn_tile_kernel, cudaFuncAttributeMaxDynamicSharedMemorySize, ATTN_SMEM);
    cudaFuncSetAttribute(gemm3x<0>, cudaFuncAttributeMaxDynamicSharedMemorySize, GEMM_SMEM);
    cudaFuncSetAttribute(gemm3x<1>, cudaFuncAttributeMaxDynamicSharedMemorySize, GEMM_SMEM);
    cudaFuncSetAttribute(gemm_lmh,  cudaFuncAttributeMaxDynamicSharedMemorySize, GEMM_SMEM);

    embed_kernel<<<(NN*EE + 255)/256, 256>>>(ids, tok, pos, ph);
    router_kernel<<<NN, RH>>>(ph, rw1, rb1, rw2, rb2, prl, pdep);

    // initial LN1 of depth 1
    ln_kernel<<<NN, 256>>>(ph, ln1g, ln1b, phn);

    for (int depth = 1; depth <= MAXD; depth++) {
        int li = depth - 1;
        {
            dim3 g(QKVW/128, NN/128);
            gemm3x<0><<<g, 256, GEMM_SMEM>>>(phn, wqkv + (size_t)li*QKVW*EE, bqkv + li*QKVW, pqkv, QKVW, EE);
        }
        attn_tile_kernel<<<dim3(SS/64, HH, BB), 256, ATTN_SMEM>>>(pqkv, pdep, depth, pattn);
        {
            // wo: split-K x2 into partial buffers (g_qkv reused; free here)
            dim3 g(EE/128, NN/128, 2);
            gemm3x<0><<<g, 256, GEMM_SMEM>>>(pattn, wo + (size_t)li*EE*EE, bo + li*EE, pqkv, EE, EE);
        }
        // fused: h += p0+p1; hn = LN2(h)
        ln_add_kernel<<<NN, 256>>>(ph, pqkv, pqkv + (size_t)NN*EE, ln2g + li*EE, ln2b + li*EE, phn);
        {
            dim3 g(II/128, NN/128);
            gemm3x<1><<<g, 256, GEMM_SMEM>>>(phn, w1 + (size_t)li*II*EE, b1 + li*II, pffa, II, EE);
        }
        {
            // w2: split-K x2 (K=3072 -> 1536 per part, 192 CTAs)
            dim3 g(EE/128, NN/128, 2);
            gemm3x<0><<<g, 256, GEMM_SMEM>>>(pffa, w2 + (size_t)li*EE*II, b2 + li*EE, pqkv, EE, II);
        }
        // fused: h += p0+p1; hn = LN1(next layer) or LNF
        const float* ng = (depth < MAXD) ? (ln1g + (size_t)(li+1)*EE) : lnfg;
        const float* nb = (depth < MAXD) ? (ln1b + (size_t)(li+1)*EE) : lnfb;
        ln_add_kernel<<<NN, 256>>>(ph, pqkv, pqkv + (size_t)NN*EE, ng, nb, phn);
    }

    {
        dim3 g(NN/128, (VV + 127)/128);   // x = m-tile, y = n-tile (W reuse in L2)
        gemm_lmh<<<g, 256, GEMM_SMEM>>>(phn, lmh, out, VV, EE);
    }

    loss_kernel<<<1, 1024>>>(prl, pdep, ploss);

    long long full = (long long)NN*VV + NN + 1 + (long long)NN*MAXD;
    if ((long long)out_size >= full)
        finalize_kernel<<<(NN*MAXD + 255)/256, 256>>>(pdep, prl, ploss, out);
}

// round 13
// speedup vs baseline: 1.1961x; 1.1961x over previous
#include <cuda_runtime.h>
#include <cuda_bf16.h>
#include <math.h>
#include <stdint.h>

// ---------------- problem constants ----------------
#define BB 2
#define SS 1024
#define NN (BB*SS)          // 2048 tokens
#define EE 768
#define HH 12
#define DD 64
#define II 3072
#define LL 4
#define RH 128
#define MAXD 4
#define VV 50257
#define QKVW (3*EE)         // 2304

// ---------------- scratch (device globals; no allocation allowed) ----------------
__device__ float g_h   [NN*EE];
__device__ float g_hn  [NN*EE];
__device__ float g_qkv [NN*QKVW];   // also reused as 2x split-K partial buffers (wo/w2)
__device__ float g_attn[NN*EE];
__device__ float g_ffa [NN*II];
__device__ float g_rlog[NN*MAXD];
__device__ int   g_dep [NN];
__device__ float g_loss[1];

// ---------------- embedding ----------------
__global__ void embed_kernel(const int* __restrict__ ids,
                             const float* __restrict__ tok,
                             const float* __restrict__ pos,
                             float* __restrict__ h) {
    int i = blockIdx.x * blockDim.x + threadIdx.x;
    if (i >= NN*EE) return;
    int n = i / EE, e = i - n*EE;
    int s = n % SS;
    h[i] = tok[(size_t)ids[n]*EE + e] + pos[(size_t)s*EE + e];
}

// ---------------- router ----------------
__global__ void router_kernel(const float* __restrict__ h,
                              const float* __restrict__ w1, const float* __restrict__ b1,
                              const float* __restrict__ w2, const float* __restrict__ b2,
                              float* __restrict__ rlog, int* __restrict__ dep) {
    int n = blockIdx.x;
    int tid = threadIdx.x;   // 128 threads
    __shared__ float r1[RH];
    __shared__ float lg[MAXD];
    const float* hr = h + (size_t)n*EE;
    {
        const float4* hv = reinterpret_cast<const float4*>(hr);
        const float4* wv = reinterpret_cast<const float4*>(w1 + (size_t)tid*EE);
        float acc = b1[tid];
        #pragma unroll 4
        for (int e = 0; e < EE/4; e++) {
            float4 a = hv[e], b = wv[e];
            acc += a.x*b.x + a.y*b.y + a.z*b.z + a.w*b.w;
        }
        r1[tid] = fmaxf(acc, 0.f);
    }
    __syncthreads();
    if (tid < MAXD) {
        float acc = b2[tid];
        const float* wr = w2 + tid*RH;
        #pragma unroll 8
        for (int j = 0; j < RH; j++) acc += r1[j]*wr[j];
        lg[tid] = acc;
        rlog[n*MAXD + tid] = acc;
    }
    __syncthreads();
    if (tid == 0) {
        int best = 0; float bv = lg[0];
        #pragma unroll
        for (int m = 1; m < MAXD; m++) if (lg[m] > bv) { bv = lg[m]; best = m; }
        dep[n] = best + 1;
    }
}

// ---------------- layernorm per token ----------------
__global__ void ln_kernel(const float* __restrict__ x,
                          const float* __restrict__ g, const float* __restrict__ b,
                          float* __restrict__ y) {
    int n = blockIdx.x, tid = threadIdx.x;   // 256 threads
    __shared__ float red[256];
    __shared__ float s_mu, s_rstd;
    const float* xr = x + (size_t)n*EE;
    float s = 0.f;
    for (int e = tid; e < EE; e += 256) s += xr[e];
    red[tid] = s; __syncthreads();
    for (int o = 128; o > 0; o >>= 1) { if (tid < o) red[tid] += red[tid+o]; __syncthreads(); }
    if (tid == 0) s_mu = red[0] * (1.f/EE);
    __syncthreads();
    float mu = s_mu;
    float v = 0.f;
    for (int e = tid; e < EE; e += 256) { float d = xr[e]-mu; v += d*d; }
    red[tid] = v; __syncthreads();
    for (int o = 128; o > 0; o >>= 1) { if (tid < o) red[tid] += red[tid+o]; __syncthreads(); }
    if (tid == 0) s_rstd = rsqrtf(red[0]*(1.f/EE) + 1e-5f);
    __syncthreads();
    float rstd = s_rstd;
    float* yr = y + (size_t)n*EE;
    for (int e = tid; e < EE; e += 256) yr[e] = (xr[e]-mu)*rstd*g[e] + b[e];
}

// ---------------- split-K reduce: h += p0 + p1 ----------------
__global__ void add2_kernel(float* __restrict__ h,
                            const float* __restrict__ p0,
                            const float* __restrict__ p1) {
    int i = blockIdx.x * blockDim.x + threadIdx.x;
    if (i < NN*EE) h[i] += p0[i] + p1[i];
}

// ---------------- bf16x3 helpers ----------------
// RN split: hi = rn_bf16x2(x,y); lo = rn_bf16x2(residuals). Per-product err ~2^-18.
__device__ __forceinline__ void split_bf16rn(float2 v, uint32_t& hi, uint32_t& lo) {
    asm("cvt.rn.bf16x2.f32 %0, %1, %2;" : "=r"(hi) : "f"(v.y), "f"(v.x));
    float hx = __uint_as_float(hi << 16);
    float hy = __uint_as_float(hi & 0xFFFF0000u);
    float lx = v.x - hx;
    float ly = v.y - hy;
    asm("cvt.rn.bf16x2.f32 %0, %1, %2;" : "=r"(lo) : "f"(ly), "f"(lx));
}

__device__ __forceinline__ void mma_bf16(float* d, const uint32_t* a, const uint32_t* b) {
    asm volatile(
        "mma.sync.aligned.m16n8k16.row.col.f32.bf16.bf16.f32 "
        "{%0,%1,%2,%3}, {%4,%5,%6,%7}, {%8,%9}, {%0,%1,%2,%3};"
        : "+f"(d[0]), "+f"(d[1]), "+f"(d[2]), "+f"(d[3])
        : "r"(a[0]), "r"(a[1]), "r"(a[2]), "r"(a[3]),
          "r"(b[0]), "r"(b[1]));
}

__device__ __forceinline__ void cp_async16(uint32_t dst, const void* src, bool pred) {
    int sz = pred ? 16 : 0;
    asm volatile("cp.async.ca.shared.global [%0], [%1], 16, %2;\n"
                 :: "r"(dst), "l"(src), "r"(sz));
}

// ---------------- GEMM NT via bf16x3 mma + cp.async 2-stage pipeline ----------------
// C[M,Nn] (op)= act(A[M,K] * W[Nn,K]^T + bias),  M = 2048 rows always.
// EPI: 0 = store, 1 = gelu + store.
// Split-K: gridDim.z = P parts; part z covers K-range [z*K/P, (z+1)*K/P) and
// writes to C + z*2048*Nn (partial buffers). bias applied only on z==0.
#define TILE_B (128*36*4)            // one 128x36 fp32 tile in bytes
#define GEMM_SMEM (4*TILE_B)         // 2 stages x (A + W)
template <int EPI>
__global__ __launch_bounds__(256, 2)
void gemm_b3(const float* __restrict__ A, const float* __restrict__ W,
             const float* __restrict__ bias, float* __restrict__ C,
             int Nn, int K) {
    extern __shared__ float smem_f[];
    uint32_t sbase;
    asm("{ .reg .u64 t; cvta.to.shared.u64 t, %1; cvt.u32.u64 %0, t; }"
        : "=r"(sbase) : "l"(smem_f));

    int tid = threadIdx.x;
    int m0 = blockIdx.y * 128;
    int n0 = blockIdx.x * 128;
    // split-K part
    int Kp = K / gridDim.z;
    int kbase = blockIdx.z * Kp;
    if (gridDim.z > 1) C += (size_t)blockIdx.z * (size_t)2048 * Nn;
    bool do_bias = (bias != nullptr) && (blockIdx.z == 0);

    int warp = tid >> 5, lane = tid & 31;
    int wm = (warp & 1) * 64;     // warp tile 64(m) x 32(n)
    int wn = (warp >> 1) * 32;
    int g = lane >> 2, t = lane & 3;

    float acc[4][4][4];
    #pragma unroll
    for (int mf = 0; mf < 4; mf++)
        #pragma unroll
        for (int nf = 0; nf < 4; nf++)
            #pragma unroll
            for (int i = 0; i < 4; i++) acc[mf][nf][i] = 0.f;

    int lrow = tid >> 3;          // 0..31
    int lk4  = (tid & 7) * 4;     // 0,4,...,28

    const int nk = Kp >> 5;

    auto load_stage = [&](int st, int k0) {
        uint32_t baseA = sbase + (uint32_t)st * 2u * TILE_B;
        uint32_t baseW = baseA + TILE_B;
        #pragma unroll
        for (int p = 0; p < 4; p++) {
            int r = lrow + p * 32;
            uint32_t off = (uint32_t)(r*36 + lk4) * 4u;
            cp_async16(baseA + off, &A[(size_t)(m0 + r)*K + kbase + k0 + lk4], true);
            int nn = n0 + r;
            int nnc = nn < Nn ? nn : (Nn - 1);
            cp_async16(baseW + off, &W[(size_t)nnc*K + kbase + k0 + lk4], nn < Nn);
        }
    };

    load_stage(0, 0);
    asm volatile("cp.async.commit_group;");

    for (int i = 0; i < nk; i++) {
        if (i + 1 < nk) {
            load_stage((i + 1) & 1, (i + 1) << 5);
            asm volatile("cp.async.commit_group;");
            asm volatile("cp.async.wait_group 1;");
        } else {
            asm volatile("cp.async.wait_group 0;");
        }
        __syncthreads();

        int st = i & 1;
        float (*sA)[36] = (float(*)[36])(smem_f + (size_t)st * 2 * 128 * 36);
        float (*sW)[36] = (float(*)[36])(smem_f + (size_t)st * 2 * 128 * 36 + 128 * 36);

        #pragma unroll
        for (int ks = 0; ks < 2; ks++) {          // two k=16 steps per 32-tile
            int kk = ks * 16;
            int t2 = 2 * t;
            uint32_t ahi[4][4], alo[4][4], bhi[4][2], blo[4][2];
            #pragma unroll
            for (int mf = 0; mf < 4; mf++) {
                int mr = wm + mf*16;
                float2 f;
                f = *reinterpret_cast<const float2*>(&sA[mr + g    ][kk + t2    ]);
                split_bf16rn(f, ahi[mf][0], alo[mf][0]);
                f = *reinterpret_cast<const float2*>(&sA[mr + g + 8][kk + t2    ]);
                split_bf16rn(f, ahi[mf][1], alo[mf][1]);
                f = *reinterpret_cast<const float2*>(&sA[mr + g    ][kk + t2 + 8]);
                split_bf16rn(f, ahi[mf][2], alo[mf][2]);
                f = *reinterpret_cast<const float2*>(&sA[mr + g + 8][kk + t2 + 8]);
                split_bf16rn(f, ahi[mf][3], alo[mf][3]);
            }
            #pragma unroll
            for (int nf = 0; nf < 4; nf++) {
                int nr = wn + nf*8;
                float2 f;
                f = *reinterpret_cast<const float2*>(&sW[nr + g][kk + t2    ]);
                split_bf16rn(f, bhi[nf][0], blo[nf][0]);
                f = *reinterpret_cast<const float2*>(&sW[nr + g][kk + t2 + 8]);
                split_bf16rn(f, bhi[nf][1], blo[nf][1]);
            }
            #pragma unroll
            for (int mf = 0; mf < 4; mf++)
                #pragma unroll
                for (int nf = 0; nf < 4; nf++) {
                    mma_bf16(acc[mf][nf], ahi[mf], bhi[nf]);
                    mma_bf16(acc[mf][nf], alo[mf], bhi[nf]);
                    mma_bf16(acc[mf][nf], ahi[mf], blo[nf]);
                }
        }
        __syncthreads();
    }

    #pragma unroll
    for (int mf = 0; mf < 4; mf++) {
        #pragma unroll
        for (int nf = 0; nf < 4; nf++) {
            #pragma unroll
            for (int i = 0; i < 4; i++) {
                int m = m0 + wm + mf*16 + g + (i >> 1) * 8;
                int n = n0 + wn + nf*8 + t*2 + (i & 1);
                if (n < Nn) {
                    float v = acc[mf][nf][i] + (do_bias ? bias[n] : 0.f);
                    if (EPI == 1) v = 0.5f*v*(1.0f + erff(v*0.70710678118654752f));
                    C[(size_t)m*Nn + n] = v;
                }
            }
        }
    }
}

// ---------------- lm_head GEMM: bf16x3 (RN splits). Grid: x = m-tile, y = n-tile ----------------
__global__ __launch_bounds__(256, 2)
void gemm_lmh(const float* __restrict__ A, const float* __restrict__ W,
              float* __restrict__ C, int Nn, int K) {
    extern __shared__ float smem_f[];
    uint32_t sbase;
    asm("{ .reg .u64 t; cvta.to.shared.u64 t, %1; cvt.u32.u64 %0, t; }"
        : "=r"(sbase) : "l"(smem_f));

    int tid = threadIdx.x;
    int m0 = blockIdx.x * 128;     // transposed grid: x = m-tile
    int n0 = blockIdx.y * 128;     //                  y = n-tile
    int warp = tid >> 5, lane = tid & 31;
    int wm = (warp & 1) * 64;
    int wn = (warp >> 1) * 32;
    int g = lane >> 2, t = lane & 3;

    float acc[4][4][4];
    #pragma unroll
    for (int mf = 0; mf < 4; mf++)
        #pragma unroll
        for (int nf = 0; nf < 4; nf++)
            #pragma unroll
            for (int i = 0; i < 4; i++) acc[mf][nf][i] = 0.f;

    int lrow = tid >> 3;
    int lk4  = (tid & 7) * 4;
    const int nk = K >> 5;

    auto load_stage = [&](int st, int k0) {
        uint32_t baseA = sbase + (uint32_t)st * 2u * TILE_B;
        uint32_t baseW = baseA + TILE_B;
        #pragma unroll
        for (int p = 0; p < 4; p++) {
            int r = lrow + p * 32;
            uint32_t off = (uint32_t)(r*36 + lk4) * 4u;
            cp_async16(baseA + off, &A[(size_t)(m0 + r)*K + k0 + lk4], true);
            int nn = n0 + r;
            int nnc = nn < Nn ? nn : (Nn - 1);
            cp_async16(baseW + off, &W[(size_t)nnc*K + k0 + lk4], nn < Nn);
        }
    };

    load_stage(0, 0);
    asm volatile("cp.async.commit_group;");

    for (int i = 0; i < nk; i++) {
        if (i + 1 < nk) {
            load_stage((i + 1) & 1, (i + 1) << 5);
            asm volatile("cp.async.commit_group;");
            asm volatile("cp.async.wait_group 1;");
        } else {
            asm volatile("cp.async.wait_group 0;");
        }
        __syncthreads();

        int st = i & 1;
        float (*sA)[36] = (float(*)[36])(smem_f + (size_t)st * 2 * 128 * 36);
        float (*sW)[36] = (float(*)[36])(smem_f + (size_t)st * 2 * 128 * 36 + 128 * 36);

        #pragma unroll
        for (int ks = 0; ks < 2; ks++) {          // two k=16 steps per 32-tile
            int kk = ks * 16;
            int t2 = 2 * t;
            uint32_t ahi[4][4], alo[4][4], bhi[4][2], blo[4][2];
            #pragma unroll
            for (int mf = 0; mf < 4; mf++) {
                int mr = wm + mf*16;
                float2 f;
                f = *reinterpret_cast<const float2*>(&sA[mr + g    ][kk + t2    ]);
                split_bf16rn(f, ahi[mf][0], alo[mf][0]);
                f = *reinterpret_cast<const float2*>(&sA[mr + g + 8][kk + t2    ]);
                split_bf16rn(f, ahi[mf][1], alo[mf][1]);
                f = *reinterpret_cast<const float2*>(&sA[mr + g    ][kk + t2 + 8]);
                split_bf16rn(f, ahi[mf][2], alo[mf][2]);
                f = *reinterpret_cast<const float2*>(&sA[mr + g + 8][kk + t2 + 8]);
                split_bf16rn(f, ahi[mf][3], alo[mf][3]);
            }
            #pragma unroll
            for (int nf = 0; nf < 4; nf++) {
                int nr = wn + nf*8;
                float2 f;
                f = *reinterpret_cast<const float2*>(&sW[nr + g][kk + t2    ]);
                split_bf16rn(f, bhi[nf][0], blo[nf][0]);
                f = *reinterpret_cast<const float2*>(&sW[nr + g][kk + t2 + 8]);
                split_bf16rn(f, bhi[nf][1], blo[nf][1]);
            }
            #pragma unroll
            for (int mf = 0; mf < 4; mf++)
                #pragma unroll
                for (int nf = 0; nf < 4; nf++) {
                    mma_bf16(acc[mf][nf], ahi[mf], bhi[nf]);
                    mma_bf16(acc[mf][nf], alo[mf], bhi[nf]);
                    mma_bf16(acc[mf][nf], ahi[mf], blo[nf]);
                }
        }
        __syncthreads();
    }

    #pragma unroll
    for (int mf = 0; mf < 4; mf++) {
        #pragma unroll
        for (int nf = 0; nf < 4; nf++) {
            #pragma unroll
            for (int i = 0; i < 4; i++) {
                int m = m0 + wm + mf*16 + g + (i >> 1) * 8;
                int n = n0 + wn + nf*8 + t*2 + (i & 1);
                if (n < Nn)
                    C[(size_t)m*Nn + n] = acc[mf][nf][i];
            }
        }
    }
}

// ---------------- tiled attention: 64 q-rows per block, online softmax ----------------
__global__ __launch_bounds__(256)
void attn_tile_kernel(const float* __restrict__ qkv, const int* __restrict__ dep,
                      int depth, float* __restrict__ out) {
    extern __shared__ float sm[];
    float (*Qs)[65] = (float(*)[65])(sm);
    float (*Ks)[65] = (float(*)[65])(sm + 64*65);
    float (*Vs)[65] = (float(*)[65])(sm + 2*64*65);
    float (*Ps)[65] = (float(*)[65])(sm + 3*64*65);
    float* m_s  = sm + 4*64*65;
    float* l_s  = m_s + 64;
    float* al_s = l_s + 64;
    int*   dq_s = (int*)(al_s + 64);
    int*   dk_s = dq_s + 64;

    int qt = blockIdx.x, h = blockIdx.y, b = blockIdx.z;
    int q0 = qt * 64;
    int tid = threadIdx.x;
    int tx = tid & 15, ty = tid >> 4;

    {
        int d4 = (tid & 15) * 4, q = tid >> 4;
        #pragma unroll
        for (int p = 0; p < 4; p++) {
            int qq = q + p*16;
            float4 v = *reinterpret_cast<const float4*>(
                &qkv[((size_t)b*SS + q0 + qq)*QKVW + h*DD + d4]);
            Qs[qq][d4+0] = v.x; Qs[qq][d4+1] = v.y; Qs[qq][d4+2] = v.z; Qs[qq][d4+3] = v.w;
        }
    }
    if (tid < 64) {
        dq_s[tid] = (dep[b*SS + q0 + tid] >= depth) ? 1 : 0;
        m_s[tid] = -1e30f;
        l_s[tid] = 0.f;
    }

    float O[4][4];
    #pragma unroll
    for (int i = 0; i < 4; i++)
        #pragma unroll
        for (int j = 0; j < 4; j++) O[i][j] = 0.f;

    for (int k0 = 0; k0 < SS; k0 += 64) {
        __syncthreads();
        {
            int d4 = (tid & 15) * 4, j = tid >> 4;
            #pragma unroll
            for (int p = 0; p < 4; p++) {
                int jj = j + p*16;
                size_t row = ((size_t)b*SS + k0 + jj)*QKVW + h*DD;
                float4 kv = *reinterpret_cast<const float4*>(&qkv[row + EE + d4]);
                Ks[jj][d4+0] = kv.x; Ks[jj][d4+1] = kv.y; Ks[jj][d4+2] = kv.z; Ks[jj][d4+3] = kv.w;
                float4 vv = *reinterpret_cast<const float4*>(&qkv[row + 2*EE + d4]);
                Vs[jj][d4+0] = vv.x; Vs[jj][d4+1] = vv.y; Vs[jj][d4+2] = vv.z; Vs[jj][d4+3] = vv.w;
            }
        }
        if (tid < 64) dk_s[tid] = (dep[b*SS + k0 + tid] >= depth) ? 1 : 0;
        __syncthreads();

        float sacc[4][4];
        #pragma unroll
        for (int i = 0; i < 4; i++)
            #pragma unroll
            for (int j = 0; j < 4; j++) sacc[i][j] = 0.f;
        #pragma unroll 8
        for (int d = 0; d < 64; d++) {
            float a[4], bb[4];
            #pragma unroll
            for (int i = 0; i < 4; i++) a[i] = Qs[ty*4+i][d];
            #pragma unroll
            for (int j = 0; j < 4; j++) bb[j] = Ks[tx*4+j][d];
            #pragma unroll
            for (int i = 0; i < 4; i++)
                #pragma unroll
                for (int j = 0; j < 4; j++) sacc[i][j] += a[i]*bb[j];
        }
        #pragma unroll
        for (int i = 0; i < 4; i++) {
            int row = ty*4 + i;
            int rowg = q0 + row;
            #pragma unroll
            for (int j = 0; j < 4; j++) {
                int col = tx*4 + j;
                int colg = k0 + col;
                float msk = (colg <= rowg && dq_s[row] && dk_s[col]) ? 1.f : 0.f;
                Ps[row][col] = sacc[i][j]*0.125f + msk;
            }
        }
        __syncthreads();

        {
            int rid = tid >> 2, sub = tid & 3;
            float mx = -1e30f;
            #pragma unroll
            for (int jj = 0; jj < 16; jj++) mx = fmaxf(mx, Ps[rid][sub*16+jj]);
            mx = fmaxf(mx, __shfl_xor_sync(0xffffffff, mx, 1));
            mx = fmaxf(mx, __shfl_xor_sync(0xffffffff, mx, 2));
            float mold = m_s[rid];
            float mnew = fmaxf(mold, mx);
            float sum = 0.f;
            #pragma unroll
            for (int jj = 0; jj < 16; jj++) {
                float p = __expf(Ps[rid][sub*16+jj] - mnew);
                Ps[rid][sub*16+jj] = p;
                sum += p;
            }
            sum += __shfl_xor_sync(0xffffffff, sum, 1);
            sum += __shfl_xor_sync(0xffffffff, sum, 2);
            if (sub == 0) {
                float alpha = __expf(mold - mnew);
                al_s[rid] = alpha;
                l_s[rid] = l_s[rid]*alpha + sum;
                m_s[rid] = mnew;
            }
        }
        __syncthreads();

        float alr[4];
        #pragma unroll
        for (int i = 0; i < 4; i++) alr[i] = al_s[ty*4+i];
        #pragma unroll
        for (int i = 0; i < 4; i++)
            #pragma unroll
            for (int j = 0; j < 4; j++) O[i][j] *= alr[i];
        #pragma unroll 8
        for (int k = 0; k < 64; k++) {
            float a[4], bb[4];
            #pragma unroll
            for (int i = 0; i < 4; i++) a[i] = Ps[ty*4+i][k];
            #pragma unroll
            for (int j = 0; j < 4; j++) bb[j] = Vs[k][tx*4+j];
            #pragma unroll
            for (int i = 0; i < 4; i++)
                #pragma unroll
                for (int j = 0; j < 4; j++) O[i][j] += a[i]*bb[j];
        }
    }
    __syncthreads();

    #pragma unroll
    for (int i = 0; i < 4; i++) {
        int row = ty*4 + i;
        float inv = 1.f / l_s[row];
        #pragma unroll
        for (int j = 0; j < 4; j++) {
            out[((size_t)b*SS + q0 + row)*EE + h*DD + tx*4 + j] = O[i][j]*inv;
        }
    }
}

// ---------------- router aux loss ----------------
__global__ void loss_kernel(const float* __restrict__ rlog, const int* __restrict__ dep,
                            float* __restrict__ loss) {
    int tid = threadIdx.x;  // 1024
    __shared__ float red[1024];
    float p[MAXD] = {0,0,0,0};
    float ds = 0.f;
    for (int n = tid; n < NN; n += 1024) {
        float l0 = rlog[n*4+0], l1 = rlog[n*4+1], l2 = rlog[n*4+2], l3 = rlog[n*4+3];
        float m = fmaxf(fmaxf(l0,l1), fmaxf(l2,l3));
        float e0 = expf(l0-m), e1 = expf(l1-m), e2 = expf(l2-m), e3 = expf(l3-m);
        float inv = 1.f/(e0+e1+e2+e3);
        p[0] += e0*inv; p[1] += e1*inv; p[2] += e2*inv; p[3] += e3*inv;
        ds += (float)dep[n];
    }
    float sums[5];
    float vals[5] = {p[0], p[1], p[2], p[3], ds};
    for (int v = 0; v < 5; v++) {
        red[tid] = vals[v]; __syncthreads();
        for (int o = 512; o > 0; o >>= 1) { if (tid < o) red[tid] += red[tid+o]; __syncthreads(); }
        sums[v] = red[0]; __syncthreads();
    }
    if (tid == 0) {
        const float u = 1.f/MAXD;
        float lb = 0.f;
        for (int m = 0; m < MAXD; m++) {
            float mp = sums[m] / (float)NN;
            lb += u * (logf(u) - logf(mp));
        }
        lb /= MAXD;
        float sparsity = (sums[4] / (float)NN) / MAXD;
        loss[0] = 0.01f*lb + 0.001f*sparsity;
    }
}

// ---------------- output tail ----------------
__global__ void finalize_kernel(const int* __restrict__ dep, const float* __restrict__ rlog,
                                const float* __restrict__ loss, float* __restrict__ out) {
    int i = blockIdx.x * blockDim.x + threadIdx.x;
    size_t base = (size_t)NN * VV;
    if (i < NN) out[base + i] = (float)dep[i];
    if (i == 0) out[base + NN] = loss[0];
    if (i < NN*MAXD) out[base + NN + 1 + i] = rlog[i];
}

// ---------------- host orchestration ----------------
extern "C" void kernel_launch(void* const* d_in, const int* in_sizes, int n_in,
                              void* d_out, int out_size) {
    const int*   ids  = (const int*)  d_in[0];
    const float* tok  = (const float*)d_in[1];
    const float* pos  = (const float*)d_in[2];
    const float* rw1  = (const float*)d_in[3];
    const float* rb1  = (const float*)d_in[4];
    const float* rw2  = (const float*)d_in[5];
    const float* rb2  = (const float*)d_in[6];
    const float* wqkv = (const float*)d_in[7];
    const float* bqkv = (const float*)d_in[8];
    const float* wo   = (const float*)d_in[9];
    const float* bo   = (const float*)d_in[10];
    const float* ln1g = (const float*)d_in[11];
    const float* ln1b = (const float*)d_in[12];
    const float* ln2g = (const float*)d_in[13];
    const float* ln2b = (const float*)d_in[14];
    const float* w1   = (const float*)d_in[15];
    const float* b1   = (const float*)d_in[16];
    const float* w2   = (const float*)d_in[17];
    const float* b2   = (const float*)d_in[18];
    const float* lnfg = (const float*)d_in[19];
    const float* lnfb = (const float*)d_in[20];
    const float* lmh  = (const float*)d_in[21];
    float* out = (float*)d_out;

    float *ph, *phn, *pqkv, *pattn, *pffa, *prl, *ploss;
    int* pdep;
    cudaGetSymbolAddress((void**)&ph,    g_h);
    cudaGetSymbolAddress((void**)&phn,   g_hn);
    cudaGetSymbolAddress((void**)&pqkv,  g_qkv);
    cudaGetSymbolAddress((void**)&pattn, g_attn);
    cudaGetSymbolAddress((void**)&pffa,  g_ffa);
    cudaGetSymbolAddress((void**)&prl,   g_rlog);
    cudaGetSymbolAddress((void**)&ploss, g_loss);
    cudaGetSymbolAddress((void**)&pdep,  g_dep);

    static const int ATTN_SMEM = (4*64*65 + 3*64) * sizeof(float) + 2*64*sizeof(int);
    cudaFuncSetAttribute(attn_tile_kernel, cudaFuncAttributeMaxDynamicSharedMemorySize, ATTN_SMEM);
    cudaFuncSetAttribute(gemm_b3<0>, cudaFuncAttributeMaxDynamicSharedMemorySize, GEMM_SMEM);
    cudaFuncSetAttribute(gemm_b3<1>, cudaFuncAttributeMaxDynamicSharedMemorySize, GEMM_SMEM);
    cudaFuncSetAttribute(gemm_lmh,   cudaFuncAttributeMaxDynamicSharedMemorySize, GEMM_SMEM);

    embed_kernel<<<(NN*EE + 255)/256, 256>>>(ids, tok, pos, ph);
    router_kernel<<<NN, RH>>>(ph, rw1, rb1, rw2, rb2, prl, pdep);

    for (int depth = 1; depth <= MAXD; depth++) {
        int li = depth - 1;
        ln_kernel<<<NN, 256>>>(ph, ln1g + li*EE, ln1b + li*EE, phn);
        {
            dim3 g(QKVW/128, NN/128);
            gemm_b3<0><<<g, 256, GEMM_SMEM>>>(phn, wqkv + (size_t)li*QKVW*EE, bqkv + li*QKVW, pqkv, QKVW, EE);
        }
        attn_tile_kernel<<<dim3(SS/64, HH, BB), 256, ATTN_SMEM>>>(pqkv, pdep, depth, pattn);
        {
            // wo: split-K x2 into partial buffers (g_qkv reused; free here), then reduce
            dim3 g(EE/128, NN/128, 2);
            gemm_b3<0><<<g, 256, GEMM_SMEM>>>(pattn, wo + (size_t)li*EE*EE, bo + li*EE, pqkv, EE, EE);
            add2_kernel<<<(NN*EE + 255)/256, 256>>>(ph, pqkv, pqkv + (size_t)NN*EE);
        }
        ln_kernel<<<NN, 256>>>(ph, ln2g + li*EE, ln2b + li*EE, phn);
        {
            dim3 g(II/128, NN/128);
            gemm_b3<1><<<g, 256, GEMM_SMEM>>>(phn, w1 + (size_t)li*II*EE, b1 + li*II, pffa, II, EE);
        }
        {
            // w2: split-K x2 (K=3072 -> 1536 per part, 192 CTAs), then reduce
            dim3 g(EE/128, NN/128, 2);
            gemm_b3<0><<<g, 256, GEMM_SMEM>>>(pffa, w2 + (size_t)li*EE*II, b2 + li*EE, pqkv, EE, II);
            add2_kernel<<<(NN*EE + 255)/256, 256>>>(ph, pqkv, pqkv + (size_t)NN*EE);
        }
    }

    ln_kernel<<<NN, 256>>>(ph, lnfg, lnfb, phn);
    {
        dim3 g(NN/128, (VV + 127)/128);   // x = m-tile, y = n-tile (W reuse in L2)
        gemm_lmh<<<g, 256, GEMM_SMEM>>>(phn, lmh, out, VV, EE);
    }

    loss_kernel<<<1, 1024>>>(prl, pdep, ploss);

    long long full = (long long)NN*VV + NN + 1 + (long long)NN*MAXD;
    if ((long long)out_size >= full)
        finalize_kernel<<<(NN*MAXD + 255)/256, 256>>>(pdep, prl, ploss, out);
}

// round 14
// speedup vs baseline: 1.2392x; 1.0360x over previous
#include <cuda_runtime.h>
#include <cuda_bf16.h>
#include <math.h>
#include <stdint.h>

// ---------------- problem constants ----------------
#define BB 2
#define SS 1024
#define NN (BB*SS)          // 2048 tokens
#define EE 768
#define HH 12
#define DD 64
#define II 3072
#define LL 4
#define RH 128
#define MAXD 4
#define VV 50257
#define QKVW (3*EE)         // 2304

// weight split offsets (elements)
#define WQKV_SZ (LL*QKVW*EE)
#define WO_SZ   (LL*EE*EE)
#define W1_SZ   (LL*II*EE)
#define W2_SZ   (LL*EE*II)
#define LMH_SZ  (VV*EE)
#define OFF_QKV 0
#define OFF_WO  (OFF_QKV + WQKV_SZ)
#define OFF_W1  (OFF_WO + WO_SZ)
#define OFF_W2  (OFF_W1 + W1_SZ)
#define OFF_LMH (OFF_W2 + W2_SZ)
#define WTOT    (OFF_LMH + LMH_SZ)   // 66,908,928

// ---------------- scratch (device globals; no allocation allowed) ----------------
__device__ float g_h   [NN*EE];
__device__ float g_qkv [NN*QKVW];   // fp32 qkv; also reused as 2x split-K partials
__device__ float g_rlog[NN*MAXD];
__device__ int   g_dep [NN];
__device__ float g_loss[1];
__device__ __align__(16) uint16_t g_hn_hi [NN*EE];
__device__ __align__(16) uint16_t g_hn_lo [NN*EE];
__device__ __align__(16) uint16_t g_at_hi [NN*EE];
__device__ __align__(16) uint16_t g_at_lo [NN*EE];
__device__ __align__(16) uint16_t g_ffa_hi[NN*II];
__device__ __align__(16) uint16_t g_ffa_lo[NN*II];
__device__ __align__(16) uint16_t g_whi[WTOT];
__device__ __align__(16) uint16_t g_wlo[WTOT];

// ---------------- bf16 split helpers ----------------
__device__ __forceinline__ void bsplit(float v, uint16_t& hi, uint16_t& lo) {
    __nv_bfloat16 hb = __float2bfloat16(v);          // RN
    float hf = __bfloat162float(hb);
    __nv_bfloat16 lb = __float2bfloat16(v - hf);     // RN residual
    hi = *reinterpret_cast<uint16_t*>(&hb);
    lo = *reinterpret_cast<uint16_t*>(&lb);
}

__device__ __forceinline__ void mma_bf16(float* d, const uint32_t* a, const uint32_t* b) {
    asm volatile(
        "mma.sync.aligned.m16n8k16.row.col.f32.bf16.bf16.f32 "
        "{%0,%1,%2,%3}, {%4,%5,%6,%7}, {%8,%9}, {%0,%1,%2,%3};"
        : "+f"(d[0]), "+f"(d[1]), "+f"(d[2]), "+f"(d[3])
        : "r"(a[0]), "r"(a[1]), "r"(a[2]), "r"(a[3]),
          "r"(b[0]), "r"(b[1]));
}

__device__ __forceinline__ void cp_async16(uint32_t dst, const void* src, bool pred) {
    int sz = pred ? 16 : 0;
    asm volatile("cp.async.ca.shared.global [%0], [%1], 16, %2;\n"
                 :: "r"(dst), "l"(src), "r"(sz));
}

// ---------------- weight pre-split: fp32 -> bf16 hi/lo (once per launch) ----------------
__global__ void wsplit_kernel(const float* __restrict__ w,
                              uint16_t* __restrict__ hi, uint16_t* __restrict__ lo, int n4) {
    int i = blockIdx.x * blockDim.x + threadIdx.x;
    if (i >= n4) return;
    float4 v = reinterpret_cast<const float4*>(w)[i];
    uint16_t h0,h1,h2,h3,l0,l1,l2,l3;
    bsplit(v.x, h0, l0); bsplit(v.y, h1, l1);
    bsplit(v.z, h2, l2); bsplit(v.w, h3, l3);
    ushort4 hv = make_ushort4(h0,h1,h2,h3);
    ushort4 lv = make_ushort4(l0,l1,l2,l3);
    reinterpret_cast<ushort4*>(hi)[i] = hv;
    reinterpret_cast<ushort4*>(lo)[i] = lv;
}

// ---------------- embedding ----------------
__global__ void embed_kernel(const int* __restrict__ ids,
                             const float* __restrict__ tok,
                             const float* __restrict__ pos,
                             float* __restrict__ h) {
    int i = blockIdx.x * blockDim.x + threadIdx.x;
    if (i >= NN*EE) return;
    int n = i / EE, e = i - n*EE;
    int s = n % SS;
    h[i] = tok[(size_t)ids[n]*EE + e] + pos[(size_t)s*EE + e];
}

// ---------------- router ----------------
__global__ void router_kernel(const float* __restrict__ h,
                              const float* __restrict__ w1, const float* __restrict__ b1,
                              const float* __restrict__ w2, const float* __restrict__ b2,
                              float* __restrict__ rlog, int* __restrict__ dep) {
    int n = blockIdx.x;
    int tid = threadIdx.x;   // 128 threads
    __shared__ float r1[RH];
    __shared__ float lg[MAXD];
    const float* hr = h + (size_t)n*EE;
    {
        const float4* hv = reinterpret_cast<const float4*>(hr);
        const float4* wv = reinterpret_cast<const float4*>(w1 + (size_t)tid*EE);
        float acc = b1[tid];
        #pragma unroll 4
        for (int e = 0; e < EE/4; e++) {
            float4 a = hv[e], b = wv[e];
            acc += a.x*b.x + a.y*b.y + a.z*b.z + a.w*b.w;
        }
        r1[tid] = fmaxf(acc, 0.f);
    }
    __syncthreads();
    if (tid < MAXD) {
        float acc = b2[tid];
        const float* wr = w2 + tid*RH;
        #pragma unroll 8
        for (int j = 0; j < RH; j++) acc += r1[j]*wr[j];
        lg[tid] = acc;
        rlog[n*MAXD + tid] = acc;
    }
    __syncthreads();
    if (tid == 0) {
        int best = 0; float bv = lg[0];
        #pragma unroll
        for (int m = 1; m < MAXD; m++) if (lg[m] > bv) { bv = lg[m]; best = m; }
        dep[n] = best + 1;
    }
}

// ---------------- layernorm per token, output pre-split to bf16 hi/lo ----------------
__global__ void ln_split_kernel(const float* __restrict__ x,
                                const float* __restrict__ g, const float* __restrict__ b,
                                uint16_t* __restrict__ yhi, uint16_t* __restrict__ ylo) {
    int n = blockIdx.x, tid = threadIdx.x;   // 256 threads
    __shared__ float red[256];
    __shared__ float s_mu, s_rstd;
    const float* xr = x + (size_t)n*EE;
    float s = 0.f;
    for (int e = tid; e < EE; e += 256) s += xr[e];
    red[tid] = s; __syncthreads();
    for (int o = 128; o > 0; o >>= 1) { if (tid < o) red[tid] += red[tid+o]; __syncthreads(); }
    if (tid == 0) s_mu = red[0] * (1.f/EE);
    __syncthreads();
    float mu = s_mu;
    float v = 0.f;
    for (int e = tid; e < EE; e += 256) { float d = xr[e]-mu; v += d*d; }
    red[tid] = v; __syncthreads();
    for (int o = 128; o > 0; o >>= 1) { if (tid < o) red[tid] += red[tid+o]; __syncthreads(); }
    if (tid == 0) s_rstd = rsqrtf(red[0]*(1.f/EE) + 1e-5f);
    __syncthreads();
    float rstd = s_rstd;
    for (int e = tid; e < EE; e += 256) {
        float y = (xr[e]-mu)*rstd*g[e] + b[e];
        uint16_t hi, lo;
        bsplit(y, hi, lo);
        yhi[(size_t)n*EE + e] = hi;
        ylo[(size_t)n*EE + e] = lo;
    }
}

// ---------------- split-K reduce: h += p0 + p1 ----------------
__global__ void add2_kernel(float* __restrict__ h,
                            const float* __restrict__ p0,
                            const float* __restrict__ p1) {
    int i = blockIdx.x * blockDim.x + threadIdx.x;
    if (i < NN*EE) h[i] += p0[i] + p1[i];
}

// ---------------- GEMM NT on pre-split bf16 operands (bf16x3 emulation) ----------------
// C[M,Nn] = act(A[M,K]*W[Nn,K]^T + bias).  M=2048.
// EPI 0: fp32 store (split-K aware).  EPI 1: gelu, then bf16 hi/lo split store.
// SWAPXY: 1 -> m-tile on blockIdx.x (lm_head L2 reuse).
// smem/stage: Ahi|Alo|Whi|Wlo, each 128 rows x 40 u16 (32 cols + pad) = 10240B.
#define PS_ARR_U16  (128*40)            // 5120
#define PS_STAGE_U16 (4*PS_ARR_U16)     // 20480
#define PS_SMEM (2*PS_STAGE_U16*2)      // bytes = 81920
template <int EPI, int SWAPXY>
__global__ __launch_bounds__(256, 2)
void gemm_ps(const uint16_t* __restrict__ Ahi, const uint16_t* __restrict__ Alo,
             const uint16_t* __restrict__ Whi, const uint16_t* __restrict__ Wlo,
             const float* __restrict__ bias, float* __restrict__ C,
             uint16_t* __restrict__ Chi, uint16_t* __restrict__ Clo,
             int Nn, int K) {
    extern __shared__ uint16_t su[];
    uint32_t sbase;
    asm("{ .reg .u64 t; cvta.to.shared.u64 t, %1; cvt.u32.u64 %0, t; }"
        : "=r"(sbase) : "l"(su));

    int tid = threadIdx.x;
    int m0 = (SWAPXY ? blockIdx.x : blockIdx.y) * 128;
    int n0 = (SWAPXY ? blockIdx.y : blockIdx.x) * 128;
    // split-K part
    int Kp = K / gridDim.z;
    int kbase = blockIdx.z * Kp;
    if (gridDim.z > 1) C += (size_t)blockIdx.z * (size_t)2048 * Nn;
    bool do_bias = (bias != nullptr) && (blockIdx.z == 0);

    int warp = tid >> 5, lane = tid & 31;
    int wm = (warp & 1) * 64;     // warp tile 64(m) x 32(n)
    int wn = (warp >> 1) * 32;
    int g = lane >> 2, t = lane & 3;

    float acc[4][4][4];
    #pragma unroll
    for (int mf = 0; mf < 4; mf++)
        #pragma unroll
        for (int nf = 0; nf < 4; nf++)
            #pragma unroll
            for (int i = 0; i < 4; i++) acc[mf][nf][i] = 0.f;

    const int nk = Kp >> 5;

    auto load_stage = [&](int st, int k0) {
        uint32_t base = sbase + (uint32_t)st * (PS_STAGE_U16 * 2u);
        #pragma unroll
        for (int cc = 0; cc < 2; cc++) {
            int c = tid + cc * 256;       // chunk 0..511
            int r = c >> 2;
            int q = (c & 3) * 8;          // col offset (elems)
            uint32_t so = (uint32_t)(r*40 + q) * 2u;
            size_t ga = (size_t)(m0 + r)*K + kbase + k0 + q;
            cp_async16(base              + so, Ahi + ga, true);
            cp_async16(base + 10240u     + so, Alo + ga, true);
            int nn = n0 + r;
            int nnc = nn < Nn ? nn : (Nn - 1);
            bool ok = nn < Nn;
            size_t gw = (size_t)nnc*K + kbase + k0 + q;
            cp_async16(base + 20480u     + so, Whi + gw, ok);
            cp_async16(base + 30720u     + so, Wlo + gw, ok);
        }
    };

    load_stage(0, 0);
    asm volatile("cp.async.commit_group;");

    for (int i = 0; i < nk; i++) {
        if (i + 1 < nk) {
            load_stage((i + 1) & 1, (i + 1) << 5);
            asm volatile("cp.async.commit_group;");
            asm volatile("cp.async.wait_group 1;");
        } else {
            asm volatile("cp.async.wait_group 0;");
        }
        __syncthreads();

        int st = i & 1;
        const uint16_t* sAhi = su + (size_t)st * PS_STAGE_U16;
        const uint16_t* sAlo = sAhi + PS_ARR_U16;
        const uint16_t* sWhi = sAhi + 2*PS_ARR_U16;
        const uint16_t* sWlo = sAhi + 3*PS_ARR_U16;

        #pragma unroll
        for (int ks = 0; ks < 2; ks++) {      // two k=16 steps per 32-tile
            int kk = ks * 16;
            int t2 = 2 * t;
            uint32_t ahi[4][4], alo[4][4], bhi[4][2], blo[4][2];
            #pragma unroll
            for (int mf = 0; mf < 4; mf++) {
                int mr = wm + mf*16;
                ahi[mf][0] = *reinterpret_cast<const uint32_t*>(sAhi + (mr+g  )*40 + kk + t2);
                ahi[mf][1] = *reinterpret_cast<const uint32_t*>(sAhi + (mr+g+8)*40 + kk + t2);
                ahi[mf][2] = *reinterpret_cast<const uint32_t*>(sAhi + (mr+g  )*40 + kk + t2 + 8);
                ahi[mf][3] = *reinterpret_cast<const uint32_t*>(sAhi + (mr+g+8)*40 + kk + t2 + 8);
                alo[mf][0] = *reinterpret_cast<const uint32_t*>(sAlo + (mr+g  )*40 + kk + t2);
                alo[mf][1] = *reinterpret_cast<const uint32_t*>(sAlo + (mr+g+8)*40 + kk + t2);
                alo[mf][2] = *reinterpret_cast<const uint32_t*>(sAlo + (mr+g  )*40 + kk + t2 + 8);
                alo[mf][3] = *reinterpret_cast<const uint32_t*>(sAlo + (mr+g+8)*40 + kk + t2 + 8);
            }
            #pragma unroll
            for (int nf = 0; nf < 4; nf++) {
                int nr = wn + nf*8;
                bhi[nf][0] = *reinterpret_cast<const uint32_t*>(sWhi + (nr+g)*40 + kk + t2);
                bhi[nf][1] = *reinterpret_cast<const uint32_t*>(sWhi + (nr+g)*40 + kk + t2 + 8);
                blo[nf][0] = *reinterpret_cast<const uint32_t*>(sWlo + (nr+g)*40 + kk + t2);
                blo[nf][1] = *reinterpret_cast<const uint32_t*>(sWlo + (nr+g)*40 + kk + t2 + 8);
            }
            #pragma unroll
            for (int mf = 0; mf < 4; mf++)
                #pragma unroll
                for (int nf = 0; nf < 4; nf++) {
                    mma_bf16(acc[mf][nf], ahi[mf], bhi[nf]);
                    mma_bf16(acc[mf][nf], alo[mf], bhi[nf]);
                    mma_bf16(acc[mf][nf], ahi[mf], blo[nf]);
                }
        }
        __syncthreads();
    }

    #pragma unroll
    for (int mf = 0; mf < 4; mf++) {
        #pragma unroll
        for (int nf = 0; nf < 4; nf++) {
            #pragma unroll
            for (int i = 0; i < 4; i++) {
                int m = m0 + wm + mf*16 + g + (i >> 1) * 8;
                int n = n0 + wn + nf*8 + t*2 + (i & 1);
                if (n < Nn) {
                    float v = acc[mf][nf][i] + (do_bias ? bias[n] : 0.f);
                    size_t ci = (size_t)m*Nn + n;
                    if (EPI == 1) {
                        v = 0.5f*v*(1.0f + erff(v*0.70710678118654752f));
                        uint16_t hi, lo;
                        bsplit(v, hi, lo);
                        Chi[ci] = hi;
                        Clo[ci] = lo;
                    } else {
                        C[ci] = v;
                    }
                }
            }
        }
    }
}

// ---------------- tiled attention: 64 q-rows per block, online softmax ----------------
// output written pre-split to bf16 hi/lo (consumed by wo GEMM)
__global__ __launch_bounds__(256)
void attn_tile_kernel(const float* __restrict__ qkv, const int* __restrict__ dep,
                      int depth, uint16_t* __restrict__ ohi, uint16_t* __restrict__ olo) {
    extern __shared__ float sm[];
    float (*Qs)[65] = (float(*)[65])(sm);
    float (*Ks)[65] = (float(*)[65])(sm + 64*65);
    float (*Vs)[65] = (float(*)[65])(sm + 2*64*65);
    float (*Ps)[65] = (float(*)[65])(sm + 3*64*65);
    float* m_s  = sm + 4*64*65;
    float* l_s  = m_s + 64;
    float* al_s = l_s + 64;
    int*   dq_s = (int*)(al_s + 64);
    int*   dk_s = dq_s + 64;

    int qt = blockIdx.x, h = blockIdx.y, b = blockIdx.z;
    int q0 = qt * 64;
    int tid = threadIdx.x;
    int tx = tid & 15, ty = tid >> 4;

    {
        int d4 = (tid & 15) * 4, q = tid >> 4;
        #pragma unroll
        for (int p = 0; p < 4; p++) {
            int qq = q + p*16;
            float4 v = *reinterpret_cast<const float4*>(
                &qkv[((size_t)b*SS + q0 + qq)*QKVW + h*DD + d4]);
            Qs[qq][d4+0] = v.x; Qs[qq][d4+1] = v.y; Qs[qq][d4+2] = v.z; Qs[qq][d4+3] = v.w;
        }
    }
    if (tid < 64) {
        dq_s[tid] = (dep[b*SS + q0 + tid] >= depth) ? 1 : 0;
        m_s[tid] = -1e30f;
        l_s[tid] = 0.f;
    }

    float O[4][4];
    #pragma unroll
    for (int i = 0; i < 4; i++)
        #pragma unroll
        for (int j = 0; j < 4; j++) O[i][j] = 0.f;

    for (int k0 = 0; k0 < SS; k0 += 64) {
        __syncthreads();
        {
            int d4 = (tid & 15) * 4, j = tid >> 4;
            #pragma unroll
            for (int p = 0; p < 4; p++) {
                int jj = j + p*16;
                size_t row = ((size_t)b*SS + k0 + jj)*QKVW + h*DD;
                float4 kv = *reinterpret_cast<const float4*>(&qkv[row + EE + d4]);
                Ks[jj][d4+0] = kv.x; Ks[jj][d4+1] = kv.y; Ks[jj][d4+2] = kv.z; Ks[jj][d4+3] = kv.w;
                float4 vv = *reinterpret_cast<const float4*>(&qkv[row + 2*EE + d4]);
                Vs[jj][d4+0] = vv.x; Vs[jj][d4+1] = vv.y; Vs[jj][d4+2] = vv.z; Vs[jj][d4+3] = vv.w;
            }
        }
        if (tid < 64) dk_s[tid] = (dep[b*SS + k0 + tid] >= depth) ? 1 : 0;
        __syncthreads();

        float sacc[4][4];
        #pragma unroll
        for (int i = 0; i < 4; i++)
            #pragma unroll
            for (int j = 0; j < 4; j++) sacc[i][j] = 0.f;
        #pragma unroll 8
        for (int d = 0; d < 64; d++) {
            float a[4], bb[4];
            #pragma unroll
            for (int i = 0; i < 4; i++) a[i] = Qs[ty*4+i][d];
            #pragma unroll
            for (int j = 0; j < 4; j++) bb[j] = Ks[tx*4+j][d];
            #pragma unroll
            for (int i = 0; i < 4; i++)
                #pragma unroll
                for (int j = 0; j < 4; j++) sacc[i][j] += a[i]*bb[j];
        }
        #pragma unroll
        for (int i = 0; i < 4; i++) {
            int row = ty*4 + i;
            int rowg = q0 + row;
            #pragma unroll
            for (int j = 0; j < 4; j++) {
                int col = tx*4 + j;
                int colg = k0 + col;
                float msk = (colg <= rowg && dq_s[row] && dk_s[col]) ? 1.f : 0.f;
                Ps[row][col] = sacc[i][j]*0.125f + msk;
            }
        }
        __syncthreads();

        {
            int rid = tid >> 2, sub = tid & 3;
            float mx = -1e30f;
            #pragma unroll
            for (int jj = 0; jj < 16; jj++) mx = fmaxf(mx, Ps[rid][sub*16+jj]);
            mx = fmaxf(mx, __shfl_xor_sync(0xffffffff, mx, 1));
            mx = fmaxf(mx, __shfl_xor_sync(0xffffffff, mx, 2));
            float mold = m_s[rid];
            float mnew = fmaxf(mold, mx);
            float sum = 0.f;
            #pragma unroll
            for (int jj = 0; jj < 16; jj++) {
                float p = __expf(Ps[rid][sub*16+jj] - mnew);
                Ps[rid][sub*16+jj] = p;
                sum += p;
            }
            sum += __shfl_xor_sync(0xffffffff, sum, 1);
            sum += __shfl_xor_sync(0xffffffff, sum, 2);
            if (sub == 0) {
                float alpha = __expf(mold - mnew);
                al_s[rid] = alpha;
                l_s[rid] = l_s[rid]*alpha + sum;
                m_s[rid] = mnew;
            }
        }
        __syncthreads();

        float alr[4];
        #pragma unroll
        for (int i = 0; i < 4; i++) alr[i] = al_s[ty*4+i];
        #pragma unroll
        for (int i = 0; i < 4; i++)
            #pragma unroll
            for (int j = 0; j < 4; j++) O[i][j] *= alr[i];
        #pragma unroll 8
        for (int k = 0; k < 64; k++) {
            float a[4], bb[4];
            #pragma unroll
            for (int i = 0; i < 4; i++) a[i] = Ps[ty*4+i][k];
            #pragma unroll
            for (int j = 0; j < 4; j++) bb[j] = Vs[k][tx*4+j];
            #pragma unroll
            for (int i = 0; i < 4; i++)
                #pragma unroll
                for (int j = 0; j < 4; j++) O[i][j] += a[i]*bb[j];
        }
    }
    __syncthreads();

    #pragma unroll
    for (int i = 0; i < 4; i++) {
        int row = ty*4 + i;
        float inv = 1.f / l_s[row];
        #pragma unroll
        for (int j = 0; j < 4; j++) {
            float v = O[i][j]*inv;
            size_t idx = ((size_t)b*SS + q0 + row)*EE + h*DD + tx*4 + j;
            uint16_t hi, lo;
            bsplit(v, hi, lo);
            ohi[idx] = hi;
            olo[idx] = lo;
        }
    }
}

// ---------------- router aux loss ----------------
__global__ void loss_kernel(const float* __restrict__ rlog, const int* __restrict__ dep,
                            float* __restrict__ loss) {
    int tid = threadIdx.x;  // 1024
    __shared__ float red[1024];
    float p[MAXD] = {0,0,0,0};
    float ds = 0.f;
    for (int n = tid; n < NN; n += 1024) {
        float l0 = rlog[n*4+0], l1 = rlog[n*4+1], l2 = rlog[n*4+2], l3 = rlog[n*4+3];
        float m = fmaxf(fmaxf(l0,l1), fmaxf(l2,l3));
        float e0 = expf(l0-m), e1 = expf(l1-m), e2 = expf(l2-m), e3 = expf(l3-m);
        float inv = 1.f/(e0+e1+e2+e3);
        p[0] += e0*inv; p[1] += e1*inv; p[2] += e2*inv; p[3] += e3*inv;
        ds += (float)dep[n];
    }
    float sums[5];
    float vals[5] = {p[0], p[1], p[2], p[3], ds};
    for (int v = 0; v < 5; v++) {
        red[tid] = vals[v]; __syncthreads();
        for (int o = 512; o > 0; o >>= 1) { if (tid < o) red[tid] += red[tid+o]; __syncthreads(); }
        sums[v] = red[0]; __syncthreads();
    }
    if (tid == 0) {
        const float u = 1.f/MAXD;
        float lb = 0.f;
        for (int m = 0; m < MAXD; m++) {
            float mp = sums[m] / (float)NN;
            lb += u * (logf(u) - logf(mp));
        }
        lb /= MAXD;
        float sparsity = (sums[4] / (float)NN) / MAXD;
        loss[0] = 0.01f*lb + 0.001f*sparsity;
    }
}

// ---------------- output tail ----------------
__global__ void finalize_kernel(const int* __restrict__ dep, const float* __restrict__ rlog,
                                const float* __restrict__ loss, float* __restrict__ out) {
    int i = blockIdx.x * blockDim.x + threadIdx.x;
    size_t base = (size_t)NN * VV;
    if (i < NN) out[base + i] = (float)dep[i];
    if (i == 0) out[base + NN] = loss[0];
    if (i < NN*MAXD) out[base + NN + 1 + i] = rlog[i];
}

// ---------------- host orchestration ----------------
extern "C" void kernel_launch(void* const* d_in, const int* in_sizes, int n_in,
                              void* d_out, int out_size) {
    const int*   ids  = (const int*)  d_in[0];
    const float* tok  = (const float*)d_in[1];
    const float* pos  = (const float*)d_in[2];
    const float* rw1  = (const float*)d_in[3];
    const float* rb1  = (const float*)d_in[4];
    const float* rw2  = (const float*)d_in[5];
    const float* rb2  = (const float*)d_in[6];
    const float* wqkv = (const float*)d_in[7];
    const float* bqkv = (const float*)d_in[8];
    const float* wo   = (const float*)d_in[9];
    const float* bo   = (const float*)d_in[10];
    const float* ln1g = (const float*)d_in[11];
    const float* ln1b = (const float*)d_in[12];
    const float* ln2g = (const float*)d_in[13];
    const float* ln2b = (const float*)d_in[14];
    const float* w1   = (const float*)d_in[15];
    const float* b1   = (const float*)d_in[16];
    const float* w2   = (const float*)d_in[17];
    const float* b2   = (const float*)d_in[18];
    const float* lnfg = (const float*)d_in[19];
    const float* lnfb = (const float*)d_in[20];
    const float* lmh  = (const float*)d_in[21];
    float* out = (float*)d_out;

    float *ph, *pqkv, *prl, *ploss;
    uint16_t *phnh, *phnl, *path, *patl, *pffh, *pffl, *pwhi, *pwlo;
    int* pdep;
    cudaGetSymbolAddress((void**)&ph,   g_h);
    cudaGetSymbolAddress((void**)&pqkv, g_qkv);
    cudaGetSymbolAddress((void**)&prl,  g_rlog);
    cudaGetSymbolAddress((void**)&ploss,g_loss);
    cudaGetSymbolAddress((void**)&pdep, g_dep);
    cudaGetSymbolAddress((void**)&phnh, g_hn_hi);
    cudaGetSymbolAddress((void**)&phnl, g_hn_lo);
    cudaGetSymbolAddress((void**)&path, g_at_hi);
    cudaGetSymbolAddress((void**)&patl, g_at_lo);
    cudaGetSymbolAddress((void**)&pffh, g_ffa_hi);
    cudaGetSymbolAddress((void**)&pffl, g_ffa_lo);
    cudaGetSymbolAddress((void**)&pwhi, g_whi);
    cudaGetSymbolAddress((void**)&pwlo, g_wlo);

    static const int ATTN_SMEM = (4*64*65 + 3*64) * sizeof(float) + 2*64*sizeof(int);
    cudaFuncSetAttribute(attn_tile_kernel, cudaFuncAttributeMaxDynamicSharedMemorySize, ATTN_SMEM);
    cudaFuncSetAttribute((gemm_ps<0,0>), cudaFuncAttributeMaxDynamicSharedMemorySize, PS_SMEM);
    cudaFuncSetAttribute((gemm_ps<1,0>), cudaFuncAttributeMaxDynamicSharedMemorySize, PS_SMEM);
    cudaFuncSetAttribute((gemm_ps<0,1>), cudaFuncAttributeMaxDynamicSharedMemorySize, PS_SMEM);

    // pre-split all weights (bf16 hi/lo; byte-neutral vs fp32)
    wsplit_kernel<<<(WQKV_SZ/4 + 255)/256, 256>>>(wqkv, pwhi + OFF_QKV, pwlo + OFF_QKV, WQKV_SZ/4);
    wsplit_kernel<<<(WO_SZ/4   + 255)/256, 256>>>(wo,   pwhi + OFF_WO,  pwlo + OFF_WO,  WO_SZ/4);
    wsplit_kernel<<<(W1_SZ/4   + 255)/256, 256>>>(w1,   pwhi + OFF_W1,  pwlo + OFF_W1,  W1_SZ/4);
    wsplit_kernel<<<(W2_SZ/4   + 255)/256, 256>>>(w2,   pwhi + OFF_W2,  pwlo + OFF_W2,  W2_SZ/4);
    wsplit_kernel<<<(LMH_SZ/4  + 255)/256, 256>>>(lmh,  pwhi + OFF_LMH, pwlo + OFF_LMH, LMH_SZ/4);

    embed_kernel<<<(NN*EE + 255)/256, 256>>>(ids, tok, pos, ph);
    router_kernel<<<NN, RH>>>(ph, rw1, rb1, rw2, rb2, prl, pdep);

    for (int depth = 1; depth <= MAXD; depth++) {
        int li = depth - 1;
        ln_split_kernel<<<NN, 256>>>(ph, ln1g + li*EE, ln1b + li*EE, phnh, phnl);
        {
            dim3 g(QKVW/128, NN/128);
            gemm_ps<0,0><<<g, 256, PS_SMEM>>>(phnh, phnl,
                pwhi + OFF_QKV + (size_t)li*QKVW*EE, pwlo + OFF_QKV + (size_t)li*QKVW*EE,
                bqkv + li*QKVW, pqkv, nullptr, nullptr, QKVW, EE);
        }
        attn_tile_kernel<<<dim3(SS/64, HH, BB), 256, ATTN_SMEM>>>(pqkv, pdep, depth, path, patl);
        {
            // wo: split-K x2 into fp32 partials (g_qkv reused), then reduce
            dim3 g(EE/128, NN/128, 2);
            gemm_ps<0,0><<<g, 256, PS_SMEM>>>(path, patl,
                pwhi + OFF_WO + (size_t)li*EE*EE, pwlo + OFF_WO + (size_t)li*EE*EE,
                bo + li*EE, pqkv, nullptr, nullptr, EE, EE);
            add2_kernel<<<(NN*EE + 255)/256, 256>>>(ph, pqkv, pqkv + (size_t)NN*EE);
        }
        ln_split_kernel<<<NN, 256>>>(ph, ln2g + li*EE, ln2b + li*EE, phnh, phnl);
        {
            dim3 g(II/128, NN/128);
            gemm_ps<1,0><<<g, 256, PS_SMEM>>>(phnh, phnl,
                pwhi + OFF_W1 + (size_t)li*II*EE, pwlo + OFF_W1 + (size_t)li*II*EE,
                b1 + li*II, nullptr, pffh, pffl, II, EE);
        }
        {
            // w2: split-K x2, fp32 partials, then reduce
            dim3 g(EE/128, NN/128, 2);
            gemm_ps<0,0><<<g, 256, PS_SMEM>>>(pffh, pffl,
                pwhi + OFF_W2 + (size_t)li*EE*II, pwlo + OFF_W2 + (size_t)li*EE*II,
                b2 + li*EE, pqkv, nullptr, nullptr, EE, II);
            add2_kernel<<<(NN*EE + 255)/256, 256>>>(ph, pqkv, pqkv + (size_t)NN*EE);
        }
    }

    ln_split_kernel<<<NN, 256>>>(ph, lnfg, lnfb, phnh, phnl);
    {
        dim3 g(NN/128, (VV + 127)/128);   // x = m-tile, y = n-tile (W reuse in L2)
        gemm_ps<0,1><<<g, 256, PS_SMEM>>>(phnh, phnl,
            pwhi + OFF_LMH, pwlo + OFF_LMH,
            (const float*)nullptr, out, nullptr, nullptr, VV, EE);
    }

    loss_kernel<<<1, 1024>>>(prl, pdep, ploss);

    long long full = (long long)NN*VV + NN + 1 + (long long)NN*MAXD;
    if ((long long)out_size >= full)
        finalize_kernel<<<(NN*MAXD + 255)/256, 256>>>(pdep, prl, ploss, out);
}

// round 15
// speedup vs baseline: 1.3294x; 1.0728x over previous
#include <cuda_runtime.h>
#include <cuda_bf16.h>
#include <math.h>
#include <stdint.h>

// ---------------- problem constants ----------------
#define BB 2
#define SS 1024
#define NN (BB*SS)          // 2048 tokens
#define EE 768
#define HH 12
#define DD 64
#define II 3072
#define LL 4
#define RH 128
#define MAXD 4
#define VV 50257
#define QKVW (3*EE)         // 2304

// weight split offsets (elements)
#define WQKV_SZ (LL*QKVW*EE)
#define WO_SZ   (LL*EE*EE)
#define W1_SZ   (LL*II*EE)
#define W2_SZ   (LL*EE*II)
#define LMH_SZ  (VV*EE)
#define OFF_QKV 0
#define OFF_WO  (OFF_QKV + WQKV_SZ)
#define OFF_W1  (OFF_WO + WO_SZ)
#define OFF_W2  (OFF_W1 + W1_SZ)
#define OFF_LMH (OFF_W2 + W2_SZ)
#define WTOT    (OFF_LMH + LMH_SZ)   // 66,908,928

// ---------------- scratch (device globals; no allocation allowed) ----------------
__device__ float g_h   [NN*EE];
__device__ float g_qkv [NN*QKVW];   // fp32 qkv; also reused as 2x split-K partials
__device__ float g_rlog[NN*MAXD];
__device__ int   g_dep [NN];
__device__ float g_loss[1];
__device__ __align__(16) uint16_t g_hn_hi [NN*EE];
__device__ __align__(16) uint16_t g_hn_lo [NN*EE];
__device__ __align__(16) uint16_t g_at_hi [NN*EE];
__device__ __align__(16) uint16_t g_at_lo [NN*EE];
__device__ __align__(16) uint16_t g_ffa_hi[NN*II];
__device__ __align__(16) uint16_t g_ffa_lo[NN*II];
__device__ __align__(16) uint16_t g_whi[WTOT];
__device__ __align__(16) uint16_t g_wlo[WTOT];

// ---------------- bf16 split helpers ----------------
__device__ __forceinline__ void bsplit(float v, uint16_t& hi, uint16_t& lo) {
    __nv_bfloat16 hb = __float2bfloat16(v);          // RN
    float hf = __bfloat162float(hb);
    __nv_bfloat16 lb = __float2bfloat16(v - hf);     // RN residual
    hi = *reinterpret_cast<uint16_t*>(&hb);
    lo = *reinterpret_cast<uint16_t*>(&lb);
}
__device__ __forceinline__ void bsplit4(float4 v, ushort4& h, ushort4& l) {
    bsplit(v.x, h.x, l.x); bsplit(v.y, h.y, l.y);
    bsplit(v.z, h.z, l.z); bsplit(v.w, h.w, l.w);
}

__device__ __forceinline__ void mma_bf16(float* d, const uint32_t* a, const uint32_t* b) {
    asm volatile(
        "mma.sync.aligned.m16n8k16.row.col.f32.bf16.bf16.f32 "
        "{%0,%1,%2,%3}, {%4,%5,%6,%7}, {%8,%9}, {%0,%1,%2,%3};"
        : "+f"(d[0]), "+f"(d[1]), "+f"(d[2]), "+f"(d[3])
        : "r"(a[0]), "r"(a[1]), "r"(a[2]), "r"(a[3]),
          "r"(b[0]), "r"(b[1]));
}

__device__ __forceinline__ void cp_async16(uint32_t dst, const void* src, bool pred) {
    int sz = pred ? 16 : 0;
    asm volatile("cp.async.ca.shared.global [%0], [%1], 16, %2;\n"
                 :: "r"(dst), "l"(src), "r"(sz));
}

// ---------------- weight pre-split: fp32 -> bf16 hi/lo (once per launch) ----------------
__global__ void wsplit_kernel(const float* __restrict__ w,
                              uint16_t* __restrict__ hi, uint16_t* __restrict__ lo, int n4) {
    int i = blockIdx.x * blockDim.x + threadIdx.x;
    if (i >= n4) return;
    float4 v = reinterpret_cast<const float4*>(w)[i];
    ushort4 hv, lv;
    bsplit4(v, hv, lv);
    reinterpret_cast<ushort4*>(hi)[i] = hv;
    reinterpret_cast<ushort4*>(lo)[i] = lv;
}

// ---------------- embedding ----------------
__global__ void embed_kernel(const int* __restrict__ ids,
                             const float* __restrict__ tok,
                             const float* __restrict__ pos,
                             float* __restrict__ h) {
    int i = blockIdx.x * blockDim.x + threadIdx.x;
    if (i >= NN*EE) return;
    int n = i / EE, e = i - n*EE;
    int s = n % SS;
    h[i] = tok[(size_t)ids[n]*EE + e] + pos[(size_t)s*EE + e];
}

// ---------------- router ----------------
__global__ void router_kernel(const float* __restrict__ h,
                              const float* __restrict__ w1, const float* __restrict__ b1,
                              const float* __restrict__ w2, const float* __restrict__ b2,
                              float* __restrict__ rlog, int* __restrict__ dep) {
    int n = blockIdx.x;
    int tid = threadIdx.x;   // 128 threads
    __shared__ float r1[RH];
    __shared__ float lg[MAXD];
    const float* hr = h + (size_t)n*EE;
    {
        const float4* hv = reinterpret_cast<const float4*>(hr);
        const float4* wv = reinterpret_cast<const float4*>(w1 + (size_t)tid*EE);
        float acc = b1[tid];
        #pragma unroll 4
        for (int e = 0; e < EE/4; e++) {
            float4 a = hv[e], b = wv[e];
            acc += a.x*b.x + a.y*b.y + a.z*b.z + a.w*b.w;
        }
        r1[tid] = fmaxf(acc, 0.f);
    }
    __syncthreads();
    if (tid < MAXD) {
        float acc = b2[tid];
        const float* wr = w2 + tid*RH;
        #pragma unroll 8
        for (int j = 0; j < RH; j++) acc += r1[j]*wr[j];
        lg[tid] = acc;
        rlog[n*MAXD + tid] = acc;
    }
    __syncthreads();
    if (tid == 0) {
        int best = 0; float bv = lg[0];
        #pragma unroll
        for (int m = 1; m < MAXD; m++) if (lg[m] > bv) { bv = lg[m]; best = m; }
        dep[n] = best + 1;
    }
}

// ---------------- layernorm per token, output pre-split to bf16 hi/lo ----------------
__global__ void ln_split_kernel(const float* __restrict__ x,
                                const float* __restrict__ g, const float* __restrict__ b,
                                uint16_t* __restrict__ yhi, uint16_t* __restrict__ ylo) {
    int n = blockIdx.x, tid = threadIdx.x;   // 256 threads
    __shared__ float red[256];
    __shared__ float s_mu, s_rstd;
    const float* xr = x + (size_t)n*EE;
    float s = 0.f;
    for (int e = tid; e < EE; e += 256) s += xr[e];
    red[tid] = s; __syncthreads();
    for (int o = 128; o > 0; o >>= 1) { if (tid < o) red[tid] += red[tid+o]; __syncthreads(); }
    if (tid == 0) s_mu = red[0] * (1.f/EE);
    __syncthreads();
    float mu = s_mu;
    float v = 0.f;
    for (int e = tid; e < EE; e += 256) { float d = xr[e]-mu; v += d*d; }
    red[tid] = v; __syncthreads();
    for (int o = 128; o > 0; o >>= 1) { if (tid < o) red[tid] += red[tid+o]; __syncthreads(); }
    if (tid == 0) s_rstd = rsqrtf(red[0]*(1.f/EE) + 1e-5f);
    __syncthreads();
    float rstd = s_rstd;
    for (int e = tid; e < EE; e += 256) {
        float y = (xr[e]-mu)*rstd*g[e] + b[e];
        uint16_t hi, lo;
        bsplit(y, hi, lo);
        yhi[(size_t)n*EE + e] = hi;
        ylo[(size_t)n*EE + e] = lo;
    }
}

// ---------------- split-K reduce: h += p0 + p1 ----------------
__global__ void add2_kernel(float* __restrict__ h,
                            const float* __restrict__ p0,
                            const float* __restrict__ p1) {
    int i = blockIdx.x * blockDim.x + threadIdx.x;
    if (i < NN*EE) h[i] += p0[i] + p1[i];
}

// ---------------- GEMM NT on pre-split bf16 operands (bf16x3 emulation) ----------------
#define PS_ARR_U16  (128*40)            // 5120
#define PS_STAGE_U16 (4*PS_ARR_U16)     // 20480
#define PS_SMEM (2*PS_STAGE_U16*2)      // bytes = 81920
template <int EPI, int SWAPXY>
__global__ __launch_bounds__(256, 2)
void gemm_ps(const uint16_t* __restrict__ Ahi, const uint16_t* __restrict__ Alo,
             const uint16_t* __restrict__ Whi, const uint16_t* __restrict__ Wlo,
             const float* __restrict__ bias, float* __restrict__ C,
             uint16_t* __restrict__ Chi, uint16_t* __restrict__ Clo,
             int Nn, int K) {
    extern __shared__ uint16_t su[];
    uint32_t sbase;
    asm("{ .reg .u64 t; cvta.to.shared.u64 t, %1; cvt.u32.u64 %0, t; }"
        : "=r"(sbase) : "l"(su));

    int tid = threadIdx.x;
    int m0 = (SWAPXY ? blockIdx.x : blockIdx.y) * 128;
    int n0 = (SWAPXY ? blockIdx.y : blockIdx.x) * 128;
    int Kp = K / gridDim.z;
    int kbase = blockIdx.z * Kp;
    if (gridDim.z > 1) C += (size_t)blockIdx.z * (size_t)2048 * Nn;
    bool do_bias = (bias != nullptr) && (blockIdx.z == 0);

    int warp = tid >> 5, lane = tid & 31;
    int wm = (warp & 1) * 64;     // warp tile 64(m) x 32(n)
    int wn = (warp >> 1) * 32;
    int g = lane >> 2, t = lane & 3;

    float acc[4][4][4];
    #pragma unroll
    for (int mf = 0; mf < 4; mf++)
        #pragma unroll
        for (int nf = 0; nf < 4; nf++)
            #pragma unroll
            for (int i = 0; i < 4; i++) acc[mf][nf][i] = 0.f;

    const int nk = Kp >> 5;

    auto load_stage = [&](int st, int k0) {
        uint32_t base = sbase + (uint32_t)st * (PS_STAGE_U16 * 2u);
        #pragma unroll
        for (int cc = 0; cc < 2; cc++) {
            int c = tid + cc * 256;       // chunk 0..511
            int r = c >> 2;
            int q = (c & 3) * 8;          // col offset (elems)
            uint32_t so = (uint32_t)(r*40 + q) * 2u;
            size_t ga = (size_t)(m0 + r)*K + kbase + k0 + q;
            cp_async16(base              + so, Ahi + ga, true);
            cp_async16(base + 10240u     + so, Alo + ga, true);
            int nn = n0 + r;
            int nnc = nn < Nn ? nn : (Nn - 1);
            bool ok = nn < Nn;
            size_t gw = (size_t)nnc*K + kbase + k0 + q;
            cp_async16(base + 20480u     + so, Whi + gw, ok);
            cp_async16(base + 30720u     + so, Wlo + gw, ok);
        }
    };

    load_stage(0, 0);
    asm volatile("cp.async.commit_group;");

    for (int i = 0; i < nk; i++) {
        if (i + 1 < nk) {
            load_stage((i + 1) & 1, (i + 1) << 5);
            asm volatile("cp.async.commit_group;");
            asm volatile("cp.async.wait_group 1;");
        } else {
            asm volatile("cp.async.wait_group 0;");
        }
        __syncthreads();

        int st = i & 1;
        const uint16_t* sAhi = su + (size_t)st * PS_STAGE_U16;
        const uint16_t* sAlo = sAhi + PS_ARR_U16;
        const uint16_t* sWhi = sAhi + 2*PS_ARR_U16;
        const uint16_t* sWlo = sAhi + 3*PS_ARR_U16;

        #pragma unroll
        for (int ks = 0; ks < 2; ks++) {      // two k=16 steps per 32-tile
            int kk = ks * 16;
            int t2 = 2 * t;
            uint32_t ahi[4][4], alo[4][4], bhi[4][2], blo[4][2];
            #pragma unroll
            for (int mf = 0; mf < 4; mf++) {
                int mr = wm + mf*16;
                ahi[mf][0] = *reinterpret_cast<const uint32_t*>(sAhi + (mr+g  )*40 + kk + t2);
                ahi[mf][1] = *reinterpret_cast<const uint32_t*>(sAhi + (mr+g+8)*40 + kk + t2);
                ahi[mf][2] = *reinterpret_cast<const uint32_t*>(sAhi + (mr+g  )*40 + kk + t2 + 8);
                ahi[mf][3] = *reinterpret_cast<const uint32_t*>(sAhi + (mr+g+8)*40 + kk + t2 + 8);
                alo[mf][0] = *reinterpret_cast<const uint32_t*>(sAlo + (mr+g  )*40 + kk + t2);
                alo[mf][1] = *reinterpret_cast<const uint32_t*>(sAlo + (mr+g+8)*40 + kk + t2);
                alo[mf][2] = *reinterpret_cast<const uint32_t*>(sAlo + (mr+g  )*40 + kk + t2 + 8);
                alo[mf][3] = *reinterpret_cast<const uint32_t*>(sAlo + (mr+g+8)*40 + kk + t2 + 8);
            }
            #pragma unroll
            for (int nf = 0; nf < 4; nf++) {
                int nr = wn + nf*8;
                bhi[nf][0] = *reinterpret_cast<const uint32_t*>(sWhi + (nr+g)*40 + kk + t2);
                bhi[nf][1] = *reinterpret_cast<const uint32_t*>(sWhi + (nr+g)*40 + kk + t2 + 8);
                blo[nf][0] = *reinterpret_cast<const uint32_t*>(sWlo + (nr+g)*40 + kk + t2);
                blo[nf][1] = *reinterpret_cast<const uint32_t*>(sWlo + (nr+g)*40 + kk + t2 + 8);
            }
            #pragma unroll
            for (int mf = 0; mf < 4; mf++)
                #pragma unroll
                for (int nf = 0; nf < 4; nf++) {
                    mma_bf16(acc[mf][nf], ahi[mf], bhi[nf]);
                    mma_bf16(acc[mf][nf], alo[mf], bhi[nf]);
                    mma_bf16(acc[mf][nf], ahi[mf], blo[nf]);
                }
        }
        __syncthreads();
    }

    #pragma unroll
    for (int mf = 0; mf < 4; mf++) {
        #pragma unroll
        for (int nf = 0; nf < 4; nf++) {
            #pragma unroll
            for (int i = 0; i < 4; i++) {
                int m = m0 + wm + mf*16 + g + (i >> 1) * 8;
                int n = n0 + wn + nf*8 + t*2 + (i & 1);
                if (n < Nn) {
                    float v = acc[mf][nf][i] + (do_bias ? bias[n] : 0.f);
                    size_t ci = (size_t)m*Nn + n;
                    if (EPI == 1) {
                        v = 0.5f*v*(1.0f + erff(v*0.70710678118654752f));
                        uint16_t hi, lo;
                        bsplit(v, hi, lo);
                        Chi[ci] = hi;
                        Clo[ci] = lo;
                    } else {
                        C[ci] = v;
                    }
                }
            }
        }
    }
}

// ---------------- attention via bf16x3 MMA: 64 q-rows per block, online softmax ----------------
// smem: Ps (64x65 f32) | stats | 8 u16 tiles (Qhi,Qlo,Khi,Klo,Vth,Vtl,Phi,Plo) 64x72
#define AT_TILE_U16 (64*72)
#define AT_STAT_OFF 16640
#define AT_U16_OFF  17920
#define AT_SMEM     (AT_U16_OFF + 8*AT_TILE_U16*2)   // 17920 + 147456/2? -> bytes: 8*9216 = 73728 -> 91648
__global__ __launch_bounds__(256)
void attn_mma_kernel(const float* __restrict__ qkv, const int* __restrict__ dep,
                     int depth, uint16_t* __restrict__ ohi, uint16_t* __restrict__ olo) {
    extern __shared__ char smc[];
    float (*Ps)[65] = (float(*)[65])(smc);
    float* m_s  = (float*)(smc + AT_STAT_OFF);
    float* l_s  = m_s + 64;
    float* al_s = l_s + 64;
    int*   dq_s = (int*)(al_s + 64);
    int*   dk_s = dq_s + 64;
    uint16_t* u16b = (uint16_t*)(smc + AT_U16_OFF);
    uint16_t* Qhi = u16b;
    uint16_t* Qlo = u16b + 1*AT_TILE_U16;
    uint16_t* Khi = u16b + 2*AT_TILE_U16;
    uint16_t* Klo = u16b + 3*AT_TILE_U16;
    uint16_t* Vth = u16b + 4*AT_TILE_U16;
    uint16_t* Vtl = u16b + 5*AT_TILE_U16;
    uint16_t* Phi = u16b + 6*AT_TILE_U16;
    uint16_t* Plo = u16b + 7*AT_TILE_U16;

    int qt = blockIdx.x, h = blockIdx.y, b = blockIdx.z;
    int q0 = qt * 64;
    int tid = threadIdx.x;
    int warp = tid >> 5, lane = tid & 31;
    int g = lane >> 2, t = lane & 3;
    int wm = (warp & 3) * 16;      // 4 m-tiles of 16
    int wn = (warp >> 2) * 32;     // 2 n-groups of 32
    int t2 = 2 * t;

    // load + split Q
    {
        int d4 = (tid & 15) * 4, r = tid >> 4;
        #pragma unroll
        for (int p = 0; p < 4; p++) {
            int row = r + p*16;
            float4 v = *reinterpret_cast<const float4*>(
                &qkv[((size_t)b*SS + q0 + row)*QKVW + h*DD + d4]);
            ushort4 hv, lv;
            bsplit4(v, hv, lv);
            *reinterpret_cast<ushort4*>(&Qhi[row*72 + d4]) = hv;
            *reinterpret_cast<ushort4*>(&Qlo[row*72 + d4]) = lv;
        }
    }
    if (tid < 64) {
        dq_s[tid] = (dep[b*SS + q0 + tid] >= depth) ? 1 : 0;
        m_s[tid] = -1e30f;
        l_s[tid] = 0.f;
    }

    float O[4][4];
    #pragma unroll
    for (int nf = 0; nf < 4; nf++)
        #pragma unroll
        for (int i = 0; i < 4; i++) O[nf][i] = 0.f;

    for (int k0 = 0; k0 < SS; k0 += 64) {
        __syncthreads();   // prior PV done; safe to overwrite K/V tiles
        {
            int d4 = (tid & 15) * 4, r = tid >> 4;
            #pragma unroll
            for (int p = 0; p < 4; p++) {
                int jj = r + p*16;
                size_t row = ((size_t)b*SS + k0 + jj)*QKVW + h*DD;
                float4 kv = *reinterpret_cast<const float4*>(&qkv[row + EE + d4]);
                ushort4 hv, lv;
                bsplit4(kv, hv, lv);
                *reinterpret_cast<ushort4*>(&Khi[jj*72 + d4]) = hv;
                *reinterpret_cast<ushort4*>(&Klo[jj*72 + d4]) = lv;
                float4 vv = *reinterpret_cast<const float4*>(&qkv[row + 2*EE + d4]);
                uint16_t hh, ll;
                bsplit(vv.x, hh, ll); Vth[(d4+0)*72 + jj] = hh; Vtl[(d4+0)*72 + jj] = ll;
                bsplit(vv.y, hh, ll); Vth[(d4+1)*72 + jj] = hh; Vtl[(d4+1)*72 + jj] = ll;
                bsplit(vv.z, hh, ll); Vth[(d4+2)*72 + jj] = hh; Vtl[(d4+2)*72 + jj] = ll;
                bsplit(vv.w, hh, ll); Vth[(d4+3)*72 + jj] = hh; Vtl[(d4+3)*72 + jj] = ll;
            }
        }
        if (tid < 64) dk_s[tid] = (dep[b*SS + k0 + tid] >= depth) ? 1 : 0;
        __syncthreads();

        // S = Q K^T (bf16x3 MMA)
        float sacc[4][4];
        #pragma unroll
        for (int nf = 0; nf < 4; nf++)
            #pragma unroll
            for (int i = 0; i < 4; i++) sacc[nf][i] = 0.f;
        #pragma unroll
        for (int ks = 0; ks < 4; ks++) {
            int kk = ks * 16;
            uint32_t ah[4], al[4];
            ah[0] = *reinterpret_cast<const uint32_t*>(&Qhi[(wm+g  )*72 + kk + t2]);
            ah[1] = *reinterpret_cast<const uint32_t*>(&Qhi[(wm+g+8)*72 + kk + t2]);
            ah[2] = *reinterpret_cast<const uint32_t*>(&Qhi[(wm+g  )*72 + kk + t2 + 8]);
            ah[3] = *reinterpret_cast<const uint32_t*>(&Qhi[(wm+g+8)*72 + kk + t2 + 8]);
            al[0] = *reinterpret_cast<const uint32_t*>(&Qlo[(wm+g  )*72 + kk + t2]);
            al[1] = *reinterpret_cast<const uint32_t*>(&Qlo[(wm+g+8)*72 + kk + t2]);
            al[2] = *reinterpret_cast<const uint32_t*>(&Qlo[(wm+g  )*72 + kk + t2 + 8]);
            al[3] = *reinterpret_cast<const uint32_t*>(&Qlo[(wm+g+8)*72 + kk + t2 + 8]);
            #pragma unroll
            for (int nf = 0; nf < 4; nf++) {
                int nr = wn + nf*8 + g;
                uint32_t bh[2], bl[2];
                bh[0] = *reinterpret_cast<const uint32_t*>(&Khi[nr*72 + kk + t2]);
                bh[1] = *reinterpret_cast<const uint32_t*>(&Khi[nr*72 + kk + t2 + 8]);
                bl[0] = *reinterpret_cast<const uint32_t*>(&Klo[nr*72 + kk + t2]);
                bl[1] = *reinterpret_cast<const uint32_t*>(&Klo[nr*72 + kk + t2 + 8]);
                mma_bf16(sacc[nf], ah, bh);
                mma_bf16(sacc[nf], al, bh);
                mma_bf16(sacc[nf], ah, bl);
            }
        }
        // write S -> Ps with scale + additive mask
        #pragma unroll
        for (int nf = 0; nf < 4; nf++) {
            #pragma unroll
            for (int i = 0; i < 4; i++) {
                int row = wm + g + (i >> 1) * 8;
                int col = wn + nf*8 + t2 + (i & 1);
                float msk = (k0 + col <= q0 + row && dq_s[row] && dk_s[col]) ? 1.f : 0.f;
                Ps[row][col] = sacc[nf][i]*0.125f + msk;
            }
        }
        __syncthreads();

        // online softmax over this 64-col tile; write P as bf16 hi/lo
        {
            int rid = tid >> 2, sub = tid & 3;
            float mx = -1e30f;
            #pragma unroll
            for (int jj = 0; jj < 16; jj++) mx = fmaxf(mx, Ps[rid][sub*16+jj]);
            mx = fmaxf(mx, __shfl_xor_sync(0xffffffff, mx, 1));
            mx = fmaxf(mx, __shfl_xor_sync(0xffffffff, mx, 2));
            float mold = m_s[rid];
            float mnew = fmaxf(mold, mx);
            float sum = 0.f;
            #pragma unroll
            for (int jj = 0; jj < 16; jj++) {
                float p = __expf(Ps[rid][sub*16+jj] - mnew);
                sum += p;
                uint16_t hi, lo;
                bsplit(p, hi, lo);
                Phi[rid*72 + sub*16 + jj] = hi;
                Plo[rid*72 + sub*16 + jj] = lo;
            }
            sum += __shfl_xor_sync(0xffffffff, sum, 1);
            sum += __shfl_xor_sync(0xffffffff, sum, 2);
            if (sub == 0) {
                float alpha = __expf(mold - mnew);
                al_s[rid] = alpha;
                l_s[rid] = l_s[rid]*alpha + sum;
                m_s[rid] = mnew;
            }
        }
        __syncthreads();

        // O = O*alpha + P V (bf16x3 MMA)
        float a0 = al_s[wm + g], a1 = al_s[wm + g + 8];
        #pragma unroll
        for (int nf = 0; nf < 4; nf++) {
            O[nf][0] *= a0; O[nf][1] *= a0;
            O[nf][2] *= a1; O[nf][3] *= a1;
        }
        #pragma unroll
        for (int ks = 0; ks < 4; ks++) {
            int kk = ks * 16;
            uint32_t ah[4], al[4];
            ah[0] = *reinterpret_cast<const uint32_t*>(&Phi[(wm+g  )*72 + kk + t2]);
            ah[1] = *reinterpret_cast<const uint32_t*>(&Phi[(wm+g+8)*72 + kk + t2]);
            ah[2] = *reinterpret_cast<const uint32_t*>(&Phi[(wm+g  )*72 + kk + t2 + 8]);
            ah[3] = *reinterpret_cast<const uint32_t*>(&Phi[(wm+g+8)*72 + kk + t2 + 8]);
            al[0] = *reinterpret_cast<const uint32_t*>(&Plo[(wm+g  )*72 + kk + t2]);
            al[1] = *reinterpret_cast<const uint32_t*>(&Plo[(wm+g+8)*72 + kk + t2]);
            al[2] = *reinterpret_cast<const uint32_t*>(&Plo[(wm+g  )*72 + kk + t2 + 8]);
            al[3] = *reinterpret_cast<const uint32_t*>(&Plo[(wm+g+8)*72 + kk + t2 + 8]);
            #pragma unroll
            for (int nf = 0; nf < 4; nf++) {
                int nr = wn + nf*8 + g;
                uint32_t bh[2], bl[2];
                bh[0] = *reinterpret_cast<const uint32_t*>(&Vth[nr*72 + kk + t2]);
                bh[1] = *reinterpret_cast<const uint32_t*>(&Vth[nr*72 + kk + t2 + 8]);
                bl[0] = *reinterpret_cast<const uint32_t*>(&Vtl[nr*72 + kk + t2]);
                bl[1] = *reinterpret_cast<const uint32_t*>(&Vtl[nr*72 + kk + t2 + 8]);
                mma_bf16(O[nf], ah, bh);
                mma_bf16(O[nf], al, bh);
                mma_bf16(O[nf], ah, bl);
            }
        }
    }

    // epilogue: scale by 1/l, split-store to bf16 hi/lo
    float inv0 = 1.f / l_s[wm + g], inv1 = 1.f / l_s[wm + g + 8];
    #pragma unroll
    for (int nf = 0; nf < 4; nf++) {
        #pragma unroll
        for (int i = 0; i < 4; i++) {
            int row = wm + g + (i >> 1) * 8;
            int col = wn + nf*8 + t2 + (i & 1);
            float v = O[nf][i] * ((i >> 1) ? inv1 : inv0);
            size_t idx = ((size_t)b*SS + q0 + row)*EE + h*DD + col;
            uint16_t hi, lo;
            bsplit(v, hi, lo);
            ohi[idx] = hi;
            olo[idx] = lo;
        }
    }
}

// ---------------- router aux loss ----------------
__global__ void loss_kernel(const float* __restrict__ rlog, const int* __restrict__ dep,
                            float* __restrict__ loss) {
    int tid = threadIdx.x;  // 1024
    __shared__ float red[1024];
    float p[MAXD] = {0,0,0,0};
    float ds = 0.f;
    for (int n = tid; n < NN; n += 1024) {
        float l0 = rlog[n*4+0], l1 = rlog[n*4+1], l2 = rlog[n*4+2], l3 = rlog[n*4+3];
        float m = fmaxf(fmaxf(l0,l1), fmaxf(l2,l3));
        float e0 = expf(l0-m), e1 = expf(l1-m), e2 = expf(l2-m), e3 = expf(l3-m);
        float inv = 1.f/(e0+e1+e2+e3);
        p[0] += e0*inv; p[1] += e1*inv; p[2] += e2*inv; p[3] += e3*inv;
        ds += (float)dep[n];
    }
    float sums[5];
    float vals[5] = {p[0], p[1], p[2], p[3], ds};
    for (int v = 0; v < 5; v++) {
        red[tid] = vals[v]; __syncthreads();
        for (int o = 512; o > 0; o >>= 1) { if (tid < o) red[tid] += red[tid+o]; __syncthreads(); }
        sums[v] = red[0]; __syncthreads();
    }
    if (tid == 0) {
        const float u = 1.f/MAXD;
        float lb = 0.f;
        for (int m = 0; m < MAXD; m++) {
            float mp = sums[m] / (float)NN;
            lb += u * (logf(u) - logf(mp));
        }
        lb /= MAXD;
        float sparsity = (sums[4] / (float)NN) / MAXD;
        loss[0] = 0.01f*lb + 0.001f*sparsity;
    }
}

// ---------------- output tail ----------------
__global__ void finalize_kernel(const int* __restrict__ dep, const float* __restrict__ rlog,
                                const float* __restrict__ loss, float* __restrict__ out) {
    int i = blockIdx.x * blockDim.x + threadIdx.x;
    size_t base = (size_t)NN * VV;
    if (i < NN) out[base + i] = (float)dep[i];
    if (i == 0) out[base + NN] = loss[0];
    if (i < NN*MAXD) out[base + NN + 1 + i] = rlog[i];
}

// ---------------- host orchestration ----------------
extern "C" void kernel_launch(void* const* d_in, const int* in_sizes, int n_in,
                              void* d_out, int out_size) {
    const int*   ids  = (const int*)  d_in[0];
    const float* tok  = (const float*)d_in[1];
    const float* pos  = (const float*)d_in[2];
    const float* rw1  = (const float*)d_in[3];
    const float* rb1  = (const float*)d_in[4];
    const float* rw2  = (const float*)d_in[5];
    const float* rb2  = (const float*)d_in[6];
    const float* wqkv = (const float*)d_in[7];
    const float* bqkv = (const float*)d_in[8];
    const float* wo   = (const float*)d_in[9];
    const float* bo   = (const float*)d_in[10];
    const float* ln1g = (const float*)d_in[11];
    const float* ln1b = (const float*)d_in[12];
    const float* ln2g = (const float*)d_in[13];
    const float* ln2b = (const float*)d_in[14];
    const float* w1   = (const float*)d_in[15];
    const float* b1   = (const float*)d_in[16];
    const float* w2   = (const float*)d_in[17];
    const float* b2   = (const float*)d_in[18];
    const float* lnfg = (const float*)d_in[19];
    const float* lnfb = (const float*)d_in[20];
    const float* lmh  = (const float*)d_in[21];
    float* out = (float*)d_out;

    float *ph, *pqkv, *prl, *ploss;
    uint16_t *phnh, *phnl, *path, *patl, *pffh, *pffl, *pwhi, *pwlo;
    int* pdep;
    cudaGetSymbolAddress((void**)&ph,   g_h);
    cudaGetSymbolAddress((void**)&pqkv, g_qkv);
    cudaGetSymbolAddress((void**)&prl,  g_rlog);
    cudaGetSymbolAddress((void**)&ploss,g_loss);
    cudaGetSymbolAddress((void**)&pdep, g_dep);
    cudaGetSymbolAddress((void**)&phnh, g_hn_hi);
    cudaGetSymbolAddress((void**)&phnl, g_hn_lo);
    cudaGetSymbolAddress((void**)&path, g_at_hi);
    cudaGetSymbolAddress((void**)&patl, g_at_lo);
    cudaGetSymbolAddress((void**)&pffh, g_ffa_hi);
    cudaGetSymbolAddress((void**)&pffl, g_ffa_lo);
    cudaGetSymbolAddress((void**)&pwhi, g_whi);
    cudaGetSymbolAddress((void**)&pwlo, g_wlo);

    cudaFuncSetAttribute(attn_mma_kernel, cudaFuncAttributeMaxDynamicSharedMemorySize, AT_SMEM);
    cudaFuncSetAttribute((gemm_ps<0,0>), cudaFuncAttributeMaxDynamicSharedMemorySize, PS_SMEM);
    cudaFuncSetAttribute((gemm_ps<1,0>), cudaFuncAttributeMaxDynamicSharedMemorySize, PS_SMEM);
    cudaFuncSetAttribute((gemm_ps<0,1>), cudaFuncAttributeMaxDynamicSharedMemorySize, PS_SMEM);

    // pre-split all weights (bf16 hi/lo; byte-neutral vs fp32)
    wsplit_kernel<<<(WQKV_SZ/4 + 255)/256, 256>>>(wqkv, pwhi + OFF_QKV, pwlo + OFF_QKV, WQKV_SZ/4);
    wsplit_kernel<<<(WO_SZ/4   + 255)/256, 256>>>(wo,   pwhi + OFF_WO,  pwlo + OFF_WO,  WO_SZ/4);
    wsplit_kernel<<<(W1_SZ/4   + 255)/256, 256>>>(w1,   pwhi + OFF_W1,  pwlo + OFF_W1,  W1_SZ/4);
    wsplit_kernel<<<(W2_SZ/4   + 255)/256, 256>>>(w2,   pwhi + OFF_W2,  pwlo + OFF_W2,  W2_SZ/4);
    wsplit_kernel<<<(LMH_SZ/4  + 255)/256, 256>>>(lmh,  pwhi + OFF_LMH, pwlo + OFF_LMH, LMH_SZ/4);

    embed_kernel<<<(NN*EE + 255)/256, 256>>>(ids, tok, pos, ph);
    router_kernel<<<NN, RH>>>(ph, rw1, rb1, rw2, rb2, prl, pdep);

    for (int depth = 1; depth <= MAXD; depth++) {
        int li = depth - 1;
        ln_split_kernel<<<NN, 256>>>(ph, ln1g + li*EE, ln1b + li*EE, phnh, phnl);
        {
            dim3 g(QKVW/128, NN/128);
            gemm_ps<0,0><<<g, 256, PS_SMEM>>>(phnh, phnl,
                pwhi + OFF_QKV + (size_t)li*QKVW*EE, pwlo + OFF_QKV + (size_t)li*QKVW*EE,
                bqkv + li*QKVW, pqkv, nullptr, nullptr, QKVW, EE);
        }
        attn_mma_kernel<<<dim3(SS/64, HH, BB), 256, AT_SMEM>>>(pqkv, pdep, depth, path, patl);
        {
            dim3 g(EE/128, NN/128, 2);
            gemm_ps<0,0><<<g, 256, PS_SMEM>>>(path, patl,
                pwhi + OFF_WO + (size_t)li*EE*EE, pwlo + OFF_WO + (size_t)li*EE*EE,
                bo + li*EE, pqkv, nullptr, nullptr, EE, EE);
            add2_kernel<<<(NN*EE + 255)/256, 256>>>(ph, pqkv, pqkv + (size_t)NN*EE);
        }
        ln_split_kernel<<<NN, 256>>>(ph, ln2g + li*EE, ln2b + li*EE, phnh, phnl);
        {
            dim3 g(II/128, NN/128);
            gemm_ps<1,0><<<g, 256, PS_SMEM>>>(phnh, phnl,
                pwhi + OFF_W1 + (size_t)li*II*EE, pwlo + OFF_W1 + (size_t)li*II*EE,
                b1 + li*II, nullptr, pffh, pffl, II, EE);
        }
        {
            dim3 g(EE/128, NN/128, 2);
            gemm_ps<0,0><<<g, 256, PS_SMEM>>>(pffh, pffl,
                pwhi + OFF_W2 + (size_t)li*EE*II, pwlo + OFF_W2 + (size_t)li*EE*II,
                b2 + li*EE, pqkv, nullptr, nullptr, EE, II);
            add2_kernel<<<(NN*EE + 255)/256, 256>>>(ph, pqkv, pqkv + (size_t)NN*EE);
        }
    }

    ln_split_kernel<<<NN, 256>>>(ph, lnfg, lnfb, phnh, phnl);
    {
        dim3 g(NN/128, (VV + 127)/128);   // x = m-tile, y = n-tile (W reuse in L2)
        gemm_ps<0,1><<<g, 256, PS_SMEM>>>(phnh, phnl,
            pwhi + OFF_LMH, pwlo + OFF_LMH,
            (const float*)nullptr, out, nullptr, nullptr, VV, EE);
    }

    loss_kernel<<<1, 1024>>>(prl, pdep, ploss);

    long long full = (long long)NN*VV + NN + 1 + (long long)NN*MAXD;
    if ((long long)out_size >= full)
        finalize_kernel<<<(NN*MAXD + 255)/256, 256>>>(pdep, prl, ploss, out);
}

// round 16
// speedup vs baseline: 1.4979x; 1.1267x over previous
#include <cuda_runtime.h>
#include <cuda_bf16.h>
#include <math.h>
#include <stdint.h>

// ---------------- problem constants ----------------
#define BB 2
#define SS 1024
#define NN (BB*SS)          // 2048 tokens
#define EE 768
#define HH 12
#define DD 64
#define II 3072
#define LL 4
#define RH 128
#define MAXD 4
#define VV 50257
#define QKVW (3*EE)         // 2304

// weight split offsets (elements)
#define WQKV_SZ (LL*QKVW*EE)
#define WO_SZ   (LL*EE*EE)
#define W1_SZ   (LL*II*EE)
#define W2_SZ   (LL*EE*II)
#define LMH_SZ  (VV*EE)
#define OFF_QKV 0
#define OFF_WO  (OFF_QKV + WQKV_SZ)
#define OFF_W1  (OFF_WO + WO_SZ)
#define OFF_W2  (OFF_W1 + W1_SZ)
#define OFF_LMH (OFF_W2 + W2_SZ)
#define WTOT    (OFF_LMH + LMH_SZ)   // 66,908,928

// ---------------- scratch (device globals; no allocation allowed) ----------------
__device__ float g_h   [NN*EE];
__device__ float g_qkv [NN*QKVW];   // fp32 qkv; also reused as 2x split-K partials
__device__ float g_rlog[NN*MAXD];
__device__ int   g_dep [NN];
__device__ float g_loss[1];
__device__ __align__(16) uint16_t g_hn_hi [NN*EE];
__device__ __align__(16) uint16_t g_hn_lo [NN*EE];
__device__ __align__(16) uint16_t g_at_hi [NN*EE];
__device__ __align__(16) uint16_t g_at_lo [NN*EE];
__device__ __align__(16) uint16_t g_ffa_hi[NN*II];
__device__ __align__(16) uint16_t g_ffa_lo[NN*II];
__device__ __align__(16) uint16_t g_whi[WTOT];
__device__ __align__(16) uint16_t g_wlo[WTOT];

// ---------------- bf16 split helpers ----------------
__device__ __forceinline__ void bsplit(float v, uint16_t& hi, uint16_t& lo) {
    __nv_bfloat16 hb = __float2bfloat16(v);          // RN
    float hf = __bfloat162float(hb);
    __nv_bfloat16 lb = __float2bfloat16(v - hf);     // RN residual
    hi = *reinterpret_cast<uint16_t*>(&hb);
    lo = *reinterpret_cast<uint16_t*>(&lb);
}
__device__ __forceinline__ void bsplit4(float4 v, ushort4& h, ushort4& l) {
    bsplit(v.x, h.x, l.x); bsplit(v.y, h.y, l.y);
    bsplit(v.z, h.z, l.z); bsplit(v.w, h.w, l.w);
}

__device__ __forceinline__ void mma_bf16(float* d, const uint32_t* a, const uint32_t* b) {
    asm volatile(
        "mma.sync.aligned.m16n8k16.row.col.f32.bf16.bf16.f32 "
        "{%0,%1,%2,%3}, {%4,%5,%6,%7}, {%8,%9}, {%0,%1,%2,%3};"
        : "+f"(d[0]), "+f"(d[1]), "+f"(d[2]), "+f"(d[3])
        : "r"(a[0]), "r"(a[1]), "r"(a[2]), "r"(a[3]),
          "r"(b[0]), "r"(b[1]));
}

__device__ __forceinline__ void ldsm_x4(uint32_t* r, uint32_t addr) {
    asm volatile("ldmatrix.sync.aligned.m8n8.x4.shared.b16 {%0,%1,%2,%3}, [%4];"
        : "=r"(r[0]), "=r"(r[1]), "=r"(r[2]), "=r"(r[3]) : "r"(addr));
}

__device__ __forceinline__ void cp_async16(uint32_t dst, const void* src, bool pred) {
    int sz = pred ? 16 : 0;
    asm volatile("cp.async.ca.shared.global [%0], [%1], 16, %2;\n"
                 :: "r"(dst), "l"(src), "r"(sz));
}

// ---------------- weight pre-split: fp32 -> bf16 hi/lo (once per launch) ----------------
__global__ void wsplit_kernel(const float* __restrict__ w,
                              uint16_t* __restrict__ hi, uint16_t* __restrict__ lo, int n4) {
    int i = blockIdx.x * blockDim.x + threadIdx.x;
    if (i >= n4) return;
    float4 v = reinterpret_cast<const float4*>(w)[i];
    ushort4 hv, lv;
    bsplit4(v, hv, lv);
    reinterpret_cast<ushort4*>(hi)[i] = hv;
    reinterpret_cast<ushort4*>(lo)[i] = lv;
}

// ---------------- embedding ----------------
__global__ void embed_kernel(const int* __restrict__ ids,
                             const float* __restrict__ tok,
                             const float* __restrict__ pos,
                             float* __restrict__ h) {
    int i = blockIdx.x * blockDim.x + threadIdx.x;
    if (i >= NN*EE) return;
    int n = i / EE, e = i - n*EE;
    int s = n % SS;
    h[i] = tok[(size_t)ids[n]*EE + e] + pos[(size_t)s*EE + e];
}

// ---------------- router ----------------
__global__ void router_kernel(const float* __restrict__ h,
                              const float* __restrict__ w1, const float* __restrict__ b1,
                              const float* __restrict__ w2, const float* __restrict__ b2,
                              float* __restrict__ rlog, int* __restrict__ dep) {
    int n = blockIdx.x;
    int tid = threadIdx.x;   // 128 threads
    __shared__ float r1[RH];
    __shared__ float lg[MAXD];
    const float* hr = h + (size_t)n*EE;
    {
        const float4* hv = reinterpret_cast<const float4*>(hr);
        const float4* wv = reinterpret_cast<const float4*>(w1 + (size_t)tid*EE);
        float acc = b1[tid];
        #pragma unroll 4
        for (int e = 0; e < EE/4; e++) {
            float4 a = hv[e], b = wv[e];
            acc += a.x*b.x + a.y*b.y + a.z*b.z + a.w*b.w;
        }
        r1[tid] = fmaxf(acc, 0.f);
    }
    __syncthreads();
    if (tid < MAXD) {
        float acc = b2[tid];
        const float* wr = w2 + tid*RH;
        #pragma unroll 8
        for (int j = 0; j < RH; j++) acc += r1[j]*wr[j];
        lg[tid] = acc;
        rlog[n*MAXD + tid] = acc;
    }
    __syncthreads();
    if (tid == 0) {
        int best = 0; float bv = lg[0];
        #pragma unroll
        for (int m = 1; m < MAXD; m++) if (lg[m] > bv) { bv = lg[m]; best = m; }
        dep[n] = best + 1;
    }
}

// ---------------- layernorm per token, output pre-split to bf16 hi/lo ----------------
__global__ void ln_split_kernel(const float* __restrict__ x,
                                const float* __restrict__ g, const float* __restrict__ b,
                                uint16_t* __restrict__ yhi, uint16_t* __restrict__ ylo) {
    int n = blockIdx.x, tid = threadIdx.x;   // 256 threads
    __shared__ float red[256];
    __shared__ float s_mu, s_rstd;
    const float* xr = x + (size_t)n*EE;
    float s = 0.f;
    for (int e = tid; e < EE; e += 256) s += xr[e];
    red[tid] = s; __syncthreads();
    for (int o = 128; o > 0; o >>= 1) { if (tid < o) red[tid] += red[tid+o]; __syncthreads(); }
    if (tid == 0) s_mu = red[0] * (1.f/EE);
    __syncthreads();
    float mu = s_mu;
    float v = 0.f;
    for (int e = tid; e < EE; e += 256) { float d = xr[e]-mu; v += d*d; }
    red[tid] = v; __syncthreads();
    for (int o = 128; o > 0; o >>= 1) { if (tid < o) red[tid] += red[tid+o]; __syncthreads(); }
    if (tid == 0) s_rstd = rsqrtf(red[0]*(1.f/EE) + 1e-5f);
    __syncthreads();
    float rstd = s_rstd;
    for (int e = tid; e < EE; e += 256) {
        float y = (xr[e]-mu)*rstd*g[e] + b[e];
        uint16_t hi, lo;
        bsplit(y, hi, lo);
        yhi[(size_t)n*EE + e] = hi;
        ylo[(size_t)n*EE + e] = lo;
    }
}

// ---------------- split-K reduce: h += p0 + p1 ----------------
__global__ void add2_kernel(float* __restrict__ h,
                            const float* __restrict__ p0,
                            const float* __restrict__ p1) {
    int i = blockIdx.x * blockDim.x + threadIdx.x;
    if (i < NN*EE) h[i] += p0[i] + p1[i];
}

// ---------------- GEMM NT on pre-split bf16 operands (bf16x3, ldmatrix loads) ----------------
#define PS_ARR_U16  (128*40)            // 5120
#define PS_STAGE_U16 (4*PS_ARR_U16)     // 20480
#define PS_SMEM (2*PS_STAGE_U16*2)      // bytes = 81920
template <int EPI, int SWAPXY>
__global__ __launch_bounds__(256, 2)
void gemm_ps(const uint16_t* __restrict__ Ahi, const uint16_t* __restrict__ Alo,
             const uint16_t* __restrict__ Whi, const uint16_t* __restrict__ Wlo,
             const float* __restrict__ bias, float* __restrict__ C,
             uint16_t* __restrict__ Chi, uint16_t* __restrict__ Clo,
             int Nn, int K) {
    extern __shared__ uint16_t su[];
    uint32_t sbase;
    asm("{ .reg .u64 t; cvta.to.shared.u64 t, %1; cvt.u32.u64 %0, t; }"
        : "=r"(sbase) : "l"(su));

    int tid = threadIdx.x;
    int m0 = (SWAPXY ? blockIdx.x : blockIdx.y) * 128;
    int n0 = (SWAPXY ? blockIdx.y : blockIdx.x) * 128;
    int Kp = K / gridDim.z;
    int kbase = blockIdx.z * Kp;
    if (gridDim.z > 1) C += (size_t)blockIdx.z * (size_t)2048 * Nn;
    bool do_bias = (bias != nullptr) && (blockIdx.z == 0);

    int warp = tid >> 5, lane = tid & 31;
    int wm = (warp & 1) * 64;     // warp tile 64(m) x 32(n)
    int wn = (warp >> 1) * 32;
    int g = lane >> 2, t = lane & 3;

    // ldmatrix per-lane offsets (bytes), relative to (tile_row0, col kk) of an array
    // A: m0=(rows 0-7,kk) m1=(rows 8-15,kk) m2=(rows 0-7,kk+8) m3=(rows 8-15,kk+8)
    uint32_t aoff = (uint32_t)(((((lane >> 3) & 1) * 8 + (lane & 7)) * 40 + (lane >> 4) * 8) * 2);
    // W (two nf packed): m0=(nf0,kk) m1=(nf0,kk+8) m2=(nf1,kk) m3=(nf1,kk+8)
    uint32_t woff = (uint32_t)((((lane >> 4) * 8 + (lane & 7)) * 40 + ((lane >> 3) & 1) * 8) * 2);

    float acc[4][4][4];
    #pragma unroll
    for (int mf = 0; mf < 4; mf++)
        #pragma unroll
        for (int nf = 0; nf < 4; nf++)
            #pragma unroll
            for (int i = 0; i < 4; i++) acc[mf][nf][i] = 0.f;

    const int nk = Kp >> 5;

    auto load_stage = [&](int st, int k0) {
        uint32_t base = sbase + (uint32_t)st * (PS_STAGE_U16 * 2u);
        #pragma unroll
        for (int cc = 0; cc < 2; cc++) {
            int c = tid + cc * 256;       // chunk 0..511
            int r = c >> 2;
            int q = (c & 3) * 8;          // col offset (elems)
            uint32_t so = (uint32_t)(r*40 + q) * 2u;
            size_t ga = (size_t)(m0 + r)*K + kbase + k0 + q;
            cp_async16(base              + so, Ahi + ga, true);
            cp_async16(base + 10240u     + so, Alo + ga, true);
            int nn = n0 + r;
            int nnc = nn < Nn ? nn : (Nn - 1);
            bool ok = nn < Nn;
            size_t gw = (size_t)nnc*K + kbase + k0 + q;
            cp_async16(base + 20480u     + so, Whi + gw, ok);
            cp_async16(base + 30720u     + so, Wlo + gw, ok);
        }
    };

    load_stage(0, 0);
    asm volatile("cp.async.commit_group;");

    for (int i = 0; i < nk; i++) {
        if (i + 1 < nk) {
            load_stage((i + 1) & 1, (i + 1) << 5);
            asm volatile("cp.async.commit_group;");
            asm volatile("cp.async.wait_group 1;");
        } else {
            asm volatile("cp.async.wait_group 0;");
        }
        __syncthreads();

        uint32_t stb = sbase + (uint32_t)(i & 1) * (PS_STAGE_U16 * 2u);

        #pragma unroll
        for (int ks = 0; ks < 2; ks++) {      // two k=16 steps per 32-tile
            int kk = ks * 16;
            uint32_t ahi[4][4], alo[4][4], bhi[4][2], blo[4][2];
            #pragma unroll
            for (int mf = 0; mf < 4; mf++) {
                uint32_t ab = stb + (uint32_t)(((wm + mf*16)*40 + kk) * 2) + aoff;
                ldsm_x4(ahi[mf], ab);
                ldsm_x4(alo[mf], ab + 10240u);
            }
            #pragma unroll
            for (int p = 0; p < 2; p++) {
                uint32_t wb = stb + 20480u + (uint32_t)(((wn + p*16)*40 + kk) * 2) + woff;
                uint32_t rh[4], rl[4];
                ldsm_x4(rh, wb);
                ldsm_x4(rl, wb + 10240u);
                bhi[2*p  ][0] = rh[0]; bhi[2*p  ][1] = rh[1];
                bhi[2*p+1][0] = rh[2]; bhi[2*p+1][1] = rh[3];
                blo[2*p  ][0] = rl[0]; blo[2*p  ][1] = rl[1];
                blo[2*p+1][0] = rl[2]; blo[2*p+1][1] = rl[3];
            }
            #pragma unroll
            for (int mf = 0; mf < 4; mf++)
                #pragma unroll
                for (int nf = 0; nf < 4; nf++) {
                    mma_bf16(acc[mf][nf], ahi[mf], bhi[nf]);
                    mma_bf16(acc[mf][nf], alo[mf], bhi[nf]);
                    mma_bf16(acc[mf][nf], ahi[mf], blo[nf]);
                }
        }
        __syncthreads();
    }

    #pragma unroll
    for (int mf = 0; mf < 4; mf++) {
        #pragma unroll
        for (int nf = 0; nf < 4; nf++) {
            #pragma unroll
            for (int i = 0; i < 4; i++) {
                int m = m0 + wm + mf*16 + g + (i >> 1) * 8;
                int n = n0 + wn + nf*8 + t*2 + (i & 1);
                if (n < Nn) {
                    float v = acc[mf][nf][i] + (do_bias ? bias[n] : 0.f);
                    size_t ci = (size_t)m*Nn + n;
                    if (EPI == 1) {
                        v = 0.5f*v*(1.0f + erff(v*0.70710678118654752f));
                        uint16_t hi, lo;
                        bsplit(v, hi, lo);
                        Chi[ci] = hi;
                        Clo[ci] = lo;
                    } else {
                        C[ci] = v;
                    }
                }
            }
        }
    }
}

// ---------------- attention via bf16x3 MMA: 64 q-rows per block, online softmax ----------------
#define AT_TILE_U16 (64*72)
#define AT_STAT_OFF 16640
#define AT_U16_OFF  17920
#define AT_SMEM     (AT_U16_OFF + 8*AT_TILE_U16*2)
__global__ __launch_bounds__(256)
void attn_mma_kernel(const float* __restrict__ qkv, const int* __restrict__ dep,
                     int depth, uint16_t* __restrict__ ohi, uint16_t* __restrict__ olo) {
    extern __shared__ char smc[];
    float (*Ps)[65] = (float(*)[65])(smc);
    float* m_s  = (float*)(smc + AT_STAT_OFF);
    float* l_s  = m_s + 64;
    float* al_s = l_s + 64;
    int*   dq_s = (int*)(al_s + 64);
    int*   dk_s = dq_s + 64;
    uint16_t* u16b = (uint16_t*)(smc + AT_U16_OFF);
    uint16_t* Qhi = u16b;
    uint16_t* Qlo = u16b + 1*AT_TILE_U16;
    uint16_t* Khi = u16b + 2*AT_TILE_U16;
    uint16_t* Klo = u16b + 3*AT_TILE_U16;
    uint16_t* Vth = u16b + 4*AT_TILE_U16;
    uint16_t* Vtl = u16b + 5*AT_TILE_U16;
    uint16_t* Phi = u16b + 6*AT_TILE_U16;
    uint16_t* Plo = u16b + 7*AT_TILE_U16;

    int qt = blockIdx.x, h = blockIdx.y, b = blockIdx.z;
    int q0 = qt * 64;
    int tid = threadIdx.x;
    int warp = tid >> 5, lane = tid & 31;
    int g = lane >> 2, t = lane & 3;
    int wm = (warp & 3) * 16;      // 4 m-tiles of 16
    int wn = (warp >> 2) * 32;     // 2 n-groups of 32
    int t2 = 2 * t;

    {
        int d4 = (tid & 15) * 4, r = tid >> 4;
        #pragma unroll
        for (int p = 0; p < 4; p++) {
            int row = r + p*16;
            float4 v = *reinterpret_cast<const float4*>(
                &qkv[((size_t)b*SS + q0 + row)*QKVW + h*DD + d4]);
            ushort4 hv, lv;
            bsplit4(v, hv, lv);
            *reinterpret_cast<ushort4*>(&Qhi[row*72 + d4]) = hv;
            *reinterpret_cast<ushort4*>(&Qlo[row*72 + d4]) = lv;
        }
    }
    if (tid < 64) {
        dq_s[tid] = (dep[b*SS + q0 + tid] >= depth) ? 1 : 0;
        m_s[tid] = -1e30f;
        l_s[tid] = 0.f;
    }

    float O[4][4];
    #pragma unroll
    for (int nf = 0; nf < 4; nf++)
        #pragma unroll
        for (int i = 0; i < 4; i++) O[nf][i] = 0.f;

    for (int k0 = 0; k0 < SS; k0 += 64) {
        __syncthreads();
        {
            int d4 = (tid & 15) * 4, r = tid >> 4;
            #pragma unroll
            for (int p = 0; p < 4; p++) {
                int jj = r + p*16;
                size_t row = ((size_t)b*SS + k0 + jj)*QKVW + h*DD;
                float4 kv = *reinterpret_cast<const float4*>(&qkv[row + EE + d4]);
                ushort4 hv, lv;
                bsplit4(kv, hv, lv);
                *reinterpret_cast<ushort4*>(&Khi[jj*72 + d4]) = hv;
                *reinterpret_cast<ushort4*>(&Klo[jj*72 + d4]) = lv;
                float4 vv = *reinterpret_cast<const float4*>(&qkv[row + 2*EE + d4]);
                uint16_t hh, ll;
                bsplit(vv.x, hh, ll); Vth[(d4+0)*72 + jj] = hh; Vtl[(d4+0)*72 + jj] = ll;
                bsplit(vv.y, hh, ll); Vth[(d4+1)*72 + jj] = hh; Vtl[(d4+1)*72 + jj] = ll;
                bsplit(vv.z, hh, ll); Vth[(d4+2)*72 + jj] = hh; Vtl[(d4+2)*72 + jj] = ll;
                bsplit(vv.w, hh, ll); Vth[(d4+3)*72 + jj] = hh; Vtl[(d4+3)*72 + jj] = ll;
            }
        }
        if (tid < 64) dk_s[tid] = (dep[b*SS + k0 + tid] >= depth) ? 1 : 0;
        __syncthreads();

        float sacc[4][4];
        #pragma unroll
        for (int nf = 0; nf < 4; nf++)
            #pragma unroll
            for (int i = 0; i < 4; i++) sacc[nf][i] = 0.f;
        #pragma unroll
        for (int ks = 0; ks < 4; ks++) {
            int kk = ks * 16;
            uint32_t ah[4], al[4];
            ah[0] = *reinterpret_cast<const uint32_t*>(&Qhi[(wm+g  )*72 + kk + t2]);
            ah[1] = *reinterpret_cast<const uint32_t*>(&Qhi[(wm+g+8)*72 + kk + t2]);
            ah[2] = *reinterpret_cast<const uint32_t*>(&Qhi[(wm+g  )*72 + kk + t2 + 8]);
            ah[3] = *reinterpret_cast<const uint32_t*>(&Qhi[(wm+g+8)*72 + kk + t2 + 8]);
            al[0] = *reinterpret_cast<const uint32_t*>(&Qlo[(wm+g  )*72 + kk + t2]);
            al[1] = *reinterpret_cast<const uint32_t*>(&Qlo[(wm+g+8)*72 + kk + t2]);
            al[2] = *reinterpret_cast<const uint32_t*>(&Qlo[(wm+g  )*72 + kk + t2 + 8]);
            al[3] = *reinterpret_cast<const uint32_t*>(&Qlo[(wm+g+8)*72 + kk + t2 + 8]);
            #pragma unroll
            for (int nf = 0; nf < 4; nf++) {
                int nr = wn + nf*8 + g;
                uint32_t bh[2], bl[2];
                bh[0] = *reinterpret_cast<const uint32_t*>(&Khi[nr*72 + kk + t2]);
                bh[1] = *reinterpret_cast<const uint32_t*>(&Khi[nr*72 + kk + t2 + 8]);
                bl[0] = *reinterpret_cast<const uint32_t*>(&Klo[nr*72 + kk + t2]);
                bl[1] = *reinterpret_cast<const uint32_t*>(&Klo[nr*72 + kk + t2 + 8]);
                mma_bf16(sacc[nf], ah, bh);
                mma_bf16(sacc[nf], al, bh);
                mma_bf16(sacc[nf], ah, bl);
            }
        }
        #pragma unroll
        for (int nf = 0; nf < 4; nf++) {
            #pragma unroll
            for (int i = 0; i < 4; i++) {
                int row = wm + g + (i >> 1) * 8;
                int col = wn + nf*8 + t2 + (i & 1);
                float msk = (k0 + col <= q0 + row && dq_s[row] && dk_s[col]) ? 1.f : 0.f;
                Ps[row][col] = sacc[nf][i]*0.125f + msk;
            }
        }
        __syncthreads();

        {
            int rid = tid >> 2, sub = tid & 3;
            float mx = -1e30f;
            #pragma unroll
            for (int jj = 0; jj < 16; jj++) mx = fmaxf(mx, Ps[rid][sub*16+jj]);
            mx = fmaxf(mx, __shfl_xor_sync(0xffffffff, mx, 1));
            mx = fmaxf(mx, __shfl_xor_sync(0xffffffff, mx, 2));
            float mold = m_s[rid];
            float mnew = fmaxf(mold, mx);
            float sum = 0.f;
            #pragma unroll
            for (int jj = 0; jj < 16; jj++) {
                float p = __expf(Ps[rid][sub*16+jj] - mnew);
                sum += p;
                uint16_t hi, lo;
                bsplit(p, hi, lo);
                Phi[rid*72 + sub*16 + jj] = hi;
                Plo[rid*72 + sub*16 + jj] = lo;
            }
            sum += __shfl_xor_sync(0xffffffff, sum, 1);
            sum += __shfl_xor_sync(0xffffffff, sum, 2);
            if (sub == 0) {
                float alpha = __expf(mold - mnew);
                al_s[rid] = alpha;
                l_s[rid] = l_s[rid]*alpha + sum;
                m_s[rid] = mnew;
            }
        }
        __syncthreads();

        float a0 = al_s[wm + g], a1 = al_s[wm + g + 8];
        #pragma unroll
        for (int nf = 0; nf < 4; nf++) {
            O[nf][0] *= a0; O[nf][1] *= a0;
            O[nf][2] *= a1; O[nf][3] *= a1;
        }
        #pragma unroll
        for (int ks = 0; ks < 4; ks++) {
            int kk = ks * 16;
            uint32_t ah[4], al[4];
            ah[0] = *reinterpret_cast<const uint32_t*>(&Phi[(wm+g  )*72 + kk + t2]);
            ah[1] = *reinterpret_cast<const uint32_t*>(&Phi[(wm+g+8)*72 + kk + t2]);
            ah[2] = *reinterpret_cast<const uint32_t*>(&Phi[(wm+g  )*72 + kk + t2 + 8]);
            ah[3] = *reinterpret_cast<const uint32_t*>(&Phi[(wm+g+8)*72 + kk + t2 + 8]);
            al[0] = *reinterpret_cast<const uint32_t*>(&Plo[(wm+g  )*72 + kk + t2]);
            al[1] = *reinterpret_cast<const uint32_t*>(&Plo[(wm+g+8)*72 + kk + t2]);
            al[2] = *reinterpret_cast<const uint32_t*>(&Plo[(wm+g  )*72 + kk + t2 + 8]);
            al[3] = *reinterpret_cast<const uint32_t*>(&Plo[(wm+g+8)*72 + kk + t2 + 8]);
            #pragma unroll
            for (int nf = 0; nf < 4; nf++) {
                int nr = wn + nf*8 + g;
                uint32_t bh[2], bl[2];
                bh[0] = *reinterpret_cast<const uint32_t*>(&Vth[nr*72 + kk + t2]);
                bh[1] = *reinterpret_cast<const uint32_t*>(&Vth[nr*72 + kk + t2 + 8]);
                bl[0] = *reinterpret_cast<const uint32_t*>(&Vtl[nr*72 + kk + t2]);
                bl[1] = *reinterpret_cast<const uint32_t*>(&Vtl[nr*72 + kk + t2 + 8]);
                mma_bf16(O[nf], ah, bh);
                mma_bf16(O[nf], al, bh);
                mma_bf16(O[nf], ah, bl);
            }
        }
    }

    float inv0 = 1.f / l_s[wm + g], inv1 = 1.f / l_s[wm + g + 8];
    #pragma unroll
    for (int nf = 0; nf < 4; nf++) {
        #pragma unroll
        for (int i = 0; i < 4; i++) {
            int row = wm + g + (i >> 1) * 8;
            int col = wn + nf*8 + t2 + (i & 1);
            float v = O[nf][i] * ((i >> 1) ? inv1 : inv0);
            size_t idx = ((size_t)b*SS + q0 + row)*EE + h*DD + col;
            uint16_t hi, lo;
            bsplit(v, hi, lo);
            ohi[idx] = hi;
            olo[idx] = lo;
        }
    }
}

// ---------------- router aux loss ----------------
__global__ void loss_kernel(const float* __restrict__ rlog, const int* __restrict__ dep,
                            float* __restrict__ loss) {
    int tid = threadIdx.x;  // 1024
    __shared__ float red[1024];
    float p[MAXD] = {0,0,0,0};
    float ds = 0.f;
    for (int n = tid; n < NN; n += 1024) {
        float l0 = rlog[n*4+0], l1 = rlog[n*4+1], l2 = rlog[n*4+2], l3 = rlog[n*4+3];
        float m = fmaxf(fmaxf(l0,l1), fmaxf(l2,l3));
        float e0 = expf(l0-m), e1 = expf(l1-m), e2 = expf(l2-m), e3 = expf(l3-m);
        float inv = 1.f/(e0+e1+e2+e3);
        p[0] += e0*inv; p[1] += e1*inv; p[2] += e2*inv; p[3] += e3*inv;
        ds += (float)dep[n];
    }
    float sums[5];
    float vals[5] = {p[0], p[1], p[2], p[3], ds};
    for (int v = 0; v < 5; v++) {
        red[tid] = vals[v]; __syncthreads();
        for (int o = 512; o > 0; o >>= 1) { if (tid < o) red[tid] += red[tid+o]; __syncthreads(); }
        sums[v] = red[0]; __syncthreads();
    }
    if (tid == 0) {
        const float u = 1.f/MAXD;
        float lb = 0.f;
        for (int m = 0; m < MAXD; m++) {
            float mp = sums[m] / (float)NN;
            lb += u * (logf(u) - logf(mp));
        }
        lb /= MAXD;
        float sparsity = (sums[4] / (float)NN) / MAXD;
        loss[0] = 0.01f*lb + 0.001f*sparsity;
    }
}

// ---------------- output tail ----------------
__global__ void finalize_kernel(const int* __restrict__ dep, const float* __restrict__ rlog,
                                const float* __restrict__ loss, float* __restrict__ out) {
    int i = blockIdx.x * blockDim.x + threadIdx.x;
    size_t base = (size_t)NN * VV;
    if (i < NN) out[base + i] = (float)dep[i];
    if (i == 0) out[base + NN] = loss[0];
    if (i < NN*MAXD) out[base + NN + 1 + i] = rlog[i];
}

// ---------------- host orchestration ----------------
extern "C" void kernel_launch(void* const* d_in, const int* in_sizes, int n_in,
                              void* d_out, int out_size) {
    const int*   ids  = (const int*)  d_in[0];
    const float* tok  = (const float*)d_in[1];
    const float* pos  = (const float*)d_in[2];
    const float* rw1  = (const float*)d_in[3];
    const float* rb1  = (const float*)d_in[4];
    const float* rw2  = (const float*)d_in[5];
    const float* rb2  = (const float*)d_in[6];
    const float* wqkv = (const float*)d_in[7];
    const float* bqkv = (const float*)d_in[8];
    const float* wo   = (const float*)d_in[9];
    const float* bo   = (const float*)d_in[10];
    const float* ln1g = (const float*)d_in[11];
    const float* ln1b = (const float*)d_in[12];
    const float* ln2g = (const float*)d_in[13];
    const float* ln2b = (const float*)d_in[14];
    const float* w1   = (const float*)d_in[15];
    const float* b1   = (const float*)d_in[16];
    const float* w2   = (const float*)d_in[17];
    const float* b2   = (const float*)d_in[18];
    const float* lnfg = (const float*)d_in[19];
    const float* lnfb = (const float*)d_in[20];
    const float* lmh  = (const float*)d_in[21];
    float* out = (float*)d_out;

    float *ph, *pqkv, *prl, *ploss;
    uint16_t *phnh, *phnl, *path, *patl, *pffh, *pffl, *pwhi, *pwlo;
    int* pdep;
    cudaGetSymbolAddress((void**)&ph,   g_h);
    cudaGetSymbolAddress((void**)&pqkv, g_qkv);
    cudaGetSymbolAddress((void**)&prl,  g_rlog);
    cudaGetSymbolAddress((void**)&ploss,g_loss);
    cudaGetSymbolAddress((void**)&pdep, g_dep);
    cudaGetSymbolAddress((void**)&phnh, g_hn_hi);
    cudaGetSymbolAddress((void**)&phnl, g_hn_lo);
    cudaGetSymbolAddress((void**)&path, g_at_hi);
    cudaGetSymbolAddress((void**)&patl, g_at_lo);
    cudaGetSymbolAddress((void**)&pffh, g_ffa_hi);
    cudaGetSymbolAddress((void**)&pffl, g_ffa_lo);
    cudaGetSymbolAddress((void**)&pwhi, g_whi);
    cudaGetSymbolAddress((void**)&pwlo, g_wlo);

    cudaFuncSetAttribute(attn_mma_kernel, cudaFuncAttributeMaxDynamicSharedMemorySize, AT_SMEM);
    cudaFuncSetAttribute((gemm_ps<0,0>), cudaFuncAttributeMaxDynamicSharedMemorySize, PS_SMEM);
    cudaFuncSetAttribute((gemm_ps<1,0>), cudaFuncAttributeMaxDynamicSharedMemorySize, PS_SMEM);
    cudaFuncSetAttribute((gemm_ps<0,1>), cudaFuncAttributeMaxDynamicSharedMemorySize, PS_SMEM);

    // pre-split all weights (bf16 hi/lo; byte-neutral vs fp32)
    wsplit_kernel<<<(WQKV_SZ/4 + 255)/256, 256>>>(wqkv, pwhi + OFF_QKV, pwlo + OFF_QKV, WQKV_SZ/4);
    wsplit_kernel<<<(WO_SZ/4   + 255)/256, 256>>>(wo,   pwhi + OFF_WO,  pwlo + OFF_WO,  WO_SZ/4);
    wsplit_kernel<<<(W1_SZ/4   + 255)/256, 256>>>(w1,   pwhi + OFF_W1,  pwlo + OFF_W1,  W1_SZ/4);
    wsplit_kernel<<<(W2_SZ/4   + 255)/256, 256>>>(w2,   pwhi + OFF_W2,  pwlo + OFF_W2,  W2_SZ/4);
    wsplit_kernel<<<(LMH_SZ/4  + 255)/256, 256>>>(lmh,  pwhi + OFF_LMH, pwlo + OFF_LMH, LMH_SZ/4);

    embed_kernel<<<(NN*EE + 255)/256, 256>>>(ids, tok, pos, ph);
    router_kernel<<<NN, RH>>>(ph, rw1, rb1, rw2, rb2, prl, pdep);

    for (int depth = 1; depth <= MAXD; depth++) {
        int li = depth - 1;
        ln_split_kernel<<<NN, 256>>>(ph, ln1g + li*EE, ln1b + li*EE, phnh, phnl);
        {
            dim3 g(QKVW/128, NN/128);
            gemm_ps<0,0><<<g, 256, PS_SMEM>>>(phnh, phnl,
                pwhi + OFF_QKV + (size_t)li*QKVW*EE, pwlo + OFF_QKV + (size_t)li*QKVW*EE,
                bqkv + li*QKVW, pqkv, nullptr, nullptr, QKVW, EE);
        }
        attn_mma_kernel<<<dim3(SS/64, HH, BB), 256, AT_SMEM>>>(pqkv, pdep, depth, path, patl);
        {
            dim3 g(EE/128, NN/128, 2);
            gemm_ps<0,0><<<g, 256, PS_SMEM>>>(path, patl,
                pwhi + OFF_WO + (size_t)li*EE*EE, pwlo + OFF_WO + (size_t)li*EE*EE,
                bo + li*EE, pqkv, nullptr, nullptr, EE, EE);
            add2_kernel<<<(NN*EE + 255)/256, 256>>>(ph, pqkv, pqkv + (size_t)NN*EE);
        }
        ln_split_kernel<<<NN, 256>>>(ph, ln2g + li*EE, ln2b + li*EE, phnh, phnl);
        {
            dim3 g(II/128, NN/128);
            gemm_ps<1,0><<<g, 256, PS_SMEM>>>(phnh, phnl,
                pwhi + OFF_W1 + (size_t)li*II*EE, pwlo + OFF_W1 + (size_t)li*II*EE,
                b1 + li*II, nullptr, pffh, pffl, II, EE);
        }
        {
            dim3 g(EE/128, NN/128, 2);
            gemm_ps<0,0><<<g, 256, PS_SMEM>>>(pffh, pffl,
                pwhi + OFF_W2 + (size_t)li*EE*II, pwlo + OFF_W2 + (size_t)li*EE*II,
                b2 + li*EE, pqkv, nullptr, nullptr, EE, II);
            add2_kernel<<<(NN*EE + 255)/256, 256>>>(ph, pqkv, pqkv + (size_t)NN*EE);
        }
    }

    ln_split_kernel<<<NN, 256>>>(ph, lnfg, lnfb, phnh, phnl);
    {
        dim3 g(NN/128, (VV + 127)/128);   // x = m-tile, y = n-tile (W reuse in L2)
        gemm_ps<0,1><<<g, 256, PS_SMEM>>>(phnh, phnl,
            pwhi + OFF_LMH, pwlo + OFF_LMH,
            (const float*)nullptr, out, nullptr, nullptr, VV, EE);
    }

    loss_kernel<<<1, 1024>>>(prl, pdep, ploss);

    long long full = (long long)NN*VV + NN + 1 + (long long)NN*MAXD;
    if ((long long)out_size >= full)
        finalize_kernel<<<(NN*MAXD + 255)/256, 256>>>(pdep, prl, ploss, out);
}

// round 17
// speedup vs baseline: 1.5103x; 1.0083x over previous
#include <cuda_runtime.h>
#include <cuda_bf16.h>
#include <math.h>
#include <stdint.h>

// ---------------- problem constants ----------------
#define BB 2
#define SS 1024
#define NN (BB*SS)          // 2048 tokens
#define EE 768
#define HH 12
#define DD 64
#define II 3072
#define LL 4
#define RH 128
#define MAXD 4
#define VV 50257
#define QKVW (3*EE)         // 2304

// weight split offsets (elements)
#define WQKV_SZ (LL*QKVW*EE)
#define WO_SZ   (LL*EE*EE)
#define W1_SZ   (LL*II*EE)
#define W2_SZ   (LL*EE*II)
#define LMH_SZ  (VV*EE)
#define OFF_QKV 0
#define OFF_WO  (OFF_QKV + WQKV_SZ)
#define OFF_W1  (OFF_WO + WO_SZ)
#define OFF_W2  (OFF_W1 + W1_SZ)
#define OFF_LMH (OFF_W2 + W2_SZ)
#define WTOT    (OFF_LMH + LMH_SZ)   // 66,908,928

// ---------------- scratch (device globals; no allocation allowed) ----------------
__device__ float g_h   [NN*EE];
__device__ float g_qkv [NN*QKVW];   // fp32 qkv; also reused as 2x split-K partials
__device__ float g_rlog[NN*MAXD];
__device__ int   g_dep [NN];
__device__ float g_loss[1];
__device__ __align__(16) uint16_t g_hn_hi [NN*EE];
__device__ __align__(16) uint16_t g_hn_lo [NN*EE];
__device__ __align__(16) uint16_t g_at_hi [NN*EE];
__device__ __align__(16) uint16_t g_at_lo [NN*EE];
__device__ __align__(16) uint16_t g_ffa_hi[NN*II];
__device__ __align__(16) uint16_t g_ffa_lo[NN*II];
__device__ __align__(16) uint16_t g_whi[WTOT];
__device__ __align__(16) uint16_t g_wlo[WTOT];

// ---------------- bf16 split helpers ----------------
__device__ __forceinline__ void bsplit(float v, uint16_t& hi, uint16_t& lo) {
    __nv_bfloat16 hb = __float2bfloat16(v);          // RN
    float hf = __bfloat162float(hb);
    __nv_bfloat16 lb = __float2bfloat16(v - hf);     // RN residual
    hi = *reinterpret_cast<uint16_t*>(&hb);
    lo = *reinterpret_cast<uint16_t*>(&lb);
}
__device__ __forceinline__ void bsplit4(float4 v, ushort4& h, ushort4& l) {
    bsplit(v.x, h.x, l.x); bsplit(v.y, h.y, l.y);
    bsplit(v.z, h.z, l.z); bsplit(v.w, h.w, l.w);
}

__device__ __forceinline__ void mma_bf16(float* d, const uint32_t* a, const uint32_t* b) {
    asm volatile(
        "mma.sync.aligned.m16n8k16.row.col.f32.bf16.bf16.f32 "
        "{%0,%1,%2,%3}, {%4,%5,%6,%7}, {%8,%9}, {%0,%1,%2,%3};"
        : "+f"(d[0]), "+f"(d[1]), "+f"(d[2]), "+f"(d[3])
        : "r"(a[0]), "r"(a[1]), "r"(a[2]), "r"(a[3]),
          "r"(b[0]), "r"(b[1]));
}

__device__ __forceinline__ void ldsm_x4(uint32_t* r, uint32_t addr) {
    asm volatile("ldmatrix.sync.aligned.m8n8.x4.shared.b16 {%0,%1,%2,%3}, [%4];"
        : "=r"(r[0]), "=r"(r[1]), "=r"(r[2]), "=r"(r[3]) : "r"(addr));
}

__device__ __forceinline__ void cp_async16(uint32_t dst, const void* src, bool pred) {
    int sz = pred ? 16 : 0;
    asm volatile("cp.async.ca.shared.global [%0], [%1], 16, %2;\n"
                 :: "r"(dst), "l"(src), "r"(sz));
}

// ---------------- weight pre-split: fp32 -> bf16 hi/lo (once per launch) ----------------
__global__ void wsplit_kernel(const float* __restrict__ w,
                              uint16_t* __restrict__ hi, uint16_t* __restrict__ lo, int n4) {
    int i = blockIdx.x * blockDim.x + threadIdx.x;
    if (i >= n4) return;
    float4 v = reinterpret_cast<const float4*>(w)[i];
    ushort4 hv, lv;
    bsplit4(v, hv, lv);
    reinterpret_cast<ushort4*>(hi)[i] = hv;
    reinterpret_cast<ushort4*>(lo)[i] = lv;
}

// ---------------- embedding ----------------
__global__ void embed_kernel(const int* __restrict__ ids,
                             const float* __restrict__ tok,
                             const float* __restrict__ pos,
                             float* __restrict__ h) {
    int i = blockIdx.x * blockDim.x + threadIdx.x;
    if (i >= NN*EE) return;
    int n = i / EE, e = i - n*EE;
    int s = n % SS;
    h[i] = tok[(size_t)ids[n]*EE + e] + pos[(size_t)s*EE + e];
}

// ---------------- router ----------------
__global__ void router_kernel(const float* __restrict__ h,
                              const float* __restrict__ w1, const float* __restrict__ b1,
                              const float* __restrict__ w2, const float* __restrict__ b2,
                              float* __restrict__ rlog, int* __restrict__ dep) {
    int n = blockIdx.x;
    int tid = threadIdx.x;   // 128 threads
    __shared__ float r1[RH];
    __shared__ float lg[MAXD];
    const float* hr = h + (size_t)n*EE;
    {
        const float4* hv = reinterpret_cast<const float4*>(hr);
        const float4* wv = reinterpret_cast<const float4*>(w1 + (size_t)tid*EE);
        float acc = b1[tid];
        #pragma unroll 4
        for (int e = 0; e < EE/4; e++) {
            float4 a = hv[e], b = wv[e];
            acc += a.x*b.x + a.y*b.y + a.z*b.z + a.w*b.w;
        }
        r1[tid] = fmaxf(acc, 0.f);
    }
    __syncthreads();
    if (tid < MAXD) {
        float acc = b2[tid];
        const float* wr = w2 + tid*RH;
        #pragma unroll 8
        for (int j = 0; j < RH; j++) acc += r1[j]*wr[j];
        lg[tid] = acc;
        rlog[n*MAXD + tid] = acc;
    }
    __syncthreads();
    if (tid == 0) {
        int best = 0; float bv = lg[0];
        #pragma unroll
        for (int m = 1; m < MAXD; m++) if (lg[m] > bv) { bv = lg[m]; best = m; }
        dep[n] = best + 1;
    }
}

// ---------------- layernorm per token, output pre-split to bf16 hi/lo ----------------
__global__ void ln_split_kernel(const float* __restrict__ x,
                                const float* __restrict__ g, const float* __restrict__ b,
                                uint16_t* __restrict__ yhi, uint16_t* __restrict__ ylo) {
    int n = blockIdx.x, tid = threadIdx.x;   // 256 threads
    __shared__ float red[256];
    __shared__ float s_mu, s_rstd;
    const float* xr = x + (size_t)n*EE;
    float s = 0.f;
    for (int e = tid; e < EE; e += 256) s += xr[e];
    red[tid] = s; __syncthreads();
    for (int o = 128; o > 0; o >>= 1) { if (tid < o) red[tid] += red[tid+o]; __syncthreads(); }
    if (tid == 0) s_mu = red[0] * (1.f/EE);
    __syncthreads();
    float mu = s_mu;
    float v = 0.f;
    for (int e = tid; e < EE; e += 256) { float d = xr[e]-mu; v += d*d; }
    red[tid] = v; __syncthreads();
    for (int o = 128; o > 0; o >>= 1) { if (tid < o) red[tid] += red[tid+o]; __syncthreads(); }
    if (tid == 0) s_rstd = rsqrtf(red[0]*(1.f/EE) + 1e-5f);
    __syncthreads();
    float rstd = s_rstd;
    for (int e = tid; e < EE; e += 256) {
        float y = (xr[e]-mu)*rstd*g[e] + b[e];
        uint16_t hi, lo;
        bsplit(y, hi, lo);
        yhi[(size_t)n*EE + e] = hi;
        ylo[(size_t)n*EE + e] = lo;
    }
}

// ---------------- split-K reduce: h += p0 + p1 ----------------
__global__ void add2_kernel(float* __restrict__ h,
                            const float* __restrict__ p0,
                            const float* __restrict__ p1) {
    int i = blockIdx.x * blockDim.x + threadIdx.x;
    if (i < NN*EE) h[i] += p0[i] + p1[i];
}

// ---------------- GEMM NT on pre-split bf16 operands (bf16x3, ldmatrix loads) ----------------
#define PS_ARR_U16  (128*40)            // 5120
#define PS_STAGE_U16 (4*PS_ARR_U16)     // 20480
#define PS_SMEM (2*PS_STAGE_U16*2)      // bytes = 81920
template <int EPI, int SWAPXY>
__global__ __launch_bounds__(256, 2)
void gemm_ps(const uint16_t* __restrict__ Ahi, const uint16_t* __restrict__ Alo,
             const uint16_t* __restrict__ Whi, const uint16_t* __restrict__ Wlo,
             const float* __restrict__ bias, float* __restrict__ C,
             uint16_t* __restrict__ Chi, uint16_t* __restrict__ Clo,
             int Nn, int K) {
    extern __shared__ uint16_t su[];
    uint32_t sbase;
    asm("{ .reg .u64 t; cvta.to.shared.u64 t, %1; cvt.u32.u64 %0, t; }"
        : "=r"(sbase) : "l"(su));

    int tid = threadIdx.x;
    int m0 = (SWAPXY ? blockIdx.x : blockIdx.y) * 128;
    int n0 = (SWAPXY ? blockIdx.y : blockIdx.x) * 128;
    int Kp = K / gridDim.z;
    int kbase = blockIdx.z * Kp;
    if (gridDim.z > 1) C += (size_t)blockIdx.z * (size_t)2048 * Nn;
    bool do_bias = (bias != nullptr) && (blockIdx.z == 0);

    int warp = tid >> 5, lane = tid & 31;
    int wm = (warp & 1) * 64;     // warp tile 64(m) x 32(n)
    int wn = (warp >> 1) * 32;
    int g = lane >> 2, t = lane & 3;

    uint32_t aoff = (uint32_t)(((((lane >> 3) & 1) * 8 + (lane & 7)) * 40 + (lane >> 4) * 8) * 2);
    uint32_t woff = (uint32_t)((((lane >> 4) * 8 + (lane & 7)) * 40 + ((lane >> 3) & 1) * 8) * 2);

    float acc[4][4][4];
    #pragma unroll
    for (int mf = 0; mf < 4; mf++)
        #pragma unroll
        for (int nf = 0; nf < 4; nf++)
            #pragma unroll
            for (int i = 0; i < 4; i++) acc[mf][nf][i] = 0.f;

    const int nk = Kp >> 5;

    auto load_stage = [&](int st, int k0) {
        uint32_t base = sbase + (uint32_t)st * (PS_STAGE_U16 * 2u);
        #pragma unroll
        for (int cc = 0; cc < 2; cc++) {
            int c = tid + cc * 256;       // chunk 0..511
            int r = c >> 2;
            int q = (c & 3) * 8;          // col offset (elems)
            uint32_t so = (uint32_t)(r*40 + q) * 2u;
            size_t ga = (size_t)(m0 + r)*K + kbase + k0 + q;
            cp_async16(base              + so, Ahi + ga, true);
            cp_async16(base + 10240u     + so, Alo + ga, true);
            int nn = n0 + r;
            int nnc = nn < Nn ? nn : (Nn - 1);
            bool ok = nn < Nn;
            size_t gw = (size_t)nnc*K + kbase + k0 + q;
            cp_async16(base + 20480u     + so, Whi + gw, ok);
            cp_async16(base + 30720u     + so, Wlo + gw, ok);
        }
    };

    load_stage(0, 0);
    asm volatile("cp.async.commit_group;");

    for (int i = 0; i < nk; i++) {
        if (i + 1 < nk) {
            load_stage((i + 1) & 1, (i + 1) << 5);
            asm volatile("cp.async.commit_group;");
            asm volatile("cp.async.wait_group 1;");
        } else {
            asm volatile("cp.async.wait_group 0;");
        }
        __syncthreads();

        uint32_t stb = sbase + (uint32_t)(i & 1) * (PS_STAGE_U16 * 2u);

        #pragma unroll
        for (int ks = 0; ks < 2; ks++) {      // two k=16 steps per 32-tile
            int kk = ks * 16;
            uint32_t ahi[4][4], alo[4][4], bhi[4][2], blo[4][2];
            #pragma unroll
            for (int mf = 0; mf < 4; mf++) {
                uint32_t ab = stb + (uint32_t)(((wm + mf*16)*40 + kk) * 2) + aoff;
                ldsm_x4(ahi[mf], ab);
                ldsm_x4(alo[mf], ab + 10240u);
            }
            #pragma unroll
            for (int p = 0; p < 2; p++) {
                uint32_t wb = stb + 20480u + (uint32_t)(((wn + p*16)*40 + kk) * 2) + woff;
                uint32_t rh[4], rl[4];
                ldsm_x4(rh, wb);
                ldsm_x4(rl, wb + 10240u);
                bhi[2*p  ][0] = rh[0]; bhi[2*p  ][1] = rh[1];
                bhi[2*p+1][0] = rh[2]; bhi[2*p+1][1] = rh[3];
                blo[2*p  ][0] = rl[0]; blo[2*p  ][1] = rl[1];
                blo[2*p+1][0] = rl[2]; blo[2*p+1][1] = rl[3];
            }
            #pragma unroll
            for (int mf = 0; mf < 4; mf++)
                #pragma unroll
                for (int nf = 0; nf < 4; nf++) {
                    mma_bf16(acc[mf][nf], ahi[mf], bhi[nf]);
                    mma_bf16(acc[mf][nf], alo[mf], bhi[nf]);
                    mma_bf16(acc[mf][nf], ahi[mf], blo[nf]);
                }
        }
        __syncthreads();
    }

    #pragma unroll
    for (int mf = 0; mf < 4; mf++) {
        #pragma unroll
        for (int nf = 0; nf < 4; nf++) {
            #pragma unroll
            for (int i = 0; i < 4; i++) {
                int m = m0 + wm + mf*16 + g + (i >> 1) * 8;
                int n = n0 + wn + nf*8 + t*2 + (i & 1);
                if (n < Nn) {
                    float v = acc[mf][nf][i] + (do_bias ? bias[n] : 0.f);
                    size_t ci = (size_t)m*Nn + n;
                    if (EPI == 1) {
                        v = 0.5f*v*(1.0f + erff(v*0.70710678118654752f));
                        uint16_t hi, lo;
                        bsplit(v, hi, lo);
                        Chi[ci] = hi;
                        Clo[ci] = lo;
                    } else {
                        C[ci] = v;
                    }
                }
            }
        }
    }
}

// ---------------- attention via bf16x3 MMA + ldmatrix: 64 q-rows per block ----------------
#define AT_TILE_U16 (64*72)
#define AT_STAT_OFF 16640
#define AT_U16_OFF  17920
#define AT_SMEM     (AT_U16_OFF + 8*AT_TILE_U16*2)
__global__ __launch_bounds__(256)
void attn_mma_kernel(const float* __restrict__ qkv, const int* __restrict__ dep,
                     int depth, uint16_t* __restrict__ ohi, uint16_t* __restrict__ olo) {
    extern __shared__ char smc[];
    float (*Ps)[65] = (float(*)[65])(smc);
    float* m_s  = (float*)(smc + AT_STAT_OFF);
    float* l_s  = m_s + 64;
    float* al_s = l_s + 64;
    int*   dq_s = (int*)(al_s + 64);
    int*   dk_s = dq_s + 64;
    uint16_t* u16b = (uint16_t*)(smc + AT_U16_OFF);
    uint16_t* Qhi = u16b;
    uint16_t* Qlo = u16b + 1*AT_TILE_U16;
    uint16_t* Khi = u16b + 2*AT_TILE_U16;
    uint16_t* Klo = u16b + 3*AT_TILE_U16;
    uint16_t* Vth = u16b + 4*AT_TILE_U16;
    uint16_t* Vtl = u16b + 5*AT_TILE_U16;
    uint16_t* Phi = u16b + 6*AT_TILE_U16;
    uint16_t* Plo = u16b + 7*AT_TILE_U16;

    uint32_t ubase;
    asm("{ .reg .u64 t; cvta.to.shared.u64 t, %1; cvt.u32.u64 %0, t; }"
        : "=r"(ubase) : "l"(u16b));
    const uint32_t TB = AT_TILE_U16 * 2u;   // tile bytes

    int qt = blockIdx.x, h = blockIdx.y, b = blockIdx.z;
    int q0 = qt * 64;
    int tid = threadIdx.x;
    int warp = tid >> 5, lane = tid & 31;
    int g = lane >> 2, t = lane & 3;
    int wm = (warp & 3) * 16;      // 4 m-tiles of 16
    int wn = (warp >> 2) * 32;     // 2 n-groups of 32
    int t2 = 2 * t;

    // ldmatrix per-lane offsets (stride 72 u16 = 144 B rows)
    uint32_t aoff = (uint32_t)(((((lane >> 3) & 1) * 8 + (lane & 7)) * 72 + (lane >> 4) * 8) * 2);
    uint32_t woff = (uint32_t)((((lane >> 4) * 8 + (lane & 7)) * 72 + ((lane >> 3) & 1) * 8) * 2);

    {
        int d4 = (tid & 15) * 4, r = tid >> 4;
        #pragma unroll
        for (int p = 0; p < 4; p++) {
            int row = r + p*16;
            float4 v = *reinterpret_cast<const float4*>(
                &qkv[((size_t)b*SS + q0 + row)*QKVW + h*DD + d4]);
            ushort4 hv, lv;
            bsplit4(v, hv, lv);
            *reinterpret_cast<ushort4*>(&Qhi[row*72 + d4]) = hv;
            *reinterpret_cast<ushort4*>(&Qlo[row*72 + d4]) = lv;
        }
    }
    if (tid < 64) {
        dq_s[tid] = (dep[b*SS + q0 + tid] >= depth) ? 1 : 0;
        m_s[tid] = -1e30f;
        l_s[tid] = 0.f;
    }

    float O[4][4];
    #pragma unroll
    for (int nf = 0; nf < 4; nf++)
        #pragma unroll
        for (int i = 0; i < 4; i++) O[nf][i] = 0.f;

    for (int k0 = 0; k0 < SS; k0 += 64) {
        __syncthreads();
        {
            int d4 = (tid & 15) * 4, r = tid >> 4;
            #pragma unroll
            for (int p = 0; p < 4; p++) {
                int jj = r + p*16;
                size_t row = ((size_t)b*SS + k0 + jj)*QKVW + h*DD;
                float4 kv = *reinterpret_cast<const float4*>(&qkv[row + EE + d4]);
                ushort4 hv, lv;
                bsplit4(kv, hv, lv);
                *reinterpret_cast<ushort4*>(&Khi[jj*72 + d4]) = hv;
                *reinterpret_cast<ushort4*>(&Klo[jj*72 + d4]) = lv;
                float4 vv = *reinterpret_cast<const float4*>(&qkv[row + 2*EE + d4]);
                uint16_t hh, ll;
                bsplit(vv.x, hh, ll); Vth[(d4+0)*72 + jj] = hh; Vtl[(d4+0)*72 + jj] = ll;
                bsplit(vv.y, hh, ll); Vth[(d4+1)*72 + jj] = hh; Vtl[(d4+1)*72 + jj] = ll;
                bsplit(vv.z, hh, ll); Vth[(d4+2)*72 + jj] = hh; Vtl[(d4+2)*72 + jj] = ll;
                bsplit(vv.w, hh, ll); Vth[(d4+3)*72 + jj] = hh; Vtl[(d4+3)*72 + jj] = ll;
            }
        }
        if (tid < 64) dk_s[tid] = (dep[b*SS + k0 + tid] >= depth) ? 1 : 0;
        __syncthreads();

        // S = Q K^T (bf16x3 MMA, ldmatrix)
        float sacc[4][4];
        #pragma unroll
        for (int nf = 0; nf < 4; nf++)
            #pragma unroll
            for (int i = 0; i < 4; i++) sacc[nf][i] = 0.f;
        #pragma unroll
        for (int ks = 0; ks < 4; ks++) {
            int kk = ks * 16;
            uint32_t ah[4], al[4], bh4[4][2], bl4[4][2];
            uint32_t ab = ubase + 0u*TB + (uint32_t)((wm*72 + kk) * 2) + aoff;   // Qhi
            ldsm_x4(ah, ab);
            ldsm_x4(al, ab + TB);                                               // Qlo
            #pragma unroll
            for (int p = 0; p < 2; p++) {
                uint32_t wb = ubase + 2u*TB + (uint32_t)(((wn + p*16)*72 + kk) * 2) + woff;  // Khi
                uint32_t rh[4], rl[4];
                ldsm_x4(rh, wb);
                ldsm_x4(rl, wb + TB);                                           // Klo
                bh4[2*p  ][0] = rh[0]; bh4[2*p  ][1] = rh[1];
                bh4[2*p+1][0] = rh[2]; bh4[2*p+1][1] = rh[3];
                bl4[2*p  ][0] = rl[0]; bl4[2*p  ][1] = rl[1];
                bl4[2*p+1][0] = rl[2]; bl4[2*p+1][1] = rl[3];
            }
            #pragma unroll
            for (int nf = 0; nf < 4; nf++) {
                mma_bf16(sacc[nf], ah, bh4[nf]);
                mma_bf16(sacc[nf], al, bh4[nf]);
                mma_bf16(sacc[nf], ah, bl4[nf]);
            }
        }
        #pragma unroll
        for (int nf = 0; nf < 4; nf++) {
            #pragma unroll
            for (int i = 0; i < 4; i++) {
                int row = wm + g + (i >> 1) * 8;
                int col = wn + nf*8 + t2 + (i & 1);
                float msk = (k0 + col <= q0 + row && dq_s[row] && dk_s[col]) ? 1.f : 0.f;
                Ps[row][col] = sacc[nf][i]*0.125f + msk;
            }
        }
        __syncthreads();

        {
            int rid = tid >> 2, sub = tid & 3;
            float mx = -1e30f;
            #pragma unroll
            for (int jj = 0; jj < 16; jj++) mx = fmaxf(mx, Ps[rid][sub*16+jj]);
            mx = fmaxf(mx, __shfl_xor_sync(0xffffffff, mx, 1));
            mx = fmaxf(mx, __shfl_xor_sync(0xffffffff, mx, 2));
            float mold = m_s[rid];
            float mnew = fmaxf(mold, mx);
            float sum = 0.f;
            #pragma unroll
            for (int jj = 0; jj < 16; jj++) {
                float p = __expf(Ps[rid][sub*16+jj] - mnew);
                sum += p;
                uint16_t hi, lo;
                bsplit(p, hi, lo);
                Phi[rid*72 + sub*16 + jj] = hi;
                Plo[rid*72 + sub*16 + jj] = lo;
            }
            sum += __shfl_xor_sync(0xffffffff, sum, 1);
            sum += __shfl_xor_sync(0xffffffff, sum, 2);
            if (sub == 0) {
                float alpha = __expf(mold - mnew);
                al_s[rid] = alpha;
                l_s[rid] = l_s[rid]*alpha + sum;
                m_s[rid] = mnew;
            }
        }
        __syncthreads();

        // O = O*alpha + P V (bf16x3 MMA, ldmatrix)
        float a0 = al_s[wm + g], a1 = al_s[wm + g + 8];
        #pragma unroll
        for (int nf = 0; nf < 4; nf++) {
            O[nf][0] *= a0; O[nf][1] *= a0;
            O[nf][2] *= a1; O[nf][3] *= a1;
        }
        #pragma unroll
        for (int ks = 0; ks < 4; ks++) {
            int kk = ks * 16;
            uint32_t ah[4], al[4], bh4[4][2], bl4[4][2];
            uint32_t ab = ubase + 6u*TB + (uint32_t)((wm*72 + kk) * 2) + aoff;   // Phi
            ldsm_x4(ah, ab);
            ldsm_x4(al, ab + TB);                                               // Plo
            #pragma unroll
            for (int p = 0; p < 2; p++) {
                uint32_t wb = ubase + 4u*TB + (uint32_t)(((wn + p*16)*72 + kk) * 2) + woff;  // Vth
                uint32_t rh[4], rl[4];
                ldsm_x4(rh, wb);
                ldsm_x4(rl, wb + TB);                                           // Vtl
                bh4[2*p  ][0] = rh[0]; bh4[2*p  ][1] = rh[1];
                bh4[2*p+1][0] = rh[2]; bh4[2*p+1][1] = rh[3];
                bl4[2*p  ][0] = rl[0]; bl4[2*p  ][1] = rl[1];
                bl4[2*p+1][0] = rl[2]; bl4[2*p+1][1] = rl[3];
            }
            #pragma unroll
            for (int nf = 0; nf < 4; nf++) {
                mma_bf16(O[nf], ah, bh4[nf]);
                mma_bf16(O[nf], al, bh4[nf]);
                mma_bf16(O[nf], ah, bl4[nf]);
            }
        }
    }

    float inv0 = 1.f / l_s[wm + g], inv1 = 1.f / l_s[wm + g + 8];
    #pragma unroll
    for (int nf = 0; nf < 4; nf++) {
        #pragma unroll
        for (int i = 0; i < 4; i++) {
            int row = wm + g + (i >> 1) * 8;
            int col = wn + nf*8 + t2 + (i & 1);
            float v = O[nf][i] * ((i >> 1) ? inv1 : inv0);
            size_t idx = ((size_t)b*SS + q0 + row)*EE + h*DD + col;
            uint16_t hi, lo;
            bsplit(v, hi, lo);
            ohi[idx] = hi;
            olo[idx] = lo;
        }
    }
}

// ---------------- router aux loss ----------------
__global__ void loss_kernel(const float* __restrict__ rlog, const int* __restrict__ dep,
                            float* __restrict__ loss) {
    int tid = threadIdx.x;  // 1024
    __shared__ float red[1024];
    float p[MAXD] = {0,0,0,0};
    float ds = 0.f;
    for (int n = tid; n < NN; n += 1024) {
        float l0 = rlog[n*4+0], l1 = rlog[n*4+1], l2 = rlog[n*4+2], l3 = rlog[n*4+3];
        float m = fmaxf(fmaxf(l0,l1), fmaxf(l2,l3));
        float e0 = expf(l0-m), e1 = expf(l1-m), e2 = expf(l2-m), e3 = expf(l3-m);
        float inv = 1.f/(e0+e1+e2+e3);
        p[0] += e0*inv; p[1] += e1*inv; p[2] += e2*inv; p[3] += e3*inv;
        ds += (float)dep[n];
    }
    float sums[5];
    float vals[5] = {p[0], p[1], p[2], p[3], ds};
    for (int v = 0; v < 5; v++) {
        red[tid] = vals[v]; __syncthreads();
        for (int o = 512; o > 0; o >>= 1) { if (tid < o) red[tid] += red[tid+o]; __syncthreads(); }
        sums[v] = red[0]; __syncthreads();
    }
    if (tid == 0) {
        const float u = 1.f/MAXD;
        float lb = 0.f;
        for (int m = 0; m < MAXD; m++) {
            float mp = sums[m] / (float)NN;
            lb += u * (logf(u) - logf(mp));
        }
        lb /= MAXD;
        float sparsity = (sums[4] / (float)NN) / MAXD;
        loss[0] = 0.01f*lb + 0.001f*sparsity;
    }
}

// ---------------- output tail ----------------
__global__ void finalize_kernel(const int* __restrict__ dep, const float* __restrict__ rlog,
                                const float* __restrict__ loss, float* __restrict__ out) {
    int i = blockIdx.x * blockDim.x + threadIdx.x;
    size_t base = (size_t)NN * VV;
    if (i < NN) out[base + i] = (float)dep[i];
    if (i == 0) out[base + NN] = loss[0];
    if (i < NN*MAXD) out[base + NN + 1 + i] = rlog[i];
}

// ---------------- host orchestration ----------------
extern "C" void kernel_launch(void* const* d_in, const int* in_sizes, int n_in,
                              void* d_out, int out_size) {
    const int*   ids  = (const int*)  d_in[0];
    const float* tok  = (const float*)d_in[1];
    const float* pos  = (const float*)d_in[2];
    const float* rw1  = (const float*)d_in[3];
    const float* rb1  = (const float*)d_in[4];
    const float* rw2  = (const float*)d_in[5];
    const float* rb2  = (const float*)d_in[6];
    const float* wqkv = (const float*)d_in[7];
    const float* bqkv = (const float*)d_in[8];
    const float* wo   = (const float*)d_in[9];
    const float* bo   = (const float*)d_in[10];
    const float* ln1g = (const float*)d_in[11];
    const float* ln1b = (const float*)d_in[12];
    const float* ln2g = (const float*)d_in[13];
    const float* ln2b = (const float*)d_in[14];
    const float* w1   = (const float*)d_in[15];
    const float* b1   = (const float*)d_in[16];
    const float* w2   = (const float*)d_in[17];
    const float* b2   = (const float*)d_in[18];
    const float* lnfg = (const float*)d_in[19];
    const float* lnfb = (const float*)d_in[20];
    const float* lmh  = (const float*)d_in[21];
    float* out = (float*)d_out;

    float *ph, *pqkv, *prl, *ploss;
    uint16_t *phnh, *phnl, *path, *patl, *pffh, *pffl, *pwhi, *pwlo;
    int* pdep;
    cudaGetSymbolAddress((void**)&ph,   g_h);
    cudaGetSymbolAddress((void**)&pqkv, g_qkv);
    cudaGetSymbolAddress((void**)&prl,  g_rlog);
    cudaGetSymbolAddress((void**)&ploss,g_loss);
    cudaGetSymbolAddress((void**)&pdep, g_dep);
    cudaGetSymbolAddress((void**)&phnh, g_hn_hi);
    cudaGetSymbolAddress((void**)&phnl, g_hn_lo);
    cudaGetSymbolAddress((void**)&path, g_at_hi);
    cudaGetSymbolAddress((void**)&patl, g_at_lo);
    cudaGetSymbolAddress((void**)&pffh, g_ffa_hi);
    cudaGetSymbolAddress((void**)&pffl, g_ffa_lo);
    cudaGetSymbolAddress((void**)&pwhi, g_whi);
    cudaGetSymbolAddress((void**)&pwlo, g_wlo);

    cudaFuncSetAttribute(attn_mma_kernel, cudaFuncAttributeMaxDynamicSharedMemorySize, AT_SMEM);
    cudaFuncSetAttribute((gemm_ps<0,0>), cudaFuncAttributeMaxDynamicSharedMemorySize, PS_SMEM);
    cudaFuncSetAttribute((gemm_ps<1,0>), cudaFuncAttributeMaxDynamicSharedMemorySize, PS_SMEM);
    cudaFuncSetAttribute((gemm_ps<0,1>), cudaFuncAttributeMaxDynamicSharedMemorySize, PS_SMEM);

    // pre-split all weights (bf16 hi/lo; byte-neutral vs fp32)
    wsplit_kernel<<<(WQKV_SZ/4 + 255)/256, 256>>>(wqkv, pwhi + OFF_QKV, pwlo + OFF_QKV, WQKV_SZ/4);
    wsplit_kernel<<<(WO_SZ/4   + 255)/256, 256>>>(wo,   pwhi + OFF_WO,  pwlo + OFF_WO,  WO_SZ/4);
    wsplit_kernel<<<(W1_SZ/4   + 255)/256, 256>>>(w1,   pwhi + OFF_W1,  pwlo + OFF_W1,  W1_SZ/4);
    wsplit_kernel<<<(W2_SZ/4   + 255)/256, 256>>>(w2,   pwhi + OFF_W2,  pwlo + OFF_W2,  W2_SZ/4);
    wsplit_kernel<<<(LMH_SZ/4  + 255)/256, 256>>>(lmh,  pwhi + OFF_LMH, pwlo + OFF_LMH, LMH_SZ/4);

    embed_kernel<<<(NN*EE + 255)/256, 256>>>(ids, tok, pos, ph);
    router_kernel<<<NN, RH>>>(ph, rw1, rb1, rw2, rb2, prl, pdep);

    for (int depth = 1; depth <= MAXD; depth++) {
        int li = depth - 1;
        ln_split_kernel<<<NN, 256>>>(ph, ln1g + li*EE, ln1b + li*EE, phnh, phnl);
        {
            dim3 g(QKVW/128, NN/128);
            gemm_ps<0,0><<<g, 256, PS_SMEM>>>(phnh, phnl,
                pwhi + OFF_QKV + (size_t)li*QKVW*EE, pwlo + OFF_QKV + (size_t)li*QKVW*EE,
                bqkv + li*QKVW, pqkv, nullptr, nullptr, QKVW, EE);
        }
        attn_mma_kernel<<<dim3(SS/64, HH, BB), 256, AT_SMEM>>>(pqkv, pdep, depth, path, patl);
        {
            dim3 g(EE/128, NN/128, 2);
            gemm_ps<0,0><<<g, 256, PS_SMEM>>>(path, patl,
                pwhi + OFF_WO + (size_t)li*EE*EE, pwlo + OFF_WO + (size_t)li*EE*EE,
                bo + li*EE, pqkv, nullptr, nullptr, EE, EE);
            add2_kernel<<<(NN*EE + 255)/256, 256>>>(ph, pqkv, pqkv + (size_t)NN*EE);
        }
        ln_split_kernel<<<NN, 256>>>(ph, ln2g + li*EE, ln2b + li*EE, phnh, phnl);
        {
            dim3 g(II/128, NN/128);
            gemm_ps<1,0><<<g, 256, PS_SMEM>>>(phnh, phnl,
                pwhi + OFF_W1 + (size_t)li*II*EE, pwlo + OFF_W1 + (size_t)li*II*EE,
                b1 + li*II, nullptr, pffh, pffl, II, EE);
        }
        {
            dim3 g(EE/128, NN/128, 2);
            gemm_ps<0,0><<<g, 256, PS_SMEM>>>(pffh, pffl,
                pwhi + OFF_W2 + (size_t)li*EE*II, pwlo + OFF_W2 + (size_t)li*EE*II,
                b2 + li*EE, pqkv, nullptr, nullptr, EE, II);
            add2_kernel<<<(NN*EE + 255)/256, 256>>>(ph, pqkv, pqkv + (size_t)NN*EE);
        }
    }

    ln_split_kernel<<<NN, 256>>>(ph, lnfg, lnfb, phnh, phnl);
    {
        dim3 g(NN/128, (VV + 127)/128);   // x = m-tile, y = n-tile (W reuse in L2)
        gemm_ps<0,1><<<g, 256, PS_SMEM>>>(phnh, phnl,
            pwhi + OFF_LMH, pwlo + OFF_LMH,
            (const float*)nullptr, out, nullptr, nullptr, VV, EE);
    }

    loss_kernel<<<1, 1024>>>(prl, pdep, ploss);

    long long full = (long long)NN*VV + NN + 1 + (long long)NN*MAXD;
    if ((long long)out_size >= full)
        finalize_kernel<<<(NN*MAXD + 255)/256, 256>>>(pdep, prl, ploss, out);
}